// round 9
// baseline (speedup 1.0000x reference)
#include <cuda_runtime.h>
#include <cuda_bf16.h>
#include <cstdint>

// Problem constants
#define NB 4
#define SLEN 32768
#define C1 128
#define C2C 256
#define C3 512
#define L1O 16384
#define L2O 8192
#define L3O 4096
#define VOCAB 2048
#define KCB 4
#define NCODES (KCB * VOCAB)   // 8192
#define MTOT (NB * L3O)        // 16384
#define NT 32                  // 8192/256 n-tiles, 8 per codebook

typedef unsigned long long u64;

// bf16 split activations, transposed: X [b][pos][CI], 4 guard rows each side.
__device__ ulonglong2 g_X1h[NB * (L1O + 8) * C1 / 8];
__device__ ulonglong2 g_X1l[NB * (L1O + 8) * C1 / 8];
__device__ ulonglong2 g_X2h[NB * (L2O + 8) * C2C / 8];
__device__ ulonglong2 g_X2l[NB * (L2O + 8) * C2C / 8];
// split weights [7][CO][CI]
__device__ ulonglong2 g_W2h[7 * C2C * C1 / 8];
__device__ ulonglong2 g_W2l[7 * C2C * C1 / 8];
__device__ ulonglong2 g_W3h[7 * C3 * C2C / 8];
__device__ ulonglong2 g_W3l[7 * C3 * C2C / 8];
// vq operands
__device__ ulonglong2 g_Ah[MTOT * 512 / 8];      // feats hi  [m][k] (conv3 output)
__device__ ulonglong2 g_Al[MTOT * 512 / 8];
__device__ ulonglong2 g_Bh[NCODES * 512 / 8];    // codes hi  [n][k]
__device__ ulonglong2 g_Bl[NCODES * 512 / 8];
__device__ float g_c2[NCODES];
__device__ u64   g_pkey[MTOT * NT];

// ---------------------------------------------------------------------------
// helpers
// ---------------------------------------------------------------------------
__device__ __forceinline__ void cp16(uint32_t dst, const void* src) {
    asm volatile("cp.async.cg.shared.global [%0], [%1], 16;" :: "r"(dst), "l"(src));
}
__device__ __forceinline__ void cp_commit() { asm volatile("cp.async.commit_group;"); }
__device__ __forceinline__ void cp_wait0()  { asm volatile("cp.async.wait_group 0;"); }

__device__ __forceinline__ uint32_t smem_u32(const void* p) {
    return (uint32_t)__cvta_generic_to_shared(p);
}

__device__ __forceinline__ u64 dist_key(float v, int n) {
    unsigned int fb = __float_as_uint(v);
    fb = (fb & 0x80000000u) ? ~fb : (fb | 0x80000000u);
    return ((u64)fb << 32) | (unsigned int)n;
}

__device__ __forceinline__ void ldm4(uint32_t* r, uint32_t addr) {
    asm volatile("ldmatrix.sync.aligned.m8n8.x4.shared.b16 {%0,%1,%2,%3}, [%4];"
                 : "=r"(r[0]), "=r"(r[1]), "=r"(r[2]), "=r"(r[3]) : "r"(addr));
}
__device__ __forceinline__ void mma16816(float* c, const uint32_t* a,
                                         uint32_t b0, uint32_t b1) {
    asm volatile(
        "mma.sync.aligned.m16n8k16.row.col.f32.bf16.bf16.f32 "
        "{%0,%1,%2,%3}, {%4,%5,%6,%7}, {%8,%9}, {%0,%1,%2,%3};"
        : "+f"(c[0]), "+f"(c[1]), "+f"(c[2]), "+f"(c[3])
        : "r"(a[0]), "r"(a[1]), "r"(a[2]), "r"(a[3]), "r"(b0), "r"(b1));
}

// smem swizzle (rows of 64 B = 4 x 16B chunks)
__device__ __forceinline__ int swz(int row, int c) {
    return row * 64 + ((c ^ ((row & 3) ^ ((row >> 2) & 1))) << 4);
}
// conv smem swizzle for 32 B rows (2 chunks)
__device__ __forceinline__ int s3(int row) {
    return (row ^ (row >> 1) ^ (row >> 2)) & 1;
}

// ---------------------------------------------------------------------------
// guard zeroing: X1/X2 guard rows (4 each side)
// ---------------------------------------------------------------------------
__global__ void guard_zero(uint32_t* x1h, uint32_t* x1l,
                           uint32_t* x2h, uint32_t* x2l) {
    int i = blockIdx.x * 256 + threadIdx.x;
    if (i < 4096) {                       // X1: 2 halves x 2048 u32
        int half = i >> 11, j = i & 2047;
        int b = j >> 9, r = (j >> 6) & 7, w = j & 63;
        int row = (r < 4) ? r : (L1O + r);
        uint32_t* p = half ? x1l : x1h;
        p[(size_t)(b * (L1O + 8) + row) * 64 + w] = 0u;
    } else if (i < 4096 + 8192) {         // X2: 2 halves x 4096 u32
        int j = i - 4096;
        int half = j >> 12; j &= 4095;
        int b = j >> 10, r = (j >> 7) & 7, w = j & 127;
        int row = (r < 4) ? r : (L2O + r);
        uint32_t* p = half ? x2l : x2h;
        p[(size_t)(b * (L2O + 8) + row) * 128 + w] = 0u;
    }
}

// ---------------------------------------------------------------------------
// split weights: w [CO][CI][7] fp32 -> Wh/Wl [7][CO][CI] bf16
// ---------------------------------------------------------------------------
__global__ void split_W(const float* __restrict__ w,
                        __nv_bfloat16* __restrict__ wh,
                        __nv_bfloat16* __restrict__ wl, int CO, int CI) {
    int i = blockIdx.x * 256 + threadIdx.x;
    if (i >= CO * CI * 7) return;
    int co = i / (CI * 7);
    int r  = i % (CI * 7);
    int ci = r / 7, t = r % 7;
    float v = w[i];
    __nv_bfloat16 h = __float2bfloat16(v);
    wh[((size_t)t * CO + co) * CI + ci] = h;
    wl[((size_t)t * CO + co) * CI + ci] = __float2bfloat16(v - __bfloat162float(h));
}

// ---------------------------------------------------------------------------
// conv1: [B,1,32768] -> relu -> X1 [b][pos][128] bf16 hi/lo (offset 4 rows)
// ---------------------------------------------------------------------------
__global__ void conv1_kernel(const float* __restrict__ x,
                             const float* __restrict__ w,
                             const float* __restrict__ bias,
                             __nv_bfloat16* __restrict__ yh,
                             __nv_bfloat16* __restrict__ yl) {
    int tid = threadIdx.x;
    int co = tid & 127;
    int l  = blockIdx.x * 2 + (tid >> 7);
    int b  = blockIdx.z;
    const float* xb = x + b * SLEN;
    float acc = bias[co];
#pragma unroll
    for (int t = 0; t < 7; ++t) {
        int g = 2 * l + t - 3;
        float xv = (g >= 0 && g < SLEN) ? xb[g] : 0.0f;
        acc = fmaf(w[co * 7 + t], xv, acc);
    }
    acc = fmaxf(acc, 0.0f);
    __nv_bfloat16 h = __float2bfloat16(acc);
    size_t o = (size_t)(b * (L1O + 8) + l + 4) * C1 + co;
    yh[o] = h;
    yl[o] = __float2bfloat16(acc - __bfloat162float(h));
}

// ---------------------------------------------------------------------------
// conv via mma.sync bf16 split (hh + hl + lh) — unchanged from R7.
// ---------------------------------------------------------------------------
#define SLAB_PAR  4352
#define SLAB_HALF 8704
#define SLAB_SZ   17408
#define W_HALF    28672
#define CBUF      74752

template <int CI>
__global__ __launch_bounds__(256, 1) void conv_mma(
        const __nv_bfloat16* __restrict__ Xh, const __nv_bfloat16* __restrict__ Xl,
        const __nv_bfloat16* __restrict__ Wh, const __nv_bfloat16* __restrict__ Wl,
        const float* __restrict__ bias,
        __nv_bfloat16* __restrict__ Yh, __nv_bfloat16* __restrict__ Yl,
        int L_in, int L_out, int CO, int do_relu, int y_pad, int y_off) {
    extern __shared__ __align__(16) char dsm[];
    const uint32_t sbase = smem_u32(dsm);

    const int tid  = threadIdx.x;
    const int lane = tid & 31;
    const int wid  = tid >> 5;
    const int wm   = wid >> 1;
    const int wn   = wid & 1;
    const int l0  = blockIdx.x * 128;
    const int co0 = blockIdx.y * 128;
    const int b   = blockIdx.z;

    float acc[2][8][4];
#pragma unroll
    for (int i = 0; i < 2; ++i)
#pragma unroll
        for (int j = 0; j < 8; ++j)
#pragma unroll
            for (int q = 0; q < 4; ++q) acc[i][j][q] = 0.0f;

    auto load_chunk = [&](int ch, int buf) {
        const int ci0 = ch * 16;
        const uint32_t bb = sbase + buf * CBUF;
        for (int i = tid; i < 262 * 4; i += 256) {
            int rel = i >> 2;
            int half = (i >> 1) & 1, ck = i & 1;
            int e = rel >> 1, par = rel & 1;
            const __nv_bfloat16* src = (half ? Xl : Xh) +
                (size_t)(b * (L_in + 8) + 2 * l0 + rel) * CI + ci0 + ck * 8;
            cp16(bb + half * SLAB_HALF + par * SLAB_PAR + e * 32 +
                 ((ck ^ s3(e)) << 4), src);
        }
#pragma unroll
        for (int r = 0; r < 14; ++r) {
            int i = tid + r * 256;
            int row = i >> 2;
            int half = (i >> 1) & 1, ck = i & 1;
            int t = row >> 7, col = row & 127;
            const __nv_bfloat16* src = (half ? Wl : Wh) +
                (size_t)(t * CO + co0 + col) * CI + ci0 + ck * 8;
            cp16(bb + SLAB_SZ + half * W_HALF + row * 32 +
                 ((ck ^ s3(row)) << 4), src);
        }
    };

    load_chunk(0, 0);
    cp_commit();

    const int a_r = lane & 15;
    const int a_h = lane >> 4;
    const int b_r = (lane & 7) + ((lane >> 4) << 3);
    const int b_h = (lane >> 3) & 1;

    const int NCH = CI / 16;
    for (int ch = 0; ch < NCH; ++ch) {
        const int buf = ch & 1;
        cp_wait0();
        __syncthreads();
        if (ch + 1 < NCH) { load_chunk(ch + 1, buf ^ 1); cp_commit(); }

        const uint32_t bb = sbase + buf * CBUF;
#pragma unroll
        for (int t = 0; t < 7; ++t) {
            const int par = (t + 1) & 1;
            const int shift = (t + 1) >> 1;
            uint32_t aH[2][4], aL[2][4];
#pragma unroll
            for (int mt = 0; mt < 2; ++mt) {
                int e = wm * 32 + mt * 16 + a_r + shift;
                uint32_t sa = bb + par * SLAB_PAR + e * 32 + ((a_h ^ s3(e)) << 4);
                ldm4(aH[mt], sa);
                ldm4(aL[mt], sa + SLAB_HALF);
            }
            uint32_t bH[4][4], bL[4][4];
#pragma unroll
            for (int g = 0; g < 4; ++g) {
                int row = t * 128 + wn * 64 + g * 16 + b_r;
                uint32_t sb = bb + SLAB_SZ + row * 32 + ((b_h ^ s3(row)) << 4);
                ldm4(bH[g], sb);
                ldm4(bL[g], sb + W_HALF);
            }
#pragma unroll
            for (int mt = 0; mt < 2; ++mt)
#pragma unroll
                for (int g = 0; g < 4; ++g) {
                    mma16816(acc[mt][g * 2],     aH[mt], bH[g][0], bH[g][1]);
                    mma16816(acc[mt][g * 2 + 1], aH[mt], bH[g][2], bH[g][3]);
                }
#pragma unroll
            for (int mt = 0; mt < 2; ++mt)
#pragma unroll
                for (int g = 0; g < 4; ++g) {
                    mma16816(acc[mt][g * 2],     aH[mt], bL[g][0], bL[g][1]);
                    mma16816(acc[mt][g * 2 + 1], aH[mt], bL[g][2], bL[g][3]);
                }
#pragma unroll
            for (int mt = 0; mt < 2; ++mt)
#pragma unroll
                for (int g = 0; g < 4; ++g) {
                    mma16816(acc[mt][g * 2],     aL[mt], bH[g][0], bH[g][1]);
                    mma16816(acc[mt][g * 2 + 1], aL[mt], bH[g][2], bH[g][3]);
                }
        }
    }

    const size_t ybase = (size_t)b * (L_out + y_pad) + y_off;
#pragma unroll
    for (int mt = 0; mt < 2; ++mt)
#pragma unroll
        for (int j = 0; j < 8; ++j)
#pragma unroll
            for (int h8 = 0; h8 < 2; ++h8) {
                int l = l0 + wm * 32 + mt * 16 + (lane >> 2) + h8 * 8;
                int co = co0 + wn * 64 + j * 8 + (lane & 3) * 2;
                float v0 = acc[mt][j][h8 * 2]     + __ldg(&bias[co]);
                float v1 = acc[mt][j][h8 * 2 + 1] + __ldg(&bias[co + 1]);
                if (do_relu) { v0 = fmaxf(v0, 0.0f); v1 = fmaxf(v1, 0.0f); }
                __nv_bfloat16 h0 = __float2bfloat16(v0);
                __nv_bfloat16 h1 = __float2bfloat16(v1);
                __nv_bfloat162 hp; hp.x = h0; hp.y = h1;
                __nv_bfloat162 lp;
                lp.x = __float2bfloat16(v0 - __bfloat162float(h0));
                lp.y = __float2bfloat16(v1 - __bfloat162float(h1));
                size_t o = (ybase + l) * CO + co;
                *(__nv_bfloat162*)(Yh + o) = hp;
                *(__nv_bfloat162*)(Yl + o) = lp;
            }
}

// ---------------------------------------------------------------------------
// c2[n] = sum_h codebook[n][h]^2 (exact fp32). One warp per row.
// ---------------------------------------------------------------------------
__global__ void c2_kernel(const float* __restrict__ cb, float* __restrict__ c2) {
    int warp = blockIdx.x * 8 + (threadIdx.x >> 5);
    int lane = threadIdx.x & 31;
    if (warp >= NCODES) return;
    const float* row = cb + (size_t)warp * 512;
    float s = 0.0f;
#pragma unroll
    for (int h = lane; h < 512; h += 32) { float v = row[h]; s = fmaf(v, v, s); }
#pragma unroll
    for (int o = 16; o > 0; o >>= 1) s += __shfl_down_sync(0xffffffffu, s, o);
    if (lane == 0) c2[warp] = s;
}

// ---------------------------------------------------------------------------
// split codebook: cb [8192][512] fp32 -> Bh/Bl [n][k] bf16
// ---------------------------------------------------------------------------
__global__ void split_B(const float* __restrict__ cb,
                        __nv_bfloat16* __restrict__ bh,
                        __nv_bfloat16* __restrict__ bl) {
    int i = blockIdx.x * 256 + threadIdx.x;
    if (i >= NCODES * 512) return;
    float v = cb[i];
    __nv_bfloat16 h = __float2bfloat16(v);
    bh[i] = h;
    bl[i] = __float2bfloat16(v - __bfloat162float(h));
}

// ---------------------------------------------------------------------------
// mma.sync VQ GEMM + argmin, 128m x 256n tile, 256 thr, 8 warps = 2m x 4n.
// Warp tile 64m x 64n. KC=32, double-buffered cp.async.
// smem/buffer: Ah 8K | Al 8K | Bh 16K | Bl 16K = 48 KB.
// ---------------------------------------------------------------------------
#define VBUF 49152

__global__ __launch_bounds__(256, 1) void vq_mma(
        const __nv_bfloat16* __restrict__ Ah, const __nv_bfloat16* __restrict__ Al,
        const __nv_bfloat16* __restrict__ Bh, const __nv_bfloat16* __restrict__ Bl,
        const float* __restrict__ c2, u64* __restrict__ pkey) {
    extern __shared__ __align__(16) char dsm[];          // 2 * 48 KB
    __shared__ u64 sRed[128][4];

    const int tid  = threadIdx.x;
    const int lane = tid & 31;
    const int wid  = tid >> 5;
    const int wm   = wid >> 2;           // 0..1: m block of 64
    const int wn   = wid & 3;            // 0..3: n block of 64
    const int m0 = blockIdx.x * 128;
    const int n0 = blockIdx.y * 256;
    const uint32_t sbase = smem_u32(dsm);

    float acc[4][8][4];
#pragma unroll
    for (int i = 0; i < 4; ++i)
#pragma unroll
        for (int j = 0; j < 8; ++j)
#pragma unroll
            for (int q = 0; q < 4; ++q) acc[i][j][q] = 0.0f;

    // chunk loader: A 1024 cp16 + B 2048 cp16 = 3072 -> 12 per thread
    auto load_chunk = [&](int c, int buf) {
        const int k0 = c * 32;
        const uint32_t bb = sbase + buf * VBUF;
#pragma unroll
        for (int r = 0; r < 12; ++r) {
            int i = tid + r * 256;
            if (i < 1024) {
                int half = i >> 9;
                int j = i & 511;
                int row = j >> 2, cc = j & 3;
                const __nv_bfloat16* src =
                    (half ? Al : Ah) + (size_t)(m0 + row) * 512 + k0 + cc * 8;
                cp16(bb + half * 8192 + swz(row, cc), src);
            } else {
                int j2 = i - 1024;
                int half = j2 >> 10;
                int jj = j2 & 1023;
                int row = jj >> 2, cc = jj & 3;
                const __nv_bfloat16* src =
                    (half ? Bl : Bh) + (size_t)(n0 + row) * 512 + k0 + cc * 8;
                cp16(bb + 16384 + half * 16384 + swz(row, cc), src);
            }
        }
    };

    load_chunk(0, 0);
    cp_commit();

    const int a_r = lane & 15;
    const int a_h = lane >> 4;
    const int b_r = (lane & 7) + ((lane >> 4) << 3);
    const int b_h = (lane >> 3) & 1;

    for (int c = 0; c < 16; ++c) {
        const int buf = c & 1;
        cp_wait0();
        __syncthreads();
        if (c < 15) { load_chunk(c + 1, buf ^ 1); cp_commit(); }

        const uint32_t bb = sbase + buf * VBUF;
#pragma unroll
        for (int s = 0; s < 2; ++s) {
            uint32_t aH[4][4], aL[4][4];
#pragma unroll
            for (int mt = 0; mt < 4; ++mt) {
                int r = wm * 64 + mt * 16 + a_r;
                uint32_t sa = bb + swz(r, s * 2 + a_h);
                ldm4(aH[mt], sa);
                ldm4(aL[mt], sa + 8192);
            }
#pragma unroll
            for (int g = 0; g < 4; ++g) {
                uint32_t bH[4], bL[4];
                int r = wn * 64 + g * 16 + b_r;
                uint32_t sb = bb + 16384 + swz(r, s * 2 + b_h);
                ldm4(bH, sb);
                ldm4(bL, sb + 16384);
#pragma unroll
                for (int mt = 0; mt < 4; ++mt) {
                    mma16816(acc[mt][g * 2],     aH[mt], bH[0], bH[1]);
                    mma16816(acc[mt][g * 2 + 1], aH[mt], bH[2], bH[3]);
                    mma16816(acc[mt][g * 2],     aH[mt], bL[0], bL[1]);
                    mma16816(acc[mt][g * 2 + 1], aH[mt], bL[2], bL[3]);
                    mma16816(acc[mt][g * 2],     aL[mt], bH[0], bH[1]);
                    mma16816(acc[mt][g * 2 + 1], aL[mt], bH[2], bH[3]);
                }
            }
        }
    }

    // c2 for this thread's 16 columns
    float c2v[16];
#pragma unroll
    for (int j = 0; j < 8; ++j)
#pragma unroll
        for (int cb = 0; cb < 2; ++cb)
            c2v[j * 2 + cb] =
                __ldg(&c2[n0 + wn * 64 + j * 8 + (lane & 3) * 2 + cb]);

    // epilogue: per-row argmin (8 rows per thread), shfl-reduce across quad
#pragma unroll
    for (int mt = 0; mt < 4; ++mt)
#pragma unroll
        for (int h = 0; h < 2; ++h) {
            u64 best = ~0ull;
#pragma unroll
            for (int j = 0; j < 8; ++j)
#pragma unroll
                for (int cb = 0; cb < 2; ++cb) {
                    float s = c2v[j * 2 + cb] - 2.0f * acc[mt][j][h * 2 + cb];
                    int n = n0 + wn * 64 + j * 8 + (lane & 3) * 2 + cb;
                    u64 k = dist_key(s, n);
                    if (k < best) best = k;
                }
            u64 o1 = __shfl_xor_sync(0xffffffffu, best, 1);
            if (o1 < best) best = o1;
            u64 o2 = __shfl_xor_sync(0xffffffffu, best, 2);
            if (o2 < best) best = o2;
            if ((lane & 3) == 0) {
                int row = wm * 64 + mt * 16 + (lane >> 2) + h * 8;
                sRed[row][wn] = best;
            }
        }
    __syncthreads();

    if (tid < 128) {
        u64 best = sRed[tid][0];
#pragma unroll
        for (int j = 1; j < 4; ++j) {
            u64 v = sRed[tid][j];
            if (v < best) best = v;
        }
        pkey[(size_t)(m0 + tid) * NT + blockIdx.y] = best;
    }
}

// ---------------------------------------------------------------------------
// Finalize: per (b,l) reduce 8 key-partials per codebook -> tokens (float),
// then emb = mean of the 4 embedding rows.
// ---------------------------------------------------------------------------
__global__ void finalize_kernel(const u64* __restrict__ pkey,
                                const float* __restrict__ emb_table,
                                float* __restrict__ out) {
    __shared__ int tok[KCB];
    const int m = blockIdx.x;
    const int b = m >> 12, l = m & 4095;
    const int tid = threadIdx.x;

    if (tid < KCB) {
        u64 best = ~0ull;
#pragma unroll
        for (int j = 0; j < 8; ++j) {
            u64 v = pkey[(size_t)m * NT + tid * 8 + j];
            if (v < best) best = v;
        }
        int t = ((int)(best & 0xffffffffu)) & (VOCAB - 1);
        tok[tid] = t;
        out[((size_t)b * KCB + tid) * L3O + l] = (float)t;
    }
    __syncthreads();

    float* out_emb = out + (size_t)NB * KCB * L3O;
    int t0 = tok[0], t1 = tok[1], t2 = tok[2], t3 = tok[3];
    for (int h = tid; h < 512; h += 128) {
        float s = emb_table[(size_t)t0 * 512 + h] + emb_table[(size_t)t1 * 512 + h]
                + emb_table[(size_t)t2 * 512 + h] + emb_table[(size_t)t3 * 512 + h];
        out_emb[((size_t)b * L3O + l) * 512 + h] = 0.25f * s;
    }
}

// ---------------------------------------------------------------------------
extern "C" void kernel_launch(void* const* d_in, const int* in_sizes, int n_in,
                              void* d_out, int out_size) {
    const float* audio = (const float*)d_in[0];
    const float* w1    = (const float*)d_in[1];
    const float* b1    = (const float*)d_in[2];
    const float* w2    = (const float*)d_in[3];
    const float* b2    = (const float*)d_in[4];
    const float* w3    = (const float*)d_in[5];
    const float* b3    = (const float*)d_in[6];
    const float* cb    = (const float*)d_in[7];
    const float* emb   = (const float*)d_in[8];
    float* out = (float*)d_out;

    __nv_bfloat16 *x1h, *x1l, *x2h, *x2l, *w2h, *w2l, *w3h, *w3l;
    __nv_bfloat16 *ah, *al, *bh, *bl;
    float* c2p;
    u64* pkey;
    cudaGetSymbolAddress((void**)&x1h, g_X1h);
    cudaGetSymbolAddress((void**)&x1l, g_X1l);
    cudaGetSymbolAddress((void**)&x2h, g_X2h);
    cudaGetSymbolAddress((void**)&x2l, g_X2l);
    cudaGetSymbolAddress((void**)&w2h, g_W2h);
    cudaGetSymbolAddress((void**)&w2l, g_W2l);
    cudaGetSymbolAddress((void**)&w3h, g_W3h);
    cudaGetSymbolAddress((void**)&w3l, g_W3l);
    cudaGetSymbolAddress((void**)&ah,  g_Ah);
    cudaGetSymbolAddress((void**)&al,  g_Al);
    cudaGetSymbolAddress((void**)&bh,  g_Bh);
    cudaGetSymbolAddress((void**)&bl,  g_Bl);
    cudaGetSymbolAddress((void**)&c2p, g_c2);
    cudaGetSymbolAddress((void**)&pkey, g_pkey);

    // prep
    guard_zero<<<(4096 + 8192 + 255) / 256, 256>>>(
        (uint32_t*)x1h, (uint32_t*)x1l, (uint32_t*)x2h, (uint32_t*)x2l);
    split_W<<<(C2C * C1 * 7 + 255) / 256, 256>>>(w2, w2h, w2l, C2C, C1);
    split_W<<<(C3 * C2C * 7 + 255) / 256, 256>>>(w3, w3h, w3l, C3, C2C);
    c2_kernel<<<NCODES / 8, 256>>>(cb, c2p);
    split_B<<<(NCODES * 512 + 255) / 256, 256>>>(cb, bh, bl);

    // conv chain (all tensor-core)
    conv1_kernel<<<dim3(L1O / 2, 1, NB), 256>>>(audio, w1, b1, x1h, x1l);

    cudaFuncSetAttribute(conv_mma<C1>, cudaFuncAttributeMaxDynamicSharedMemorySize,
                         2 * CBUF);
    conv_mma<C1><<<dim3(L2O / 128, C2C / 128, NB), 256, 2 * CBUF>>>(
        x1h, x1l, w2h, w2l, b2, x2h, x2l, L1O, L2O, C2C, 1, 8, 4);

    cudaFuncSetAttribute(conv_mma<C2C>, cudaFuncAttributeMaxDynamicSharedMemorySize,
                         2 * CBUF);
    conv_mma<C2C><<<dim3(L3O / 128, C3 / 128, NB), 256, 2 * CBUF>>>(
        x2h, x2l, w3h, w3l, b3, ah, al, L2O, L3O, C3, 0, 0, 0);

    // vq GEMM + argmin (A comes straight from conv3)
    cudaFuncSetAttribute(vq_mma, cudaFuncAttributeMaxDynamicSharedMemorySize,
                         2 * VBUF);
    vq_mma<<<dim3(MTOT / 128, NCODES / 256), 256, 2 * VBUF>>>(
        ah, al, bh, bl, c2p, pkey);

    finalize_kernel<<<MTOT, 128>>>(pkey, emb, out);
}

// round 10
// speedup vs baseline: 1.1832x; 1.1832x over previous
#include <cuda_runtime.h>
#include <cuda_bf16.h>
#include <cstdint>

// Problem constants
#define NB 4
#define SLEN 32768
#define C1 128
#define C2C 256
#define C3 512
#define L1O 16384
#define L2O 8192
#define L3O 4096
#define VOCAB 2048
#define KCB 4
#define NCODES (KCB * VOCAB)   // 8192
#define MTOT (NB * L3O)        // 16384
#define NGRP 512               // 16-code subgroups per row (8192/16)

typedef unsigned long long u64;

// bf16 split activations, transposed: X [b][pos][CI], 4 guard rows each side.
__device__ ulonglong2 g_X1h[NB * (L1O + 8) * C1 / 8];
__device__ ulonglong2 g_X1l[NB * (L1O + 8) * C1 / 8];
__device__ ulonglong2 g_X2h[NB * (L2O + 8) * C2C / 8];
__device__ ulonglong2 g_X2l[NB * (L2O + 8) * C2C / 8];
// split weights [7][CO][CI]
__device__ ulonglong2 g_W2h[7 * C2C * C1 / 8];
__device__ ulonglong2 g_W2l[7 * C2C * C1 / 8];
__device__ ulonglong2 g_W3h[7 * C3 * C2C / 8];
__device__ ulonglong2 g_W3l[7 * C3 * C2C / 8];
// vq operands
__device__ ulonglong2 g_Ah[MTOT * 512 / 8];      // feats hi  [m][k] (conv3 output)
__device__ ulonglong2 g_Al[MTOT * 512 / 8];
__device__ ulonglong2 g_Bh[NCODES * 512 / 8];    // codes hi  [n][k]
__device__ ulonglong2 g_Bl[NCODES * 512 / 8];
__device__ float  g_c2[NCODES];
__device__ float2 g_an[MTOT];                    // per-row ||Ah||^2, ||Al||^2
__device__ u64    g_gkey[(size_t)MTOT * NGRP];   // per (row, subgroup) min key
__device__ uint32_t g_items[(size_t)MTOT * NGRP];// work list (worst case)
__device__ uint32_t g_misc[4];                   // [0]=count [1]=maxBh2 [2]=maxBl2
__device__ u64    g_res[MTOT * KCB];             // final per (row, cb) key

// ---------------------------------------------------------------------------
// helpers
// ---------------------------------------------------------------------------
__device__ __forceinline__ void cp16(uint32_t dst, const void* src) {
    asm volatile("cp.async.cg.shared.global [%0], [%1], 16;" :: "r"(dst), "l"(src));
}
__device__ __forceinline__ void cp_commit() { asm volatile("cp.async.commit_group;"); }
__device__ __forceinline__ void cp_wait0()  { asm volatile("cp.async.wait_group 0;"); }

__device__ __forceinline__ uint32_t smem_u32(const void* p) {
    return (uint32_t)__cvta_generic_to_shared(p);
}

__device__ __forceinline__ u64 dist_key(float v, int n) {
    unsigned int fb = __float_as_uint(v);
    fb = (fb & 0x80000000u) ? ~fb : (fb | 0x80000000u);
    return ((u64)fb << 32) | (unsigned int)n;
}
__device__ __forceinline__ float key_to_dist(u64 k) {
    unsigned int x = (unsigned int)(k >> 32);
    unsigned int vb = (x & 0x80000000u) ? (x & 0x7fffffffu) : ~x;
    return __uint_as_float(vb);
}
__device__ __forceinline__ unsigned int enc_bits(float v) {
    unsigned int tb = __float_as_uint(v);
    return (tb & 0x80000000u) ? ~tb : (tb | 0x80000000u);
}

__device__ __forceinline__ void ldm4(uint32_t* r, uint32_t addr) {
    asm volatile("ldmatrix.sync.aligned.m8n8.x4.shared.b16 {%0,%1,%2,%3}, [%4];"
                 : "=r"(r[0]), "=r"(r[1]), "=r"(r[2]), "=r"(r[3]) : "r"(addr));
}
__device__ __forceinline__ void mma16816(float* c, const uint32_t* a,
                                         uint32_t b0, uint32_t b1) {
    asm volatile(
        "mma.sync.aligned.m16n8k16.row.col.f32.bf16.bf16.f32 "
        "{%0,%1,%2,%3}, {%4,%5,%6,%7}, {%8,%9}, {%0,%1,%2,%3};"
        : "+f"(c[0]), "+f"(c[1]), "+f"(c[2]), "+f"(c[3])
        : "r"(a[0]), "r"(a[1]), "r"(a[2]), "r"(a[3]), "r"(b0), "r"(b1));
}

// smem swizzle (rows of 64 B = 4 x 16B chunks)
__device__ __forceinline__ int swz(int row, int c) {
    return row * 64 + ((c ^ ((row & 3) ^ ((row >> 2) & 1))) << 4);
}
// conv smem swizzle for 32 B rows (2 chunks)
__device__ __forceinline__ int s3(int row) {
    return (row ^ (row >> 1) ^ (row >> 2)) & 1;
}
// unpack 8 bf16 (uint4) -> 8 floats (exact: bf16 = fp32 top bits)
__device__ __forceinline__ void bf8(const uint4 v, float* o) {
    o[0] = __uint_as_float(v.x << 16); o[1] = __uint_as_float(v.x & 0xffff0000u);
    o[2] = __uint_as_float(v.y << 16); o[3] = __uint_as_float(v.y & 0xffff0000u);
    o[4] = __uint_as_float(v.z << 16); o[5] = __uint_as_float(v.z & 0xffff0000u);
    o[6] = __uint_as_float(v.w << 16); o[7] = __uint_as_float(v.w & 0xffff0000u);
}

// ---------------------------------------------------------------------------
// init: g_res = ~0, misc counters/maxes = 0
// ---------------------------------------------------------------------------
__global__ void init_kernel(u64* res, uint32_t* misc) {
    int i = blockIdx.x * 256 + threadIdx.x;
    if (i < MTOT * KCB) res[i] = ~0ull;
    if (i < 4) misc[i] = 0u;
}

// ---------------------------------------------------------------------------
// guard zeroing: X1/X2 guard rows (4 each side)
// ---------------------------------------------------------------------------
__global__ void guard_zero(uint32_t* x1h, uint32_t* x1l,
                           uint32_t* x2h, uint32_t* x2l) {
    int i = blockIdx.x * 256 + threadIdx.x;
    if (i < 4096) {
        int half = i >> 11, j = i & 2047;
        int b = j >> 9, r = (j >> 6) & 7, w = j & 63;
        int row = (r < 4) ? r : (L1O + r);
        uint32_t* p = half ? x1l : x1h;
        p[(size_t)(b * (L1O + 8) + row) * 64 + w] = 0u;
    } else if (i < 4096 + 8192) {
        int j = i - 4096;
        int half = j >> 12; j &= 4095;
        int b = j >> 10, r = (j >> 7) & 7, w = j & 127;
        int row = (r < 4) ? r : (L2O + r);
        uint32_t* p = half ? x2l : x2h;
        p[(size_t)(b * (L2O + 8) + row) * 128 + w] = 0u;
    }
}

// ---------------------------------------------------------------------------
// split weights: w [CO][CI][7] fp32 -> Wh/Wl [7][CO][CI] bf16
// ---------------------------------------------------------------------------
__global__ void split_W(const float* __restrict__ w,
                        __nv_bfloat16* __restrict__ wh,
                        __nv_bfloat16* __restrict__ wl, int CO, int CI) {
    int i = blockIdx.x * 256 + threadIdx.x;
    if (i >= CO * CI * 7) return;
    int co = i / (CI * 7);
    int r  = i % (CI * 7);
    int ci = r / 7, t = r % 7;
    float v = w[i];
    __nv_bfloat16 h = __float2bfloat16(v);
    wh[((size_t)t * CO + co) * CI + ci] = h;
    wl[((size_t)t * CO + co) * CI + ci] = __float2bfloat16(v - __bfloat162float(h));
}

// ---------------------------------------------------------------------------
// conv1: [B,1,32768] -> relu -> X1 [b][pos][128] bf16 hi/lo (offset 4 rows)
// ---------------------------------------------------------------------------
__global__ void conv1_kernel(const float* __restrict__ x,
                             const float* __restrict__ w,
                             const float* __restrict__ bias,
                             __nv_bfloat16* __restrict__ yh,
                             __nv_bfloat16* __restrict__ yl) {
    int tid = threadIdx.x;
    int co = tid & 127;
    int l  = blockIdx.x * 2 + (tid >> 7);
    int b  = blockIdx.z;
    const float* xb = x + b * SLEN;
    float acc = bias[co];
#pragma unroll
    for (int t = 0; t < 7; ++t) {
        int g = 2 * l + t - 3;
        float xv = (g >= 0 && g < SLEN) ? xb[g] : 0.0f;
        acc = fmaf(w[co * 7 + t], xv, acc);
    }
    acc = fmaxf(acc, 0.0f);
    __nv_bfloat16 h = __float2bfloat16(acc);
    size_t o = (size_t)(b * (L1O + 8) + l + 4) * C1 + co;
    yh[o] = h;
    yl[o] = __float2bfloat16(acc - __bfloat162float(h));
}

// ---------------------------------------------------------------------------
// conv via mma.sync bf16 split (hh + hl + lh) — unchanged from R7.
// ---------------------------------------------------------------------------
#define SLAB_PAR  4352
#define SLAB_HALF 8704
#define SLAB_SZ   17408
#define W_HALF    28672
#define CBUF      74752

template <int CI>
__global__ __launch_bounds__(256, 1) void conv_mma(
        const __nv_bfloat16* __restrict__ Xh, const __nv_bfloat16* __restrict__ Xl,
        const __nv_bfloat16* __restrict__ Wh, const __nv_bfloat16* __restrict__ Wl,
        const float* __restrict__ bias,
        __nv_bfloat16* __restrict__ Yh, __nv_bfloat16* __restrict__ Yl,
        int L_in, int L_out, int CO, int do_relu, int y_pad, int y_off) {
    extern __shared__ __align__(16) char dsm[];
    const uint32_t sbase = smem_u32(dsm);

    const int tid  = threadIdx.x;
    const int lane = tid & 31;
    const int wid  = tid >> 5;
    const int wm   = wid >> 1;
    const int wn   = wid & 1;
    const int l0  = blockIdx.x * 128;
    const int co0 = blockIdx.y * 128;
    const int b   = blockIdx.z;

    float acc[2][8][4];
#pragma unroll
    for (int i = 0; i < 2; ++i)
#pragma unroll
        for (int j = 0; j < 8; ++j)
#pragma unroll
            for (int q = 0; q < 4; ++q) acc[i][j][q] = 0.0f;

    auto load_chunk = [&](int ch, int buf) {
        const int ci0 = ch * 16;
        const uint32_t bb = sbase + buf * CBUF;
        for (int i = tid; i < 262 * 4; i += 256) {
            int rel = i >> 2;
            int half = (i >> 1) & 1, ck = i & 1;
            int e = rel >> 1, par = rel & 1;
            const __nv_bfloat16* src = (half ? Xl : Xh) +
                (size_t)(b * (L_in + 8) + 2 * l0 + rel) * CI + ci0 + ck * 8;
            cp16(bb + half * SLAB_HALF + par * SLAB_PAR + e * 32 +
                 ((ck ^ s3(e)) << 4), src);
        }
#pragma unroll
        for (int r = 0; r < 14; ++r) {
            int i = tid + r * 256;
            int row = i >> 2;
            int half = (i >> 1) & 1, ck = i & 1;
            int t = row >> 7, col = row & 127;
            const __nv_bfloat16* src = (half ? Wl : Wh) +
                (size_t)(t * CO + co0 + col) * CI + ci0 + ck * 8;
            cp16(bb + SLAB_SZ + half * W_HALF + row * 32 +
                 ((ck ^ s3(row)) << 4), src);
        }
    };

    load_chunk(0, 0);
    cp_commit();

    const int a_r = lane & 15;
    const int a_h = lane >> 4;
    const int b_r = (lane & 7) + ((lane >> 4) << 3);
    const int b_h = (lane >> 3) & 1;

    const int NCH = CI / 16;
    for (int ch = 0; ch < NCH; ++ch) {
        const int buf = ch & 1;
        cp_wait0();
        __syncthreads();
        if (ch + 1 < NCH) { load_chunk(ch + 1, buf ^ 1); cp_commit(); }

        const uint32_t bb = sbase + buf * CBUF;
#pragma unroll
        for (int t = 0; t < 7; ++t) {
            const int par = (t + 1) & 1;
            const int shift = (t + 1) >> 1;
            uint32_t aH[2][4], aL[2][4];
#pragma unroll
            for (int mt = 0; mt < 2; ++mt) {
                int e = wm * 32 + mt * 16 + a_r + shift;
                uint32_t sa = bb + par * SLAB_PAR + e * 32 + ((a_h ^ s3(e)) << 4);
                ldm4(aH[mt], sa);
                ldm4(aL[mt], sa + SLAB_HALF);
            }
            uint32_t bH[4][4], bL[4][4];
#pragma unroll
            for (int g = 0; g < 4; ++g) {
                int row = t * 128 + wn * 64 + g * 16 + b_r;
                uint32_t sb = bb + SLAB_SZ + row * 32 + ((b_h ^ s3(row)) << 4);
                ldm4(bH[g], sb);
                ldm4(bL[g], sb + W_HALF);
            }
#pragma unroll
            for (int mt = 0; mt < 2; ++mt)
#pragma unroll
                for (int g = 0; g < 4; ++g) {
                    mma16816(acc[mt][g * 2],     aH[mt], bH[g][0], bH[g][1]);
                    mma16816(acc[mt][g * 2 + 1], aH[mt], bH[g][2], bH[g][3]);
                }
#pragma unroll
            for (int mt = 0; mt < 2; ++mt)
#pragma unroll
                for (int g = 0; g < 4; ++g) {
                    mma16816(acc[mt][g * 2],     aH[mt], bL[g][0], bL[g][1]);
                    mma16816(acc[mt][g * 2 + 1], aH[mt], bL[g][2], bL[g][3]);
                }
#pragma unroll
            for (int mt = 0; mt < 2; ++mt)
#pragma unroll
                for (int g = 0; g < 4; ++g) {
                    mma16816(acc[mt][g * 2],     aL[mt], bH[g][0], bH[g][1]);
                    mma16816(acc[mt][g * 2 + 1], aL[mt], bH[g][2], bH[g][3]);
                }
        }
    }

    const size_t ybase = (size_t)b * (L_out + y_pad) + y_off;
#pragma unroll
    for (int mt = 0; mt < 2; ++mt)
#pragma unroll
        for (int j = 0; j < 8; ++j)
#pragma unroll
            for (int h8 = 0; h8 < 2; ++h8) {
                int l = l0 + wm * 32 + mt * 16 + (lane >> 2) + h8 * 8;
                int co = co0 + wn * 64 + j * 8 + (lane & 3) * 2;
                float v0 = acc[mt][j][h8 * 2]     + __ldg(&bias[co]);
                float v1 = acc[mt][j][h8 * 2 + 1] + __ldg(&bias[co + 1]);
                if (do_relu) { v0 = fmaxf(v0, 0.0f); v1 = fmaxf(v1, 0.0f); }
                __nv_bfloat16 h0 = __float2bfloat16(v0);
                __nv_bfloat16 h1 = __float2bfloat16(v1);
                __nv_bfloat162 hp; hp.x = h0; hp.y = h1;
                __nv_bfloat162 lp;
                lp.x = __float2bfloat16(v0 - __bfloat162float(h0));
                lp.y = __float2bfloat16(v1 - __bfloat162float(h1));
                size_t o = (ybase + l) * CO + co;
                *(__nv_bfloat162*)(Yh + o) = hp;
                *(__nv_bfloat162*)(Yl + o) = lp;
            }
}

// ---------------------------------------------------------------------------
// bnorm: per code, exact c2 + ||Bh||^2/||Bl||^2 with global atomicMax
// ---------------------------------------------------------------------------
__global__ void bnorm_kernel(const float* __restrict__ cb, float* __restrict__ c2,
                             uint32_t* __restrict__ misc) {
    int code = blockIdx.x * 8 + (threadIdx.x >> 5);
    int lane = threadIdx.x & 31;
    if (code >= NCODES) return;
    const float* row = cb + (size_t)code * 512;
    float s = 0.0f, h2 = 0.0f, l2 = 0.0f;
    for (int e = lane; e < 512; e += 32) {
        float v = row[e];
        s = fmaf(v, v, s);
        float hf = __bfloat162float(__float2bfloat16(v));
        float lf = __bfloat162float(__float2bfloat16(v - hf));
        h2 = fmaf(hf, hf, h2);
        l2 = fmaf(lf, lf, l2);
    }
#pragma unroll
    for (int o = 16; o > 0; o >>= 1) {
        s  += __shfl_down_sync(0xffffffffu, s, o);
        h2 += __shfl_down_sync(0xffffffffu, h2, o);
        l2 += __shfl_down_sync(0xffffffffu, l2, o);
    }
    if (lane == 0) {
        c2[code] = s;
        atomicMax(&misc[1], __float_as_uint(h2));   // values >= 0: bit-order ok
        atomicMax(&misc[2], __float_as_uint(l2));
    }
}

// ---------------------------------------------------------------------------
// split codebook: cb [8192][512] fp32 -> Bh/Bl [n][k] bf16
// ---------------------------------------------------------------------------
__global__ void split_B(const float* __restrict__ cb,
                        __nv_bfloat16* __restrict__ bh,
                        __nv_bfloat16* __restrict__ bl) {
    int i = blockIdx.x * 256 + threadIdx.x;
    if (i >= NCODES * 512) return;
    float v = cb[i];
    __nv_bfloat16 h = __float2bfloat16(v);
    bh[i] = h;
    bl[i] = __float2bfloat16(v - __bfloat162float(h));
}

// ---------------------------------------------------------------------------
// anorm: per feats row, ||Ah||^2 and ||Al||^2
// ---------------------------------------------------------------------------
__global__ void anorm_kernel(const __nv_bfloat16* __restrict__ Ah,
                             const __nv_bfloat16* __restrict__ Al,
                             float2* __restrict__ an) {
    int row = blockIdx.x * 8 + (threadIdx.x >> 5);
    int lane = threadIdx.x & 31;
    if (row >= MTOT) return;
    const uint4* ph = (const uint4*)(Ah + (size_t)row * 512 + lane * 16);
    const uint4* pl = (const uint4*)(Al + (size_t)row * 512 + lane * 16);
    float fh[16], fl[16];
    bf8(ph[0], fh); bf8(ph[1], fh + 8);
    bf8(pl[0], fl); bf8(pl[1], fl + 8);
    float sh = 0.0f, sl = 0.0f;
#pragma unroll
    for (int e = 0; e < 16; ++e) {
        sh = fmaf(fh[e], fh[e], sh);
        sl = fmaf(fl[e], fl[e], sl);
    }
#pragma unroll
    for (int o = 16; o > 0; o >>= 1) {
        sh += __shfl_down_sync(0xffffffffu, sh, o);
        sl += __shfl_down_sync(0xffffffffu, sl, o);
    }
    if (lane == 0) an[row] = make_float2(sh, sl);
}

// ---------------------------------------------------------------------------
// Approx VQ GEMM (hh only) + per-(row, 16-code subgroup) min keys.
// 128m x 128n tile, 8 warps = 4m x 2n (R7 geometry), KC=32 double-buffered.
// smem/buffer: Ah 8K | Bh 8K = 16 KB.
// ---------------------------------------------------------------------------
#define VBUF2 16384

__global__ __launch_bounds__(256, 2) void vq_approx(
        const __nv_bfloat16* __restrict__ Ah, const __nv_bfloat16* __restrict__ Bh,
        const float* __restrict__ c2, u64* __restrict__ gkey) {
    extern __shared__ __align__(16) char dsm[];          // 2 * 16 KB
    __shared__ u64 sG[128][8];

    const int tid  = threadIdx.x;
    const int lane = tid & 31;
    const int wid  = tid >> 5;
    const int wm   = wid >> 1;           // 0..3: m block of 32
    const int wn   = wid & 1;            // 0..1: n block of 64
    const int m0 = blockIdx.x * 128;
    const int n0 = blockIdx.y * 128;
    const uint32_t sbase = smem_u32(dsm);

    float acc[2][8][4];
#pragma unroll
    for (int i = 0; i < 2; ++i)
#pragma unroll
        for (int j = 0; j < 8; ++j)
#pragma unroll
            for (int q = 0; q < 4; ++q) acc[i][j][q] = 0.0f;

    auto load_chunk = [&](int c, int buf) {
        const int k0 = c * 32;
        const uint32_t bb = sbase + buf * VBUF2;
#pragma unroll
        for (int r = 0; r < 4; ++r) {
            int i = tid + r * 256;             // 0..1023
            int row = (i >> 2) & 127;
            int cc  = i & 3;
            if (i < 512) {
                cp16(bb + swz(row, cc),
                     Ah + (size_t)(m0 + row) * 512 + k0 + cc * 8);
            } else {
                cp16(bb + 8192 + swz(row, cc),
                     Bh + (size_t)(n0 + row) * 512 + k0 + cc * 8);
            }
        }
    };

    load_chunk(0, 0);
    cp_commit();

    const int a_r = lane & 15;
    const int a_h = lane >> 4;
    const int b_r = (lane & 7) + ((lane >> 4) << 3);
    const int b_h = (lane >> 3) & 1;

    for (int c = 0; c < 16; ++c) {
        const int buf = c & 1;
        cp_wait0();
        __syncthreads();
        if (c < 15) { load_chunk(c + 1, buf ^ 1); cp_commit(); }

        const uint32_t bb = sbase + buf * VBUF2;
#pragma unroll
        for (int s = 0; s < 2; ++s) {
            uint32_t a[2][4];
#pragma unroll
            for (int mt = 0; mt < 2; ++mt) {
                int r = wm * 32 + mt * 16 + a_r;
                ldm4(a[mt], bb + swz(r, s * 2 + a_h));
            }
#pragma unroll
            for (int g = 0; g < 4; ++g) {
                uint32_t bH[4];
                int r = wn * 64 + g * 16 + b_r;
                ldm4(bH, bb + 8192 + swz(r, s * 2 + b_h));
#pragma unroll
                for (int mt = 0; mt < 2; ++mt) {
                    mma16816(acc[mt][g * 2],     a[mt], bH[0], bH[1]);
                    mma16816(acc[mt][g * 2 + 1], a[mt], bH[2], bH[3]);
                }
            }
        }
    }

    // c2 for this thread's 16 columns
    float c2v[16];
#pragma unroll
    for (int j = 0; j < 8; ++j)
#pragma unroll
        for (int cb = 0; cb < 2; ++cb)
            c2v[j * 2 + cb] =
                __ldg(&c2[n0 + wn * 64 + j * 8 + (lane & 3) * 2 + cb]);

    // subgroup (16-code) min keys
#pragma unroll
    for (int mt = 0; mt < 2; ++mt)
#pragma unroll
        for (int h = 0; h < 2; ++h) {
#pragma unroll
            for (int s = 0; s < 4; ++s) {
                u64 best = ~0ull;
#pragma unroll
                for (int jo = 0; jo < 2; ++jo)
#pragma unroll
                    for (int cb = 0; cb < 2; ++cb) {
                        int j = s * 2 + jo;
                        float d = c2v[j * 2 + cb] - 2.0f * acc[mt][j][h * 2 + cb];
                        int n = n0 + wn * 64 + j * 8 + (lane & 3) * 2 + cb;
                        u64 k = dist_key(d, n);
                        if (k < best) best = k;
                    }
                u64 o1 = __shfl_xor_sync(0xffffffffu, best, 1);
                if (o1 < best) best = o1;
                u64 o2 = __shfl_xor_sync(0xffffffffu, best, 2);
                if (o2 < best) best = o2;
                if ((lane & 3) == 0) {
                    int row = wm * 32 + mt * 16 + (lane >> 2) + h * 8;
                    sG[row][wn * 4 + s] = best;
                }
            }
        }
    __syncthreads();

    // coalesced write: per row 8 contiguous u64
    for (int i = tid; i < 1024; i += 256) {
        int row = i >> 3, j = i & 7;
        gkey[(size_t)(m0 + row) * NGRP + blockIdx.y * 8 + j] = sG[row][j];
    }
}

// ---------------------------------------------------------------------------
// flag: per (row, cb) min over 128 subgroup keys, threshold, emit work items
// ---------------------------------------------------------------------------
__global__ void flag_kernel(const u64* __restrict__ gkey,
                            const float2* __restrict__ an,
                            uint32_t* __restrict__ misc,
                            uint32_t* __restrict__ items) {
    int m = blockIdx.x * 8 + (threadIdx.x >> 5);
    int lane = threadIdx.x & 31;
    if (m >= MTOT) return;

    float2 a = an[m];
    float maxBh2 = __uint_as_float(misc[1]);
    float maxBl2 = __uint_as_float(misc[2]);
    float ebound = 2.0f * (sqrtf(a.x * maxBl2) + sqrtf(a.y * maxBh2)
                           + sqrtf(a.y * maxBl2));
    float eps = 1.5f * ebound + 0.5f;

    unsigned int mask = 0;
    u64 kq[4][4];   // [cb][q]
#pragma unroll
    for (int cb = 0; cb < 4; ++cb) {
        u64 mn = ~0ull;
#pragma unroll
        for (int q = 0; q < 4; ++q) {
            u64 k = gkey[(size_t)m * NGRP + cb * 128 + q * 32 + lane];
            kq[cb][q] = k;
            if (k < mn) mn = k;
        }
#pragma unroll
        for (int o = 16; o > 0; o >>= 1) {
            u64 v = __shfl_xor_sync(0xffffffffu, mn, o);
            if (v < mn) mn = v;
        }
        float M = key_to_dist(mn);
        float T = M + 2.0f * eps;
        unsigned int encT = enc_bits(T);
#pragma unroll
        for (int q = 0; q < 4; ++q)
            if ((unsigned int)(kq[cb][q] >> 32) <= encT)
                mask |= 1u << (cb * 4 + q);
    }

    int cnt = __popc(mask);
    int incl = cnt;
#pragma unroll
    for (int o = 1; o < 32; o <<= 1) {
        int v = __shfl_up_sync(0xffffffffu, incl, o);
        if (lane >= o) incl += v;
    }
    int total = __shfl_sync(0xffffffffu, incl, 31);
    unsigned int base = 0;
    if (lane == 31 && total > 0) base = atomicAdd(&misc[0], (unsigned int)total);
    base = __shfl_sync(0xffffffffu, base, 31);
    int off = (int)base + incl - cnt;
    unsigned int mm = mask;
    while (mm) {
        int bpos = __ffs(mm) - 1;
        mm &= mm - 1;
        int cb = bpos >> 2, q = bpos & 3;
        items[off++] = (unsigned int)(m * NGRP + cb * 128 + q * 32 + lane);
    }
}

// ---------------------------------------------------------------------------
// refine: exact fp32 distances for all 16 codes of each flagged subgroup
// ---------------------------------------------------------------------------
__global__ void refine_kernel(const __nv_bfloat16* __restrict__ Ah,
                              const __nv_bfloat16* __restrict__ Al,
                              const __nv_bfloat16* __restrict__ Bh,
                              const __nv_bfloat16* __restrict__ Bl,
                              const float* __restrict__ c2,
                              const uint32_t* __restrict__ misc,
                              const uint32_t* __restrict__ items,
                              u64* __restrict__ res) {
    const int lane = threadIdx.x & 31;
    const int wgid = blockIdx.x * 8 + (threadIdx.x >> 5);
    const int nw = gridDim.x * 8;
    const int cnt = (int)misc[0];

    for (int it = wgid; it < cnt; it += nw) {
        unsigned int item = items[it];
        int m = item >> 9;
        int g = item & 511;
        int cb = g >> 7;
        int n0 = g * 16;

        float f[16], t0[8], t1[8];
        {
            const uint4* ph = (const uint4*)(Ah + (size_t)m * 512 + lane * 16);
            const uint4* pl = (const uint4*)(Al + (size_t)m * 512 + lane * 16);
            uint4 h0 = ph[0], h1 = ph[1], l0v = pl[0], l1v = pl[1];
            bf8(h0, f); bf8(h1, f + 8);
            bf8(l0v, t0); bf8(l1v, t1);
#pragma unroll
            for (int e = 0; e < 8; ++e)  f[e] += t0[e];
#pragma unroll
            for (int e = 0; e < 8; ++e)  f[e + 8] += t1[e];
        }

        u64 best = ~0ull;
#pragma unroll 4
        for (int c = 0; c < 16; ++c) {
            int n = n0 + c;
            const uint4* pb = (const uint4*)(Bh + (size_t)n * 512 + lane * 16);
            const uint4* pq = (const uint4*)(Bl + (size_t)n * 512 + lane * 16);
            uint4 b0 = pb[0], b1 = pb[1], q0 = pq[0], q1 = pq[1];
            float g0[8], g1[8], r0[8], r1[8];
            bf8(b0, g0); bf8(b1, g1); bf8(q0, r0); bf8(q1, r1);
            float dot = 0.0f;
#pragma unroll
            for (int e = 0; e < 8; ++e) dot = fmaf(f[e], g0[e] + r0[e], dot);
#pragma unroll
            for (int e = 0; e < 8; ++e) dot = fmaf(f[e + 8], g1[e] + r1[e], dot);
#pragma unroll
            for (int o = 16; o > 0; o >>= 1)
                dot += __shfl_down_sync(0xffffffffu, dot, o);
            if (lane == 0) {
                float d = __ldg(&c2[n]) - 2.0f * dot;
                u64 k = dist_key(d, n);
                if (k < best) best = k;
            }
        }
        if (lane == 0) atomicMin(&res[m * 4 + cb], best);
    }
}

// ---------------------------------------------------------------------------
// Finalize: tokens from g_res + embedding mean
// ---------------------------------------------------------------------------
__global__ void finalize_kernel(const u64* __restrict__ res,
                                const float* __restrict__ emb_table,
                                float* __restrict__ out) {
    __shared__ int tok[KCB];
    const int m = blockIdx.x;
    const int b = m >> 12, l = m & 4095;
    const int tid = threadIdx.x;

    if (tid < KCB) {
        int t = ((int)(res[m * 4 + tid] & 0xffffffffu)) & (VOCAB - 1);
        tok[tid] = t;
        out[((size_t)b * KCB + tid) * L3O + l] = (float)t;
    }
    __syncthreads();

    float* out_emb = out + (size_t)NB * KCB * L3O;
    int t0 = tok[0], t1 = tok[1], t2 = tok[2], t3 = tok[3];
    for (int h = tid; h < 512; h += 128) {
        float s = emb_table[(size_t)t0 * 512 + h] + emb_table[(size_t)t1 * 512 + h]
                + emb_table[(size_t)t2 * 512 + h] + emb_table[(size_t)t3 * 512 + h];
        out_emb[((size_t)b * L3O + l) * 512 + h] = 0.25f * s;
    }
}

// ---------------------------------------------------------------------------
extern "C" void kernel_launch(void* const* d_in, const int* in_sizes, int n_in,
                              void* d_out, int out_size) {
    const float* audio = (const float*)d_in[0];
    const float* w1    = (const float*)d_in[1];
    const float* b1    = (const float*)d_in[2];
    const float* w2    = (const float*)d_in[3];
    const float* b2    = (const float*)d_in[4];
    const float* w3    = (const float*)d_in[5];
    const float* b3    = (const float*)d_in[6];
    const float* cb    = (const float*)d_in[7];
    const float* emb   = (const float*)d_in[8];
    float* out = (float*)d_out;

    __nv_bfloat16 *x1h, *x1l, *x2h, *x2l, *w2h, *w2l, *w3h, *w3l;
    __nv_bfloat16 *ah, *al, *bh, *bl;
    float* c2p;
    float2* anp;
    u64 *gkeyp, *resp;
    uint32_t *miscp, *itemsp;
    cudaGetSymbolAddress((void**)&x1h, g_X1h);
    cudaGetSymbolAddress((void**)&x1l, g_X1l);
    cudaGetSymbolAddress((void**)&x2h, g_X2h);
    cudaGetSymbolAddress((void**)&x2l, g_X2l);
    cudaGetSymbolAddress((void**)&w2h, g_W2h);
    cudaGetSymbolAddress((void**)&w2l, g_W2l);
    cudaGetSymbolAddress((void**)&w3h, g_W3h);
    cudaGetSymbolAddress((void**)&w3l, g_W3l);
    cudaGetSymbolAddress((void**)&ah,  g_Ah);
    cudaGetSymbolAddress((void**)&al,  g_Al);
    cudaGetSymbolAddress((void**)&bh,  g_Bh);
    cudaGetSymbolAddress((void**)&bl,  g_Bl);
    cudaGetSymbolAddress((void**)&c2p, g_c2);
    cudaGetSymbolAddress((void**)&anp, g_an);
    cudaGetSymbolAddress((void**)&gkeyp, g_gkey);
    cudaGetSymbolAddress((void**)&itemsp, g_items);
    cudaGetSymbolAddress((void**)&miscp, g_misc);
    cudaGetSymbolAddress((void**)&resp, g_res);

    // prep
    init_kernel<<<(MTOT * KCB + 255) / 256, 256>>>(resp, miscp);
    guard_zero<<<(4096 + 8192 + 255) / 256, 256>>>(
        (uint32_t*)x1h, (uint32_t*)x1l, (uint32_t*)x2h, (uint32_t*)x2l);
    split_W<<<(C2C * C1 * 7 + 255) / 256, 256>>>(w2, w2h, w2l, C2C, C1);
    split_W<<<(C3 * C2C * 7 + 255) / 256, 256>>>(w3, w3h, w3l, C3, C2C);
    bnorm_kernel<<<NCODES / 8, 256>>>(cb, c2p, miscp);
    split_B<<<(NCODES * 512 + 255) / 256, 256>>>(cb, bh, bl);

    // conv chain (all tensor-core)
    conv1_kernel<<<dim3(L1O / 2, 1, NB), 256>>>(audio, w1, b1, x1h, x1l);

    cudaFuncSetAttribute(conv_mma<C1>, cudaFuncAttributeMaxDynamicSharedMemorySize,
                         2 * CBUF);
    conv_mma<C1><<<dim3(L2O / 128, C2C / 128, NB), 256, 2 * CBUF>>>(
        x1h, x1l, w2h, w2l, b2, x2h, x2l, L1O, L2O, C2C, 1, 8, 4);

    cudaFuncSetAttribute(conv_mma<C2C>, cudaFuncAttributeMaxDynamicSharedMemorySize,
                         2 * CBUF);
    conv_mma<C2C><<<dim3(L3O / 128, C3 / 128, NB), 256, 2 * CBUF>>>(
        x2h, x2l, w3h, w3l, b3, ah, al, L2O, L3O, C3, 0, 0, 0);

    // feats norms (for the error bound)
    anorm_kernel<<<MTOT / 8, 256>>>(ah, al, anp);

    // approx vq (hh only) -> subgroup keys
    cudaFuncSetAttribute(vq_approx, cudaFuncAttributeMaxDynamicSharedMemorySize,
                         2 * VBUF2);
    vq_approx<<<dim3(MTOT / 128, NCODES / 128), 256, 2 * VBUF2>>>(
        ah, bh, c2p, gkeyp);

    // flag candidate subgroups, then exact refine
    flag_kernel<<<MTOT / 8, 256>>>(gkeyp, anp, miscp, itemsp);
    refine_kernel<<<1024, 256>>>(ah, al, bh, bl, c2p, miscp, itemsp, resp);

    finalize_kernel<<<MTOT, 128>>>(resp, emb, out);
}

// round 11
// speedup vs baseline: 1.3283x; 1.1226x over previous
#include <cuda_runtime.h>
#include <cuda_bf16.h>
#include <cstdint>

// Problem constants
#define NB 4
#define SLEN 32768
#define C1 128
#define C2C 256
#define C3 512
#define L1O 16384
#define L2O 8192
#define L3O 4096
#define VOCAB 2048
#define KCB 4
#define NCODES (KCB * VOCAB)   // 8192
#define MTOT (NB * L3O)        // 16384
#define NGRP 1024              // 8-code subgroups per row (8192/8)

typedef unsigned long long u64;

// bf16 split activations, transposed: X [b][pos][CI], 4 guard rows each side.
__device__ ulonglong2 g_X1h[NB * (L1O + 8) * C1 / 8];
__device__ ulonglong2 g_X1l[NB * (L1O + 8) * C1 / 8];
__device__ ulonglong2 g_X2h[NB * (L2O + 8) * C2C / 8];
__device__ ulonglong2 g_X2l[NB * (L2O + 8) * C2C / 8];
// split weights [7][CO][CI]
__device__ ulonglong2 g_W2h[7 * C2C * C1 / 8];
__device__ ulonglong2 g_W2l[7 * C2C * C1 / 8];
__device__ ulonglong2 g_W3h[7 * C3 * C2C / 8];
__device__ ulonglong2 g_W3l[7 * C3 * C2C / 8];
// vq operands
__device__ ulonglong2 g_Ah[MTOT * 512 / 8];      // feats hi  [m][k] (conv3 output)
__device__ ulonglong2 g_Al[MTOT * 512 / 8];
__device__ ulonglong2 g_Bh[NCODES * 512 / 8];    // codes hi  [n][k]
__device__ ulonglong2 g_Bl[NCODES * 512 / 8];
__device__ float  g_c2[NCODES];
__device__ float2 g_an[MTOT];                    // per-row ||Ah||^2, ||Al||^2
__device__ u64    g_gkey[(size_t)MTOT * NGRP];   // per (row, subgroup) min key
__device__ uint32_t g_items[(size_t)MTOT * NGRP];// work list (worst case)
__device__ uint32_t g_misc[4];                   // [0]=count [1]=maxBh2 [2]=maxBl2
__device__ u64    g_res[MTOT * KCB];             // final per (row, cb) key

// ---------------------------------------------------------------------------
// helpers
// ---------------------------------------------------------------------------
__device__ __forceinline__ void cp16(uint32_t dst, const void* src) {
    asm volatile("cp.async.cg.shared.global [%0], [%1], 16;" :: "r"(dst), "l"(src));
}
__device__ __forceinline__ void cp_commit() { asm volatile("cp.async.commit_group;"); }
__device__ __forceinline__ void cp_wait0()  { asm volatile("cp.async.wait_group 0;"); }

__device__ __forceinline__ uint32_t smem_u32(const void* p) {
    return (uint32_t)__cvta_generic_to_shared(p);
}

__device__ __forceinline__ u64 dist_key(float v, int n) {
    unsigned int fb = __float_as_uint(v);
    fb = (fb & 0x80000000u) ? ~fb : (fb | 0x80000000u);
    return ((u64)fb << 32) | (unsigned int)n;
}
__device__ __forceinline__ float key_to_dist(u64 k) {
    unsigned int x = (unsigned int)(k >> 32);
    unsigned int vb = (x & 0x80000000u) ? (x & 0x7fffffffu) : ~x;
    return __uint_as_float(vb);
}
__device__ __forceinline__ unsigned int enc_bits(float v) {
    unsigned int tb = __float_as_uint(v);
    return (tb & 0x80000000u) ? ~tb : (tb | 0x80000000u);
}

__device__ __forceinline__ void ldm4(uint32_t* r, uint32_t addr) {
    asm volatile("ldmatrix.sync.aligned.m8n8.x4.shared.b16 {%0,%1,%2,%3}, [%4];"
                 : "=r"(r[0]), "=r"(r[1]), "=r"(r[2]), "=r"(r[3]) : "r"(addr));
}
__device__ __forceinline__ void mma16816(float* c, const uint32_t* a,
                                         uint32_t b0, uint32_t b1) {
    asm volatile(
        "mma.sync.aligned.m16n8k16.row.col.f32.bf16.bf16.f32 "
        "{%0,%1,%2,%3}, {%4,%5,%6,%7}, {%8,%9}, {%0,%1,%2,%3};"
        : "+f"(c[0]), "+f"(c[1]), "+f"(c[2]), "+f"(c[3])
        : "r"(a[0]), "r"(a[1]), "r"(a[2]), "r"(a[3]), "r"(b0), "r"(b1));
}

// smem swizzle (rows of 64 B = 4 x 16B chunks)
__device__ __forceinline__ int swz(int row, int c) {
    return row * 64 + ((c ^ ((row & 3) ^ ((row >> 2) & 1))) << 4);
}
// conv smem swizzle for 32 B rows (2 chunks)
__device__ __forceinline__ int s3(int row) {
    return (row ^ (row >> 1) ^ (row >> 2)) & 1;
}
// unpack 8 bf16 (uint4) -> 8 floats (exact: bf16 = fp32 top bits)
__device__ __forceinline__ void bf8(const uint4 v, float* o) {
    o[0] = __uint_as_float(v.x << 16); o[1] = __uint_as_float(v.x & 0xffff0000u);
    o[2] = __uint_as_float(v.y << 16); o[3] = __uint_as_float(v.y & 0xffff0000u);
    o[4] = __uint_as_float(v.z << 16); o[5] = __uint_as_float(v.z & 0xffff0000u);
    o[6] = __uint_as_float(v.w << 16); o[7] = __uint_as_float(v.w & 0xffff0000u);
}

// ---------------------------------------------------------------------------
// prep: res init + guard zeroing + misc counters
// ---------------------------------------------------------------------------
__global__ void prep_kernel(u64* res, uint32_t* misc,
                            uint32_t* x1h, uint32_t* x1l,
                            uint32_t* x2h, uint32_t* x2l) {
    int i = blockIdx.x * 256 + threadIdx.x;
    if (i < MTOT * KCB) res[i] = ~0ull;
    if (i < 4) misc[i] = 0u;
    if (i < 4096) {
        int half = i >> 11, j = i & 2047;
        int b = j >> 9, r = (j >> 6) & 7, w = j & 63;
        int row = (r < 4) ? r : (L1O + r);
        uint32_t* p = half ? x1l : x1h;
        p[(size_t)(b * (L1O + 8) + row) * 64 + w] = 0u;
    } else if (i < 4096 + 8192) {
        int j = i - 4096;
        int half = j >> 12; j &= 4095;
        int b = j >> 10, r = (j >> 7) & 7, w = j & 127;
        int row = (r < 4) ? r : (L2O + r);
        uint32_t* p = half ? x2l : x2h;
        p[(size_t)(b * (L2O + 8) + row) * 128 + w] = 0u;
    }
}

// ---------------------------------------------------------------------------
// split weights: w [CO][CI][7] fp32 -> Wh/Wl [7][CO][CI] bf16
// ---------------------------------------------------------------------------
__global__ void split_W(const float* __restrict__ w,
                        __nv_bfloat16* __restrict__ wh,
                        __nv_bfloat16* __restrict__ wl, int CO, int CI) {
    int i = blockIdx.x * 256 + threadIdx.x;
    if (i >= CO * CI * 7) return;
    int co = i / (CI * 7);
    int r  = i % (CI * 7);
    int ci = r / 7, t = r % 7;
    float v = w[i];
    __nv_bfloat16 h = __float2bfloat16(v);
    wh[((size_t)t * CO + co) * CI + ci] = h;
    wl[((size_t)t * CO + co) * CI + ci] = __float2bfloat16(v - __bfloat162float(h));
}

// ---------------------------------------------------------------------------
// conv1: [B,1,32768] -> relu -> X1 [b][pos][128] bf16 hi/lo (offset 4 rows)
// ---------------------------------------------------------------------------
__global__ void conv1_kernel(const float* __restrict__ x,
                             const float* __restrict__ w,
                             const float* __restrict__ bias,
                             __nv_bfloat16* __restrict__ yh,
                             __nv_bfloat16* __restrict__ yl) {
    int tid = threadIdx.x;
    int co = tid & 127;
    int l  = blockIdx.x * 2 + (tid >> 7);
    int b  = blockIdx.z;
    const float* xb = x + b * SLEN;
    float acc = bias[co];
#pragma unroll
    for (int t = 0; t < 7; ++t) {
        int g = 2 * l + t - 3;
        float xv = (g >= 0 && g < SLEN) ? xb[g] : 0.0f;
        acc = fmaf(w[co * 7 + t], xv, acc);
    }
    acc = fmaxf(acc, 0.0f);
    __nv_bfloat16 h = __float2bfloat16(acc);
    size_t o = (size_t)(b * (L1O + 8) + l + 4) * C1 + co;
    yh[o] = h;
    yl[o] = __float2bfloat16(acc - __bfloat162float(h));
}

// ---------------------------------------------------------------------------
// conv via mma.sync bf16 split (hh + hl + lh) — unchanged from R7.
// ---------------------------------------------------------------------------
#define SLAB_PAR  4352
#define SLAB_HALF 8704
#define SLAB_SZ   17408
#define W_HALF    28672
#define CBUF      74752

template <int CI>
__global__ __launch_bounds__(256, 1) void conv_mma(
        const __nv_bfloat16* __restrict__ Xh, const __nv_bfloat16* __restrict__ Xl,
        const __nv_bfloat16* __restrict__ Wh, const __nv_bfloat16* __restrict__ Wl,
        const float* __restrict__ bias,
        __nv_bfloat16* __restrict__ Yh, __nv_bfloat16* __restrict__ Yl,
        int L_in, int L_out, int CO, int do_relu, int y_pad, int y_off) {
    extern __shared__ __align__(16) char dsm[];
    const uint32_t sbase = smem_u32(dsm);

    const int tid  = threadIdx.x;
    const int lane = tid & 31;
    const int wid  = tid >> 5;
    const int wm   = wid >> 1;
    const int wn   = wid & 1;
    const int l0  = blockIdx.x * 128;
    const int co0 = blockIdx.y * 128;
    const int b   = blockIdx.z;

    float acc[2][8][4];
#pragma unroll
    for (int i = 0; i < 2; ++i)
#pragma unroll
        for (int j = 0; j < 8; ++j)
#pragma unroll
            for (int q = 0; q < 4; ++q) acc[i][j][q] = 0.0f;

    auto load_chunk = [&](int ch, int buf) {
        const int ci0 = ch * 16;
        const uint32_t bb = sbase + buf * CBUF;
        for (int i = tid; i < 262 * 4; i += 256) {
            int rel = i >> 2;
            int half = (i >> 1) & 1, ck = i & 1;
            int e = rel >> 1, par = rel & 1;
            const __nv_bfloat16* src = (half ? Xl : Xh) +
                (size_t)(b * (L_in + 8) + 2 * l0 + rel) * CI + ci0 + ck * 8;
            cp16(bb + half * SLAB_HALF + par * SLAB_PAR + e * 32 +
                 ((ck ^ s3(e)) << 4), src);
        }
#pragma unroll
        for (int r = 0; r < 14; ++r) {
            int i = tid + r * 256;
            int row = i >> 2;
            int half = (i >> 1) & 1, ck = i & 1;
            int t = row >> 7, col = row & 127;
            const __nv_bfloat16* src = (half ? Wl : Wh) +
                (size_t)(t * CO + co0 + col) * CI + ci0 + ck * 8;
            cp16(bb + SLAB_SZ + half * W_HALF + row * 32 +
                 ((ck ^ s3(row)) << 4), src);
        }
    };

    load_chunk(0, 0);
    cp_commit();

    const int a_r = lane & 15;
    const int a_h = lane >> 4;
    const int b_r = (lane & 7) + ((lane >> 4) << 3);
    const int b_h = (lane >> 3) & 1;

    const int NCH = CI / 16;
    for (int ch = 0; ch < NCH; ++ch) {
        const int buf = ch & 1;
        cp_wait0();
        __syncthreads();
        if (ch + 1 < NCH) { load_chunk(ch + 1, buf ^ 1); cp_commit(); }

        const uint32_t bb = sbase + buf * CBUF;
#pragma unroll
        for (int t = 0; t < 7; ++t) {
            const int par = (t + 1) & 1;
            const int shift = (t + 1) >> 1;
            uint32_t aH[2][4], aL[2][4];
#pragma unroll
            for (int mt = 0; mt < 2; ++mt) {
                int e = wm * 32 + mt * 16 + a_r + shift;
                uint32_t sa = bb + par * SLAB_PAR + e * 32 + ((a_h ^ s3(e)) << 4);
                ldm4(aH[mt], sa);
                ldm4(aL[mt], sa + SLAB_HALF);
            }
            uint32_t bH[4][4], bL[4][4];
#pragma unroll
            for (int g = 0; g < 4; ++g) {
                int row = t * 128 + wn * 64 + g * 16 + b_r;
                uint32_t sb = bb + SLAB_SZ + row * 32 + ((b_h ^ s3(row)) << 4);
                ldm4(bH[g], sb);
                ldm4(bL[g], sb + W_HALF);
            }
#pragma unroll
            for (int mt = 0; mt < 2; ++mt)
#pragma unroll
                for (int g = 0; g < 4; ++g) {
                    mma16816(acc[mt][g * 2],     aH[mt], bH[g][0], bH[g][1]);
                    mma16816(acc[mt][g * 2 + 1], aH[mt], bH[g][2], bH[g][3]);
                }
#pragma unroll
            for (int mt = 0; mt < 2; ++mt)
#pragma unroll
                for (int g = 0; g < 4; ++g) {
                    mma16816(acc[mt][g * 2],     aH[mt], bL[g][0], bL[g][1]);
                    mma16816(acc[mt][g * 2 + 1], aH[mt], bL[g][2], bL[g][3]);
                }
#pragma unroll
            for (int mt = 0; mt < 2; ++mt)
#pragma unroll
                for (int g = 0; g < 4; ++g) {
                    mma16816(acc[mt][g * 2],     aL[mt], bH[g][0], bH[g][1]);
                    mma16816(acc[mt][g * 2 + 1], aL[mt], bH[g][2], bH[g][3]);
                }
        }
    }

    const size_t ybase = (size_t)b * (L_out + y_pad) + y_off;
#pragma unroll
    for (int mt = 0; mt < 2; ++mt)
#pragma unroll
        for (int j = 0; j < 8; ++j)
#pragma unroll
            for (int h8 = 0; h8 < 2; ++h8) {
                int l = l0 + wm * 32 + mt * 16 + (lane >> 2) + h8 * 8;
                int co = co0 + wn * 64 + j * 8 + (lane & 3) * 2;
                float v0 = acc[mt][j][h8 * 2]     + __ldg(&bias[co]);
                float v1 = acc[mt][j][h8 * 2 + 1] + __ldg(&bias[co + 1]);
                if (do_relu) { v0 = fmaxf(v0, 0.0f); v1 = fmaxf(v1, 0.0f); }
                __nv_bfloat16 h0 = __float2bfloat16(v0);
                __nv_bfloat16 h1 = __float2bfloat16(v1);
                __nv_bfloat162 hp; hp.x = h0; hp.y = h1;
                __nv_bfloat162 lp;
                lp.x = __float2bfloat16(v0 - __bfloat162float(h0));
                lp.y = __float2bfloat16(v1 - __bfloat162float(h1));
                size_t o = (ybase + l) * CO + co;
                *(__nv_bfloat162*)(Yh + o) = hp;
                *(__nv_bfloat162*)(Yl + o) = lp;
            }
}

// ---------------------------------------------------------------------------
// bnorm: per code, exact c2 + ||Bh||^2/||Bl||^2 with global atomicMax
// ---------------------------------------------------------------------------
__global__ void bnorm_kernel(const float* __restrict__ cb, float* __restrict__ c2,
                             uint32_t* __restrict__ misc) {
    int code = blockIdx.x * 8 + (threadIdx.x >> 5);
    int lane = threadIdx.x & 31;
    if (code >= NCODES) return;
    const float* row = cb + (size_t)code * 512;
    float s = 0.0f, h2 = 0.0f, l2 = 0.0f;
    for (int e = lane; e < 512; e += 32) {
        float v = row[e];
        s = fmaf(v, v, s);
        float hf = __bfloat162float(__float2bfloat16(v));
        float lf = __bfloat162float(__float2bfloat16(v - hf));
        h2 = fmaf(hf, hf, h2);
        l2 = fmaf(lf, lf, l2);
    }
#pragma unroll
    for (int o = 16; o > 0; o >>= 1) {
        s  += __shfl_down_sync(0xffffffffu, s, o);
        h2 += __shfl_down_sync(0xffffffffu, h2, o);
        l2 += __shfl_down_sync(0xffffffffu, l2, o);
    }
    if (lane == 0) {
        c2[code] = s;
        atomicMax(&misc[1], __float_as_uint(h2));
        atomicMax(&misc[2], __float_as_uint(l2));
    }
}

// ---------------------------------------------------------------------------
// split codebook: cb [8192][512] fp32 -> Bh/Bl [n][k] bf16
// ---------------------------------------------------------------------------
__global__ void split_B(const float* __restrict__ cb,
                        __nv_bfloat16* __restrict__ bh,
                        __nv_bfloat16* __restrict__ bl) {
    int i = blockIdx.x * 256 + threadIdx.x;
    if (i >= NCODES * 512) return;
    float v = cb[i];
    __nv_bfloat16 h = __float2bfloat16(v);
    bh[i] = h;
    bl[i] = __float2bfloat16(v - __bfloat162float(h));
}

// ---------------------------------------------------------------------------
// anorm: per feats row, ||Ah||^2 and ||Al||^2
// ---------------------------------------------------------------------------
__global__ void anorm_kernel(const __nv_bfloat16* __restrict__ Ah,
                             const __nv_bfloat16* __restrict__ Al,
                             float2* __restrict__ an) {
    int row = blockIdx.x * 8 + (threadIdx.x >> 5);
    int lane = threadIdx.x & 31;
    if (row >= MTOT) return;
    const uint4* ph = (const uint4*)(Ah + (size_t)row * 512 + lane * 16);
    const uint4* pl = (const uint4*)(Al + (size_t)row * 512 + lane * 16);
    float fh[16], fl[16];
    bf8(ph[0], fh); bf8(ph[1], fh + 8);
    bf8(pl[0], fl); bf8(pl[1], fl + 8);
    float sh = 0.0f, sl = 0.0f;
#pragma unroll
    for (int e = 0; e < 16; ++e) {
        sh = fmaf(fh[e], fh[e], sh);
        sl = fmaf(fl[e], fl[e], sl);
    }
#pragma unroll
    for (int o = 16; o > 0; o >>= 1) {
        sh += __shfl_down_sync(0xffffffffu, sh, o);
        sl += __shfl_down_sync(0xffffffffu, sl, o);
    }
    if (lane == 0) an[row] = make_float2(sh, sl);
}

// ---------------------------------------------------------------------------
// Approx VQ GEMM (hh only) + per-(row, 8-code subgroup) min keys.
// 128m x 128n tile, 8 warps = 4m x 2n, KC=32 double-buffered.
// ---------------------------------------------------------------------------
#define VBUF2 16384

__global__ __launch_bounds__(256, 2) void vq_approx(
        const __nv_bfloat16* __restrict__ Ah, const __nv_bfloat16* __restrict__ Bh,
        const float* __restrict__ c2, u64* __restrict__ gkey) {
    extern __shared__ __align__(16) char dsm[];          // 2 * 16 KB
    __shared__ u64 sG[128][16];

    const int tid  = threadIdx.x;
    const int lane = tid & 31;
    const int wid  = tid >> 5;
    const int wm   = wid >> 1;           // 0..3: m block of 32
    const int wn   = wid & 1;            // 0..1: n block of 64
    const int m0 = blockIdx.x * 128;
    const int n0 = blockIdx.y * 128;
    const uint32_t sbase = smem_u32(dsm);

    float acc[2][8][4];
#pragma unroll
    for (int i = 0; i < 2; ++i)
#pragma unroll
        for (int j = 0; j < 8; ++j)
#pragma unroll
            for (int q = 0; q < 4; ++q) acc[i][j][q] = 0.0f;

    auto load_chunk = [&](int c, int buf) {
        const int k0 = c * 32;
        const uint32_t bb = sbase + buf * VBUF2;
#pragma unroll
        for (int r = 0; r < 4; ++r) {
            int i = tid + r * 256;             // 0..1023
            int row = (i >> 2) & 127;
            int cc  = i & 3;
            if (i < 512) {
                cp16(bb + swz(row, cc),
                     Ah + (size_t)(m0 + row) * 512 + k0 + cc * 8);
            } else {
                cp16(bb + 8192 + swz(row, cc),
                     Bh + (size_t)(n0 + row) * 512 + k0 + cc * 8);
            }
        }
    };

    load_chunk(0, 0);
    cp_commit();

    const int a_r = lane & 15;
    const int a_h = lane >> 4;
    const int b_r = (lane & 7) + ((lane >> 4) << 3);
    const int b_h = (lane >> 3) & 1;

    for (int c = 0; c < 16; ++c) {
        const int buf = c & 1;
        cp_wait0();
        __syncthreads();
        if (c < 15) { load_chunk(c + 1, buf ^ 1); cp_commit(); }

        const uint32_t bb = sbase + buf * VBUF2;
#pragma unroll
        for (int s = 0; s < 2; ++s) {
            uint32_t a[2][4];
#pragma unroll
            for (int mt = 0; mt < 2; ++mt) {
                int r = wm * 32 + mt * 16 + a_r;
                ldm4(a[mt], bb + swz(r, s * 2 + a_h));
            }
#pragma unroll
            for (int g = 0; g < 4; ++g) {
                uint32_t bH[4];
                int r = wn * 64 + g * 16 + b_r;
                ldm4(bH, bb + 8192 + swz(r, s * 2 + b_h));
#pragma unroll
                for (int mt = 0; mt < 2; ++mt) {
                    mma16816(acc[mt][g * 2],     a[mt], bH[0], bH[1]);
                    mma16816(acc[mt][g * 2 + 1], a[mt], bH[2], bH[3]);
                }
            }
        }
    }

    // c2 for this thread's 16 columns
    float c2v[16];
#pragma unroll
    for (int j = 0; j < 8; ++j)
#pragma unroll
        for (int cb = 0; cb < 2; ++cb)
            c2v[j * 2 + cb] =
                __ldg(&c2[n0 + wn * 64 + j * 8 + (lane & 3) * 2 + cb]);

    // per-(row, 8-code subgroup) min keys: one group per j
#pragma unroll
    for (int mt = 0; mt < 2; ++mt)
#pragma unroll
        for (int h = 0; h < 2; ++h) {
#pragma unroll
            for (int j = 0; j < 8; ++j) {
                u64 best = ~0ull;
#pragma unroll
                for (int cb = 0; cb < 2; ++cb) {
                    float d = c2v[j * 2 + cb] - 2.0f * acc[mt][j][h * 2 + cb];
                    int n = n0 + wn * 64 + j * 8 + (lane & 3) * 2 + cb;
                    u64 k = dist_key(d, n);
                    if (k < best) best = k;
                }
                u64 o1 = __shfl_xor_sync(0xffffffffu, best, 1);
                if (o1 < best) best = o1;
                u64 o2 = __shfl_xor_sync(0xffffffffu, best, 2);
                if (o2 < best) best = o2;
                if ((lane & 3) == 0) {
                    int row = wm * 32 + mt * 16 + (lane >> 2) + h * 8;
                    sG[row][wn * 8 + j] = best;
                }
            }
        }
    __syncthreads();

    // coalesced write: per row 16 contiguous u64
    for (int i = tid; i < 2048; i += 256) {
        int row = i >> 4, j = i & 15;
        gkey[(size_t)(m0 + row) * NGRP + blockIdx.y * 16 + j] = sG[row][j];
    }
}

// ---------------------------------------------------------------------------
// flag: per (row, cb) min over 256 subgroup keys, tight threshold, emit items
// ---------------------------------------------------------------------------
__global__ void flag_kernel(const u64* __restrict__ gkey,
                            const float2* __restrict__ an,
                            uint32_t* __restrict__ misc,
                            uint32_t* __restrict__ items) {
    int m = blockIdx.x * 8 + (threadIdx.x >> 5);
    int lane = threadIdx.x & 31;
    if (m >= MTOT) return;

    float2 a = an[m];
    float maxBh2 = __uint_as_float(misc[1]);
    float maxBl2 = __uint_as_float(misc[2]);
    // rigorous per-code error bound (Cauchy-Schwarz on dropped terms)
    float eb = 2.0f * (sqrtf(a.x * maxBl2) + sqrtf(a.y * maxBh2)
                       + sqrtf(a.y * maxBl2));

    unsigned int mask = 0;
#pragma unroll
    for (int cb = 0; cb < 4; ++cb) {
        u64 kq[8];
        u64 mn = ~0ull;
#pragma unroll
        for (int q = 0; q < 8; ++q) {
            u64 k = gkey[(size_t)m * NGRP + cb * 256 + q * 32 + lane];
            kq[q] = k;
            if (k < mn) mn = k;
        }
#pragma unroll
        for (int o = 16; o > 0; o >>= 1) {
            u64 v = __shfl_xor_sync(0xffffffffu, mn, o);
            if (v < mn) mn = v;
        }
        float M = key_to_dist(mn);
        float T = M + 2.0f * eb + 0.25f;     // sufficient: min(g*) <= M + 2eb
        unsigned int encT = enc_bits(T);
#pragma unroll
        for (int q = 0; q < 8; ++q)
            if ((unsigned int)(kq[q] >> 32) <= encT)
                mask |= 1u << (cb * 8 + q);
    }

    int cnt = __popc(mask);
    int incl = cnt;
#pragma unroll
    for (int o = 1; o < 32; o <<= 1) {
        int v = __shfl_up_sync(0xffffffffu, incl, o);
        if (lane >= o) incl += v;
    }
    int total = __shfl_sync(0xffffffffu, incl, 31);
    unsigned int base = 0;
    if (lane == 31 && total > 0) base = atomicAdd(&misc[0], (unsigned int)total);
    base = __shfl_sync(0xffffffffu, base, 31);
    int off = (int)base + incl - cnt;
    unsigned int mm = mask;
    while (mm) {
        int bpos = __ffs(mm) - 1;
        mm &= mm - 1;
        int cb = bpos >> 3, q = bpos & 7;
        items[off++] = (unsigned int)(m * NGRP + cb * 256 + q * 32 + lane);
    }
}

// ---------------------------------------------------------------------------
// refine: exact fp32 distances for all 8 codes of each flagged subgroup
// ---------------------------------------------------------------------------
__global__ void refine_kernel(const __nv_bfloat16* __restrict__ Ah,
                              const __nv_bfloat16* __restrict__ Al,
                              const __nv_bfloat16* __restrict__ Bh,
                              const __nv_bfloat16* __restrict__ Bl,
                              const float* __restrict__ c2,
                              const uint32_t* __restrict__ misc,
                              const uint32_t* __restrict__ items,
                              u64* __restrict__ res) {
    const int lane = threadIdx.x & 31;
    const int wgid = blockIdx.x * 8 + (threadIdx.x >> 5);
    const int nw = gridDim.x * 8;
    const int cnt = (int)misc[0];

    for (int it = wgid; it < cnt; it += nw) {
        unsigned int item = items[it];
        int m = item >> 10;
        int g = item & 1023;
        int cb = g >> 8;
        int n0 = g * 8;

        float f[16], t0[8], t1[8];
        {
            const uint4* ph = (const uint4*)(Ah + (size_t)m * 512 + lane * 16);
            const uint4* pl = (const uint4*)(Al + (size_t)m * 512 + lane * 16);
            uint4 h0 = ph[0], h1 = ph[1], l0v = pl[0], l1v = pl[1];
            bf8(h0, f); bf8(h1, f + 8);
            bf8(l0v, t0); bf8(l1v, t1);
#pragma unroll
            for (int e = 0; e < 8; ++e)  f[e] += t0[e];
#pragma unroll
            for (int e = 0; e < 8; ++e)  f[e + 8] += t1[e];
        }

        u64 best = ~0ull;
#pragma unroll 4
        for (int c = 0; c < 8; ++c) {
            int n = n0 + c;
            const uint4* pb = (const uint4*)(Bh + (size_t)n * 512 + lane * 16);
            const uint4* pq = (const uint4*)(Bl + (size_t)n * 512 + lane * 16);
            uint4 b0 = pb[0], b1 = pb[1], q0 = pq[0], q1 = pq[1];
            float g0[8], g1[8], r0[8], r1[8];
            bf8(b0, g0); bf8(b1, g1); bf8(q0, r0); bf8(q1, r1);
            float dot = 0.0f;
#pragma unroll
            for (int e = 0; e < 8; ++e) dot = fmaf(f[e], g0[e] + r0[e], dot);
#pragma unroll
            for (int e = 0; e < 8; ++e) dot = fmaf(f[e + 8], g1[e] + r1[e], dot);
#pragma unroll
            for (int o = 16; o > 0; o >>= 1)
                dot += __shfl_down_sync(0xffffffffu, dot, o);
            if (lane == 0) {
                float d = __ldg(&c2[n]) - 2.0f * dot;
                u64 k = dist_key(d, n);
                if (k < best) best = k;
            }
        }
        if (lane == 0) atomicMin(&res[m * 4 + cb], best);
    }
}

// ---------------------------------------------------------------------------
// Finalize: tokens from g_res + embedding mean
// ---------------------------------------------------------------------------
__global__ void finalize_kernel(const u64* __restrict__ res,
                                const float* __restrict__ emb_table,
                                float* __restrict__ out) {
    __shared__ int tok[KCB];
    const int m = blockIdx.x;
    const int b = m >> 12, l = m & 4095;
    const int tid = threadIdx.x;

    if (tid < KCB) {
        int t = ((int)(res[m * 4 + tid] & 0xffffffffu)) & (VOCAB - 1);
        tok[tid] = t;
        out[((size_t)b * KCB + tid) * L3O + l] = (float)t;
    }
    __syncthreads();

    float* out_emb = out + (size_t)NB * KCB * L3O;
    int t0 = tok[0], t1 = tok[1], t2 = tok[2], t3 = tok[3];
    for (int h = tid; h < 512; h += 128) {
        float s = emb_table[(size_t)t0 * 512 + h] + emb_table[(size_t)t1 * 512 + h]
                + emb_table[(size_t)t2 * 512 + h] + emb_table[(size_t)t3 * 512 + h];
        out_emb[((size_t)b * L3O + l) * 512 + h] = 0.25f * s;
    }
}

// ---------------------------------------------------------------------------
extern "C" void kernel_launch(void* const* d_in, const int* in_sizes, int n_in,
                              void* d_out, int out_size) {
    const float* audio = (const float*)d_in[0];
    const float* w1    = (const float*)d_in[1];
    const float* b1    = (const float*)d_in[2];
    const float* w2    = (const float*)d_in[3];
    const float* b2    = (const float*)d_in[4];
    const float* w3    = (const float*)d_in[5];
    const float* b3    = (const float*)d_in[6];
    const float* cb    = (const float*)d_in[7];
    const float* emb   = (const float*)d_in[8];
    float* out = (float*)d_out;

    __nv_bfloat16 *x1h, *x1l, *x2h, *x2l, *w2h, *w2l, *w3h, *w3l;
    __nv_bfloat16 *ah, *al, *bh, *bl;
    float* c2p;
    float2* anp;
    u64 *gkeyp, *resp;
    uint32_t *miscp, *itemsp;
    cudaGetSymbolAddress((void**)&x1h, g_X1h);
    cudaGetSymbolAddress((void**)&x1l, g_X1l);
    cudaGetSymbolAddress((void**)&x2h, g_X2h);
    cudaGetSymbolAddress((void**)&x2l, g_X2l);
    cudaGetSymbolAddress((void**)&w2h, g_W2h);
    cudaGetSymbolAddress((void**)&w2l, g_W2l);
    cudaGetSymbolAddress((void**)&w3h, g_W3h);
    cudaGetSymbolAddress((void**)&w3l, g_W3l);
    cudaGetSymbolAddress((void**)&ah,  g_Ah);
    cudaGetSymbolAddress((void**)&al,  g_Al);
    cudaGetSymbolAddress((void**)&bh,  g_Bh);
    cudaGetSymbolAddress((void**)&bl,  g_Bl);
    cudaGetSymbolAddress((void**)&c2p, g_c2);
    cudaGetSymbolAddress((void**)&anp, g_an);
    cudaGetSymbolAddress((void**)&gkeyp, g_gkey);
    cudaGetSymbolAddress((void**)&itemsp, g_items);
    cudaGetSymbolAddress((void**)&miscp, g_misc);
    cudaGetSymbolAddress((void**)&resp, g_res);

    // prep (res init + guards + misc) and codebook prep
    prep_kernel<<<(MTOT * KCB + 255) / 256, 256>>>(
        resp, miscp, (uint32_t*)x1h, (uint32_t*)x1l, (uint32_t*)x2h, (uint32_t*)x2l);
    split_W<<<(C2C * C1 * 7 + 255) / 256, 256>>>(w2, w2h, w2l, C2C, C1);
    split_W<<<(C3 * C2C * 7 + 255) / 256, 256>>>(w3, w3h, w3l, C3, C2C);
    bnorm_kernel<<<NCODES / 8, 256>>>(cb, c2p, miscp);
    split_B<<<(NCODES * 512 + 255) / 256, 256>>>(cb, bh, bl);

    // conv chain (all tensor-core)
    conv1_kernel<<<dim3(L1O / 2, 1, NB), 256>>>(audio, w1, b1, x1h, x1l);

    cudaFuncSetAttribute(conv_mma<C1>, cudaFuncAttributeMaxDynamicSharedMemorySize,
                         2 * CBUF);
    conv_mma<C1><<<dim3(L2O / 128, C2C / 128, NB), 256, 2 * CBUF>>>(
        x1h, x1l, w2h, w2l, b2, x2h, x2l, L1O, L2O, C2C, 1, 8, 4);

    cudaFuncSetAttribute(conv_mma<C2C>, cudaFuncAttributeMaxDynamicSharedMemorySize,
                         2 * CBUF);
    conv_mma<C2C><<<dim3(L3O / 128, C3 / 128, NB), 256, 2 * CBUF>>>(
        x2h, x2l, w3h, w3l, b3, ah, al, L2O, L3O, C3, 0, 0, 0);

    // feats norms (for the error bound)
    anorm_kernel<<<MTOT / 8, 256>>>(ah, al, anp);

    // approx vq (hh only) -> 8-code subgroup keys
    cudaFuncSetAttribute(vq_approx, cudaFuncAttributeMaxDynamicSharedMemorySize,
                         2 * VBUF2);
    vq_approx<<<dim3(MTOT / 128, NCODES / 128), 256, 2 * VBUF2>>>(
        ah, bh, c2p, gkeyp);

    // flag candidate subgroups, then exact refine
    flag_kernel<<<MTOT / 8, 256>>>(gkeyp, anp, miscp, itemsp);
    refine_kernel<<<1024, 256>>>(ah, al, bh, bl, c2p, miscp, itemsp, resp);

    finalize_kernel<<<MTOT, 128>>>(resp, emb, out);
}

// round 12
// speedup vs baseline: 1.4034x; 1.0565x over previous
#include <cuda_runtime.h>
#include <cuda_bf16.h>
#include <cstdint>

// Problem constants
#define NB 4
#define SLEN 32768
#define C1 128
#define C2C 256
#define C3 512
#define L1O 16384
#define L2O 8192
#define L3O 4096
#define VOCAB 2048
#define KCB 4
#define NCODES (KCB * VOCAB)   // 8192
#define MTOT (NB * L3O)        // 16384
#define NGRP 1024              // 8-code subgroups per row (8192/8)

typedef unsigned long long u64;

// bf16 split activations, transposed: X [b][pos][CI], 4 guard rows each side.
__device__ ulonglong2 g_X1h[NB * (L1O + 8) * C1 / 8];
__device__ ulonglong2 g_X1l[NB * (L1O + 8) * C1 / 8];
__device__ ulonglong2 g_X2h[NB * (L2O + 8) * C2C / 8];
__device__ ulonglong2 g_X2l[NB * (L2O + 8) * C2C / 8];
// split weights [7][CO][CI]
__device__ ulonglong2 g_W2h[7 * C2C * C1 / 8];
__device__ ulonglong2 g_W2l[7 * C2C * C1 / 8];
__device__ ulonglong2 g_W3h[7 * C3 * C2C / 8];
__device__ ulonglong2 g_W3l[7 * C3 * C2C / 8];
// vq operands
__device__ ulonglong2 g_Ah[MTOT * 512 / 8];      // feats hi  [m][k] (conv3 output)
__device__ ulonglong2 g_Al[MTOT * 512 / 8];
__device__ ulonglong2 g_Bh[NCODES * 512 / 8];    // codes hi  [n][k]
__device__ ulonglong2 g_Bl[NCODES * 512 / 8];
__device__ float  g_c2[NCODES];
__device__ float  g_thr[MTOT];                   // per-row threshold 2*eb + 0.25
__device__ u64    g_gkey[(size_t)MTOT * NGRP];   // per (row, subgroup) min key+mask
__device__ uint32_t g_items[(size_t)MTOT * NGRP];// work list (worst case)
__device__ uint32_t g_misc[4];                   // [0]=count [1]=maxBh2 [2]=maxBl2
__device__ u64    g_res[MTOT * KCB];             // final per (row, cb) key

// ---------------------------------------------------------------------------
// helpers
// ---------------------------------------------------------------------------
__device__ __forceinline__ void cp16(uint32_t dst, const void* src) {
    asm volatile("cp.async.cg.shared.global [%0], [%1], 16;" :: "r"(dst), "l"(src));
}
__device__ __forceinline__ void cp_commit() { asm volatile("cp.async.commit_group;"); }
__device__ __forceinline__ void cp_wait0()  { asm volatile("cp.async.wait_group 0;"); }

__device__ __forceinline__ uint32_t smem_u32(const void* p) {
    return (uint32_t)__cvta_generic_to_shared(p);
}

__device__ __forceinline__ u64 dist_key(float v, int n) {
    unsigned int fb = __float_as_uint(v);
    fb = (fb & 0x80000000u) ? ~fb : (fb | 0x80000000u);
    return ((u64)fb << 32) | (unsigned int)n;
}
__device__ __forceinline__ float key_to_dist(u64 k) {
    unsigned int x = (unsigned int)(k >> 32);
    unsigned int vb = (x & 0x80000000u) ? (x & 0x7fffffffu) : ~x;
    return __uint_as_float(vb);
}
__device__ __forceinline__ unsigned int enc_bits(float v) {
    unsigned int tb = __float_as_uint(v);
    return (tb & 0x80000000u) ? ~tb : (tb | 0x80000000u);
}

__device__ __forceinline__ void ldm4(uint32_t* r, uint32_t addr) {
    asm volatile("ldmatrix.sync.aligned.m8n8.x4.shared.b16 {%0,%1,%2,%3}, [%4];"
                 : "=r"(r[0]), "=r"(r[1]), "=r"(r[2]), "=r"(r[3]) : "r"(addr));
}
__device__ __forceinline__ void mma16816(float* c, const uint32_t* a,
                                         uint32_t b0, uint32_t b1) {
    asm volatile(
        "mma.sync.aligned.m16n8k16.row.col.f32.bf16.bf16.f32 "
        "{%0,%1,%2,%3}, {%4,%5,%6,%7}, {%8,%9}, {%0,%1,%2,%3};"
        : "+f"(c[0]), "+f"(c[1]), "+f"(c[2]), "+f"(c[3])
        : "r"(a[0]), "r"(a[1]), "r"(a[2]), "r"(a[3]), "r"(b0), "r"(b1));
}

// smem swizzle (rows of 64 B = 4 x 16B chunks)
__device__ __forceinline__ int swz(int row, int c) {
    return row * 64 + ((c ^ ((row & 3) ^ ((row >> 2) & 1))) << 4);
}
// conv smem swizzle for 32 B rows (2 chunks)
__device__ __forceinline__ int s3(int row) {
    return (row ^ (row >> 1) ^ (row >> 2)) & 1;
}
// unpack 8 bf16 (uint4) -> 8 floats (exact: bf16 = fp32 top bits)
__device__ __forceinline__ void bf8(const uint4 v, float* o) {
    o[0] = __uint_as_float(v.x << 16); o[1] = __uint_as_float(v.x & 0xffff0000u);
    o[2] = __uint_as_float(v.y << 16); o[3] = __uint_as_float(v.y & 0xffff0000u);
    o[4] = __uint_as_float(v.z << 16); o[5] = __uint_as_float(v.z & 0xffff0000u);
    o[6] = __uint_as_float(v.w << 16); o[7] = __uint_as_float(v.w & 0xffff0000u);
}

// ---------------------------------------------------------------------------
// prep: res init + guard zeroing + misc counters
// ---------------------------------------------------------------------------
__global__ void prep_kernel(u64* res, uint32_t* misc,
                            uint32_t* x1h, uint32_t* x1l,
                            uint32_t* x2h, uint32_t* x2l) {
    int i = blockIdx.x * 256 + threadIdx.x;
    if (i < MTOT * KCB) res[i] = ~0ull;
    if (i < 4) misc[i] = 0u;
    if (i < 4096) {
        int half = i >> 11, j = i & 2047;
        int b = j >> 9, r = (j >> 6) & 7, w = j & 63;
        int row = (r < 4) ? r : (L1O + r);
        uint32_t* p = half ? x1l : x1h;
        p[(size_t)(b * (L1O + 8) + row) * 64 + w] = 0u;
    } else if (i < 4096 + 8192) {
        int j = i - 4096;
        int half = j >> 12; j &= 4095;
        int b = j >> 10, r = (j >> 7) & 7, w = j & 127;
        int row = (r < 4) ? r : (L2O + r);
        uint32_t* p = half ? x2l : x2h;
        p[(size_t)(b * (L2O + 8) + row) * 128 + w] = 0u;
    }
}

// ---------------------------------------------------------------------------
// split weights: w [CO][CI][7] fp32 -> Wh/Wl [7][CO][CI] bf16
// ---------------------------------------------------------------------------
__global__ void split_W(const float* __restrict__ w,
                        __nv_bfloat16* __restrict__ wh,
                        __nv_bfloat16* __restrict__ wl, int CO, int CI) {
    int i = blockIdx.x * 256 + threadIdx.x;
    if (i >= CO * CI * 7) return;
    int co = i / (CI * 7);
    int r  = i % (CI * 7);
    int ci = r / 7, t = r % 7;
    float v = w[i];
    __nv_bfloat16 h = __float2bfloat16(v);
    wh[((size_t)t * CO + co) * CI + ci] = h;
    wl[((size_t)t * CO + co) * CI + ci] = __float2bfloat16(v - __bfloat162float(h));
}

// ---------------------------------------------------------------------------
// conv1: [B,1,32768] -> relu -> X1 [b][pos][128] bf16 hi/lo (offset 4 rows)
// ---------------------------------------------------------------------------
__global__ void conv1_kernel(const float* __restrict__ x,
                             const float* __restrict__ w,
                             const float* __restrict__ bias,
                             __nv_bfloat16* __restrict__ yh,
                             __nv_bfloat16* __restrict__ yl) {
    int tid = threadIdx.x;
    int co = tid & 127;
    int l  = blockIdx.x * 2 + (tid >> 7);
    int b  = blockIdx.z;
    const float* xb = x + b * SLEN;
    float acc = bias[co];
#pragma unroll
    for (int t = 0; t < 7; ++t) {
        int g = 2 * l + t - 3;
        float xv = (g >= 0 && g < SLEN) ? xb[g] : 0.0f;
        acc = fmaf(w[co * 7 + t], xv, acc);
    }
    acc = fmaxf(acc, 0.0f);
    __nv_bfloat16 h = __float2bfloat16(acc);
    size_t o = (size_t)(b * (L1O + 8) + l + 4) * C1 + co;
    yh[o] = h;
    yl[o] = __float2bfloat16(acc - __bfloat162float(h));
}

// ---------------------------------------------------------------------------
// conv via mma.sync bf16 split (hh + hl + lh) — unchanged from R7.
// ---------------------------------------------------------------------------
#define SLAB_PAR  4352
#define SLAB_HALF 8704
#define SLAB_SZ   17408
#define W_HALF    28672
#define CBUF      74752

template <int CI>
__global__ __launch_bounds__(256, 1) void conv_mma(
        const __nv_bfloat16* __restrict__ Xh, const __nv_bfloat16* __restrict__ Xl,
        const __nv_bfloat16* __restrict__ Wh, const __nv_bfloat16* __restrict__ Wl,
        const float* __restrict__ bias,
        __nv_bfloat16* __restrict__ Yh, __nv_bfloat16* __restrict__ Yl,
        int L_in, int L_out, int CO, int do_relu, int y_pad, int y_off) {
    extern __shared__ __align__(16) char dsm[];
    const uint32_t sbase = smem_u32(dsm);

    const int tid  = threadIdx.x;
    const int lane = tid & 31;
    const int wid  = tid >> 5;
    const int wm   = wid >> 1;
    const int wn   = wid & 1;
    const int l0  = blockIdx.x * 128;
    const int co0 = blockIdx.y * 128;
    const int b   = blockIdx.z;

    float acc[2][8][4];
#pragma unroll
    for (int i = 0; i < 2; ++i)
#pragma unroll
        for (int j = 0; j < 8; ++j)
#pragma unroll
            for (int q = 0; q < 4; ++q) acc[i][j][q] = 0.0f;

    auto load_chunk = [&](int ch, int buf) {
        const int ci0 = ch * 16;
        const uint32_t bb = sbase + buf * CBUF;
        for (int i = tid; i < 262 * 4; i += 256) {
            int rel = i >> 2;
            int half = (i >> 1) & 1, ck = i & 1;
            int e = rel >> 1, par = rel & 1;
            const __nv_bfloat16* src = (half ? Xl : Xh) +
                (size_t)(b * (L_in + 8) + 2 * l0 + rel) * CI + ci0 + ck * 8;
            cp16(bb + half * SLAB_HALF + par * SLAB_PAR + e * 32 +
                 ((ck ^ s3(e)) << 4), src);
        }
#pragma unroll
        for (int r = 0; r < 14; ++r) {
            int i = tid + r * 256;
            int row = i >> 2;
            int half = (i >> 1) & 1, ck = i & 1;
            int t = row >> 7, col = row & 127;
            const __nv_bfloat16* src = (half ? Wl : Wh) +
                (size_t)(t * CO + co0 + col) * CI + ci0 + ck * 8;
            cp16(bb + SLAB_SZ + half * W_HALF + row * 32 +
                 ((ck ^ s3(row)) << 4), src);
        }
    };

    load_chunk(0, 0);
    cp_commit();

    const int a_r = lane & 15;
    const int a_h = lane >> 4;
    const int b_r = (lane & 7) + ((lane >> 4) << 3);
    const int b_h = (lane >> 3) & 1;

    const int NCH = CI / 16;
    for (int ch = 0; ch < NCH; ++ch) {
        const int buf = ch & 1;
        cp_wait0();
        __syncthreads();
        if (ch + 1 < NCH) { load_chunk(ch + 1, buf ^ 1); cp_commit(); }

        const uint32_t bb = sbase + buf * CBUF;
#pragma unroll
        for (int t = 0; t < 7; ++t) {
            const int par = (t + 1) & 1;
            const int shift = (t + 1) >> 1;
            uint32_t aH[2][4], aL[2][4];
#pragma unroll
            for (int mt = 0; mt < 2; ++mt) {
                int e = wm * 32 + mt * 16 + a_r + shift;
                uint32_t sa = bb + par * SLAB_PAR + e * 32 + ((a_h ^ s3(e)) << 4);
                ldm4(aH[mt], sa);
                ldm4(aL[mt], sa + SLAB_HALF);
            }
            uint32_t bH[4][4], bL[4][4];
#pragma unroll
            for (int g = 0; g < 4; ++g) {
                int row = t * 128 + wn * 64 + g * 16 + b_r;
                uint32_t sb = bb + SLAB_SZ + row * 32 + ((b_h ^ s3(row)) << 4);
                ldm4(bH[g], sb);
                ldm4(bL[g], sb + W_HALF);
            }
#pragma unroll
            for (int mt = 0; mt < 2; ++mt)
#pragma unroll
                for (int g = 0; g < 4; ++g) {
                    mma16816(acc[mt][g * 2],     aH[mt], bH[g][0], bH[g][1]);
                    mma16816(acc[mt][g * 2 + 1], aH[mt], bH[g][2], bH[g][3]);
                }
#pragma unroll
            for (int mt = 0; mt < 2; ++mt)
#pragma unroll
                for (int g = 0; g < 4; ++g) {
                    mma16816(acc[mt][g * 2],     aH[mt], bL[g][0], bL[g][1]);
                    mma16816(acc[mt][g * 2 + 1], aH[mt], bL[g][2], bL[g][3]);
                }
#pragma unroll
            for (int mt = 0; mt < 2; ++mt)
#pragma unroll
                for (int g = 0; g < 4; ++g) {
                    mma16816(acc[mt][g * 2],     aL[mt], bH[g][0], bH[g][1]);
                    mma16816(acc[mt][g * 2 + 1], aL[mt], bH[g][2], bH[g][3]);
                }
        }
    }

    const size_t ybase = (size_t)b * (L_out + y_pad) + y_off;
#pragma unroll
    for (int mt = 0; mt < 2; ++mt)
#pragma unroll
        for (int j = 0; j < 8; ++j)
#pragma unroll
            for (int h8 = 0; h8 < 2; ++h8) {
                int l = l0 + wm * 32 + mt * 16 + (lane >> 2) + h8 * 8;
                int co = co0 + wn * 64 + j * 8 + (lane & 3) * 2;
                float v0 = acc[mt][j][h8 * 2]     + __ldg(&bias[co]);
                float v1 = acc[mt][j][h8 * 2 + 1] + __ldg(&bias[co + 1]);
                if (do_relu) { v0 = fmaxf(v0, 0.0f); v1 = fmaxf(v1, 0.0f); }
                __nv_bfloat16 h0 = __float2bfloat16(v0);
                __nv_bfloat16 h1 = __float2bfloat16(v1);
                __nv_bfloat162 hp; hp.x = h0; hp.y = h1;
                __nv_bfloat162 lp;
                lp.x = __float2bfloat16(v0 - __bfloat162float(h0));
                lp.y = __float2bfloat16(v1 - __bfloat162float(h1));
                size_t o = (ybase + l) * CO + co;
                *(__nv_bfloat162*)(Yh + o) = hp;
                *(__nv_bfloat162*)(Yl + o) = lp;
            }
}

// ---------------------------------------------------------------------------
// fused split_B + bnorm: one pass over cb -> Bh/Bl + c2 + max split norms
// One warp per code row; lane handles 16 contiguous elements.
// ---------------------------------------------------------------------------
__global__ void splitb_kernel(const float* __restrict__ cb,
                              __nv_bfloat16* __restrict__ bh,
                              __nv_bfloat16* __restrict__ bl,
                              float* __restrict__ c2,
                              uint32_t* __restrict__ misc) {
    int code = blockIdx.x * 8 + (threadIdx.x >> 5);
    int lane = threadIdx.x & 31;
    if (code >= NCODES) return;
    const float* row = cb + (size_t)code * 512 + lane * 16;
    float s = 0.0f, h2 = 0.0f, l2 = 0.0f;
    unsigned int hw[8], lw[8];          // 16 bf16 packed as 8 u32 per half
#pragma unroll
    for (int q = 0; q < 4; ++q) {
        float4 v = *(const float4*)(row + q * 4);
        float vv[4] = {v.x, v.y, v.z, v.w};
#pragma unroll
        for (int e = 0; e < 2; ++e) {
            float a0 = vv[e * 2], a1 = vv[e * 2 + 1];
            __nv_bfloat16 hb0 = __float2bfloat16(a0);
            __nv_bfloat16 hb1 = __float2bfloat16(a1);
            float hf0 = __bfloat162float(hb0), hf1 = __bfloat162float(hb1);
            float lf0 = a0 - hf0, lf1 = a1 - hf1;
            __nv_bfloat16 lb0 = __float2bfloat16(lf0);
            __nv_bfloat16 lb1 = __float2bfloat16(lf1);
            float lq0 = __bfloat162float(lb0), lq1 = __bfloat162float(lb1);
            __nv_bfloat162 hp; hp.x = hb0; hp.y = hb1;
            __nv_bfloat162 lp; lp.x = lb0; lp.y = lb1;
            hw[q * 2 + e] = *(unsigned int*)&hp;
            lw[q * 2 + e] = *(unsigned int*)&lp;
            s  = fmaf(a0, a0, fmaf(a1, a1, s));
            h2 = fmaf(hf0, hf0, fmaf(hf1, hf1, h2));
            l2 = fmaf(lq0, lq0, fmaf(lq1, lq1, l2));
        }
    }
    uint4* dh = (uint4*)(bh + (size_t)code * 512 + lane * 16);
    uint4* dl = (uint4*)(bl + (size_t)code * 512 + lane * 16);
    dh[0] = make_uint4(hw[0], hw[1], hw[2], hw[3]);
    dh[1] = make_uint4(hw[4], hw[5], hw[6], hw[7]);
    dl[0] = make_uint4(lw[0], lw[1], lw[2], lw[3]);
    dl[1] = make_uint4(lw[4], lw[5], lw[6], lw[7]);
#pragma unroll
    for (int o = 16; o > 0; o >>= 1) {
        s  += __shfl_down_sync(0xffffffffu, s, o);
        h2 += __shfl_down_sync(0xffffffffu, h2, o);
        l2 += __shfl_down_sync(0xffffffffu, l2, o);
    }
    if (lane == 0) {
        c2[code] = s;
        atomicMax(&misc[1], __float_as_uint(h2));
        atomicMax(&misc[2], __float_as_uint(l2));
    }
}

// ---------------------------------------------------------------------------
// thr: per feats row, threshold 2*eb + 0.25 from split norms
// ---------------------------------------------------------------------------
__global__ void thr_kernel(const __nv_bfloat16* __restrict__ Ah,
                           const __nv_bfloat16* __restrict__ Al,
                           const uint32_t* __restrict__ misc,
                           float* __restrict__ thr) {
    int row = blockIdx.x * 8 + (threadIdx.x >> 5);
    int lane = threadIdx.x & 31;
    if (row >= MTOT) return;
    const uint4* ph = (const uint4*)(Ah + (size_t)row * 512 + lane * 16);
    const uint4* pl = (const uint4*)(Al + (size_t)row * 512 + lane * 16);
    float fh[16], fl[16];
    bf8(ph[0], fh); bf8(ph[1], fh + 8);
    bf8(pl[0], fl); bf8(pl[1], fl + 8);
    float sh = 0.0f, sl = 0.0f;
#pragma unroll
    for (int e = 0; e < 16; ++e) {
        sh = fmaf(fh[e], fh[e], sh);
        sl = fmaf(fl[e], fl[e], sl);
    }
#pragma unroll
    for (int o = 16; o > 0; o >>= 1) {
        sh += __shfl_down_sync(0xffffffffu, sh, o);
        sl += __shfl_down_sync(0xffffffffu, sl, o);
    }
    if (lane == 0) {
        float maxBh2 = __uint_as_float(misc[1]);
        float maxBl2 = __uint_as_float(misc[2]);
        float eb = 2.0f * (sqrtf(sh * maxBl2) + sqrtf(sl * maxBh2)
                           + sqrtf(sl * maxBl2));
        thr[row] = 2.0f * eb + 0.25f;
    }
}

// ---------------------------------------------------------------------------
// Approx VQ GEMM (hh only) + per-(row, 8-code subgroup) min key + cand mask.
// Key layout: [dist 32][pad][mask 8 @bits 13..20][n 13 @bits 0..12]
// ---------------------------------------------------------------------------
#define VBUF2 16384

__global__ __launch_bounds__(256, 2) void vq_approx(
        const __nv_bfloat16* __restrict__ Ah, const __nv_bfloat16* __restrict__ Bh,
        const float* __restrict__ c2, const float* __restrict__ thr,
        u64* __restrict__ gkey) {
    extern __shared__ __align__(16) char dsm[];          // 2 * 16 KB
    __shared__ u64 sG[128][16];

    const int tid  = threadIdx.x;
    const int lane = tid & 31;
    const int wid  = tid >> 5;
    const int wm   = wid >> 1;           // 0..3: m block of 32
    const int wn   = wid & 1;            // 0..1: n block of 64
    const int m0 = blockIdx.x * 128;
    const int n0 = blockIdx.y * 128;
    const uint32_t sbase = smem_u32(dsm);

    float acc[2][8][4];
#pragma unroll
    for (int i = 0; i < 2; ++i)
#pragma unroll
        for (int j = 0; j < 8; ++j)
#pragma unroll
            for (int q = 0; q < 4; ++q) acc[i][j][q] = 0.0f;

    auto load_chunk = [&](int c, int buf) {
        const int k0 = c * 32;
        const uint32_t bb = sbase + buf * VBUF2;
#pragma unroll
        for (int r = 0; r < 4; ++r) {
            int i = tid + r * 256;             // 0..1023
            int row = (i >> 2) & 127;
            int cc  = i & 3;
            if (i < 512) {
                cp16(bb + swz(row, cc),
                     Ah + (size_t)(m0 + row) * 512 + k0 + cc * 8);
            } else {
                cp16(bb + 8192 + swz(row, cc),
                     Bh + (size_t)(n0 + row) * 512 + k0 + cc * 8);
            }
        }
    };

    load_chunk(0, 0);
    cp_commit();

    const int a_r = lane & 15;
    const int a_h = lane >> 4;
    const int b_r = (lane & 7) + ((lane >> 4) << 3);
    const int b_h = (lane >> 3) & 1;

    for (int c = 0; c < 16; ++c) {
        const int buf = c & 1;
        cp_wait0();
        __syncthreads();
        if (c < 15) { load_chunk(c + 1, buf ^ 1); cp_commit(); }

        const uint32_t bb = sbase + buf * VBUF2;
#pragma unroll
        for (int s = 0; s < 2; ++s) {
            uint32_t a[2][4];
#pragma unroll
            for (int mt = 0; mt < 2; ++mt) {
                int r = wm * 32 + mt * 16 + a_r;
                ldm4(a[mt], bb + swz(r, s * 2 + a_h));
            }
#pragma unroll
            for (int g = 0; g < 4; ++g) {
                uint32_t bH[4];
                int r = wn * 64 + g * 16 + b_r;
                ldm4(bH, bb + 8192 + swz(r, s * 2 + b_h));
#pragma unroll
                for (int mt = 0; mt < 2; ++mt) {
                    mma16816(acc[mt][g * 2],     a[mt], bH[0], bH[1]);
                    mma16816(acc[mt][g * 2 + 1], a[mt], bH[2], bH[3]);
                }
            }
        }
    }

    // c2 for this thread's 16 columns
    float c2v[16];
#pragma unroll
    for (int j = 0; j < 8; ++j)
#pragma unroll
        for (int cb = 0; cb < 2; ++cb)
            c2v[j * 2 + cb] =
                __ldg(&c2[n0 + wn * 64 + j * 8 + (lane & 3) * 2 + cb]);

    // per-(row, 8-code subgroup) min keys + candidate masks
#pragma unroll
    for (int mt = 0; mt < 2; ++mt)
#pragma unroll
        for (int h = 0; h < 2; ++h) {
            int row = wm * 32 + mt * 16 + (lane >> 2) + h * 8;
            float tv = __ldg(&thr[m0 + row]);
#pragma unroll
            for (int j = 0; j < 8; ++j) {
                float d0 = c2v[j * 2]     - 2.0f * acc[mt][j][h * 2];
                float d1 = c2v[j * 2 + 1] - 2.0f * acc[mt][j][h * 2 + 1];
                int nc = n0 + wn * 64 + j * 8 + (lane & 3) * 2;
                u64 k0 = dist_key(d0, nc);
                u64 k1 = dist_key(d1, nc + 1);
                u64 best = k0 < k1 ? k0 : k1;
                u64 o1 = __shfl_xor_sync(0xffffffffu, best, 1);
                if (o1 < best) best = o1;
                u64 o2 = __shfl_xor_sync(0xffffffffu, best, 2);
                if (o2 < best) best = o2;
                // within-group candidate mask (superset of global candidates)
                float Tg = key_to_dist(best) + tv;
                unsigned int lm = 0;
                if (d0 <= Tg) lm |= 1u << ((lane & 3) * 2);
                if (d1 <= Tg) lm |= 1u << ((lane & 3) * 2 + 1);
                lm |= __shfl_xor_sync(0xffffffffu, lm, 1);
                lm |= __shfl_xor_sync(0xffffffffu, lm, 2);
                if ((lane & 3) == 0)
                    sG[row][wn * 8 + j] = best | ((u64)lm << 13);
            }
        }
    __syncthreads();

    // coalesced write: per row 16 contiguous u64
    for (int i = tid; i < 2048; i += 256) {
        int row = i >> 4, j = i & 15;
        gkey[(size_t)(m0 + row) * NGRP + blockIdx.y * 16 + j] = sG[row][j];
    }
}

// ---------------------------------------------------------------------------
// flag: per (row, cb) min over 256 subgroup keys, threshold, emit items
// item = m(14b) << 18 | group(10b) << 8 | mask(8b)
// ---------------------------------------------------------------------------
__global__ void flag_kernel(const u64* __restrict__ gkey,
                            const float* __restrict__ thr,
                            uint32_t* __restrict__ misc,
                            uint32_t* __restrict__ items) {
    int m = blockIdx.x * 8 + (threadIdx.x >> 5);
    int lane = threadIdx.x & 31;
    if (m >= MTOT) return;

    float tv = __ldg(&thr[m]);

    unsigned int fmask = 0;
    unsigned int gmask[4];
#pragma unroll
    for (int cb = 0; cb < 4; ++cb) {
        u64 kq[8];
        u64 mn = ~0ull;
#pragma unroll
        for (int q = 0; q < 8; ++q) {
            u64 k = gkey[(size_t)m * NGRP + cb * 256 + q * 32 + lane];
            kq[q] = k;
            if (k < mn) mn = k;
        }
#pragma unroll
        for (int o = 16; o > 0; o >>= 1) {
            u64 v = __shfl_xor_sync(0xffffffffu, mn, o);
            if (v < mn) mn = v;
        }
        float T = key_to_dist(mn) + tv;
        unsigned int encT = enc_bits(T);
        gmask[cb] = 0;
#pragma unroll
        for (int q = 0; q < 8; ++q)
            if ((unsigned int)(kq[q] >> 32) <= encT) {
                fmask |= 1u << (cb * 8 + q);
                gmask[cb] |= ((unsigned int)(kq[q] >> 13) & 0xffu) << (q * 4 % 32);
            }
        // store per-q masks compactly: re-extract at emit time instead
        (void)gmask;
        // keep kq for emit
#pragma unroll
        for (int q = 0; q < 8; ++q)
            if (fmask & (1u << (cb * 8 + q))) {
                // nothing here; emit below re-reads mask from kq
            }
        // stash kq masks into registers for emit
        if (cb == 0) { }
        // (emit loop below re-derives mask from gkey re-load to keep regs low)
    }

    int cnt = __popc(fmask);
    int incl = cnt;
#pragma unroll
    for (int o = 1; o < 32; o <<= 1) {
        int v = __shfl_up_sync(0xffffffffu, incl, o);
        if (lane >= o) incl += v;
    }
    int total = __shfl_sync(0xffffffffu, incl, 31);
    unsigned int base = 0;
    if (lane == 31 && total > 0) base = atomicAdd(&misc[0], (unsigned int)total);
    base = __shfl_sync(0xffffffffu, base, 31);
    int off = (int)base + incl - cnt;
    unsigned int mm = fmask;
    while (mm) {
        int bpos = __ffs(mm) - 1;
        mm &= mm - 1;
        int cb = bpos >> 3, q = bpos & 7;
        int g = cb * 256 + q * 32 + lane;
        u64 k = gkey[(size_t)m * NGRP + g];          // L2-hot re-read
        unsigned int cmask = (unsigned int)(k >> 13) & 0xffu;
        items[off++] = ((unsigned int)m << 18) | ((unsigned int)g << 8) | cmask;
    }
}

// ---------------------------------------------------------------------------
// refine: exact fp32 distances for masked codes of each flagged subgroup
// ---------------------------------------------------------------------------
__global__ void refine_kernel(const __nv_bfloat16* __restrict__ Ah,
                              const __nv_bfloat16* __restrict__ Al,
                              const __nv_bfloat16* __restrict__ Bh,
                              const __nv_bfloat16* __restrict__ Bl,
                              const float* __restrict__ c2,
                              const uint32_t* __restrict__ misc,
                              const uint32_t* __restrict__ items,
                              u64* __restrict__ res) {
    const int lane = threadIdx.x & 31;
    const int wgid = blockIdx.x * 8 + (threadIdx.x >> 5);
    const int nw = gridDim.x * 8;
    const int cnt = (int)misc[0];

    for (int it = wgid; it < cnt; it += nw) {
        unsigned int item = items[it];
        int m = item >> 18;
        int g = (item >> 8) & 1023;
        unsigned int cmask = item & 0xffu;
        int cb = g >> 8;
        int n0 = g * 8;

        float f[16], t0[8], t1[8];
        {
            const uint4* ph = (const uint4*)(Ah + (size_t)m * 512 + lane * 16);
            const uint4* pl = (const uint4*)(Al + (size_t)m * 512 + lane * 16);
            uint4 h0 = ph[0], h1 = ph[1], l0v = pl[0], l1v = pl[1];
            bf8(h0, f); bf8(h1, f + 8);
            bf8(l0v, t0); bf8(l1v, t1);
#pragma unroll
            for (int e = 0; e < 8; ++e)  f[e] += t0[e];
#pragma unroll
            for (int e = 0; e < 8; ++e)  f[e + 8] += t1[e];
        }

        u64 best = ~0ull;
        unsigned int mm = cmask;
        while (mm) {
            int c = __ffs(mm) - 1;
            mm &= mm - 1;
            int n = n0 + c;
            const uint4* pb = (const uint4*)(Bh + (size_t)n * 512 + lane * 16);
            const uint4* pq = (const uint4*)(Bl + (size_t)n * 512 + lane * 16);
            uint4 b0 = pb[0], b1 = pb[1], q0 = pq[0], q1 = pq[1];
            float g0[8], g1[8], r0[8], r1[8];
            bf8(b0, g0); bf8(b1, g1); bf8(q0, r0); bf8(q1, r1);
            float dot = 0.0f;
#pragma unroll
            for (int e = 0; e < 8; ++e) dot = fmaf(f[e], g0[e] + r0[e], dot);
#pragma unroll
            for (int e = 0; e < 8; ++e) dot = fmaf(f[e + 8], g1[e] + r1[e], dot);
#pragma unroll
            for (int o = 16; o > 0; o >>= 1)
                dot += __shfl_down_sync(0xffffffffu, dot, o);
            if (lane == 0) {
                float d = __ldg(&c2[n]) - 2.0f * dot;
                u64 k = dist_key(d, n);
                if (k < best) best = k;
            }
        }
        if (lane == 0 && best != ~0ull) atomicMin(&res[m * 4 + cb], best);
    }
}

// ---------------------------------------------------------------------------
// Finalize: tokens from g_res + embedding mean
// ---------------------------------------------------------------------------
__global__ void finalize_kernel(const u64* __restrict__ res,
                                const float* __restrict__ emb_table,
                                float* __restrict__ out) {
    __shared__ int tok[KCB];
    const int m = blockIdx.x;
    const int b = m >> 12, l = m & 4095;
    const int tid = threadIdx.x;

    if (tid < KCB) {
        int t = ((int)(res[m * 4 + tid] & 0xffffffffu)) & (VOCAB - 1);
        tok[tid] = t;
        out[((size_t)b * KCB + tid) * L3O + l] = (float)t;
    }
    __syncthreads();

    float* out_emb = out + (size_t)NB * KCB * L3O;
    int t0 = tok[0], t1 = tok[1], t2 = tok[2], t3 = tok[3];
    for (int h = tid; h < 512; h += 128) {
        float s = emb_table[(size_t)t0 * 512 + h] + emb_table[(size_t)t1 * 512 + h]
                + emb_table[(size_t)t2 * 512 + h] + emb_table[(size_t)t3 * 512 + h];
        out_emb[((size_t)b * L3O + l) * 512 + h] = 0.25f * s;
    }
}

// ---------------------------------------------------------------------------
extern "C" void kernel_launch(void* const* d_in, const int* in_sizes, int n_in,
                              void* d_out, int out_size) {
    const float* audio = (const float*)d_in[0];
    const float* w1    = (const float*)d_in[1];
    const float* b1    = (const float*)d_in[2];
    const float* w2    = (const float*)d_in[3];
    const float* b2    = (const float*)d_in[4];
    const float* w3    = (const float*)d_in[5];
    const float* b3    = (const float*)d_in[6];
    const float* cb    = (const float*)d_in[7];
    const float* emb   = (const float*)d_in[8];
    float* out = (float*)d_out;

    __nv_bfloat16 *x1h, *x1l, *x2h, *x2l, *w2h, *w2l, *w3h, *w3l;
    __nv_bfloat16 *ah, *al, *bh, *bl;
    float *c2p, *thrp;
    u64 *gkeyp, *resp;
    uint32_t *miscp, *itemsp;
    cudaGetSymbolAddress((void**)&x1h, g_X1h);
    cudaGetSymbolAddress((void**)&x1l, g_X1l);
    cudaGetSymbolAddress((void**)&x2h, g_X2h);
    cudaGetSymbolAddress((void**)&x2l, g_X2l);
    cudaGetSymbolAddress((void**)&w2h, g_W2h);
    cudaGetSymbolAddress((void**)&w2l, g_W2l);
    cudaGetSymbolAddress((void**)&w3h, g_W3h);
    cudaGetSymbolAddress((void**)&w3l, g_W3l);
    cudaGetSymbolAddress((void**)&ah,  g_Ah);
    cudaGetSymbolAddress((void**)&al,  g_Al);
    cudaGetSymbolAddress((void**)&bh,  g_Bh);
    cudaGetSymbolAddress((void**)&bl,  g_Bl);
    cudaGetSymbolAddress((void**)&c2p, g_c2);
    cudaGetSymbolAddress((void**)&thrp, g_thr);
    cudaGetSymbolAddress((void**)&gkeyp, g_gkey);
    cudaGetSymbolAddress((void**)&itemsp, g_items);
    cudaGetSymbolAddress((void**)&miscp, g_misc);
    cudaGetSymbolAddress((void**)&resp, g_res);

    // prep (res init + guards + misc), weights, fused codebook split+norms
    prep_kernel<<<(MTOT * KCB + 255) / 256, 256>>>(
        resp, miscp, (uint32_t*)x1h, (uint32_t*)x1l, (uint32_t*)x2h, (uint32_t*)x2l);
    split_W<<<(C2C * C1 * 7 + 255) / 256, 256>>>(w2, w2h, w2l, C2C, C1);
    split_W<<<(C3 * C2C * 7 + 255) / 256, 256>>>(w3, w3h, w3l, C3, C2C);
    splitb_kernel<<<NCODES / 8, 256>>>(cb, bh, bl, c2p, miscp);

    // conv chain (all tensor-core)
    conv1_kernel<<<dim3(L1O / 2, 1, NB), 256>>>(audio, w1, b1, x1h, x1l);

    cudaFuncSetAttribute(conv_mma<C1>, cudaFuncAttributeMaxDynamicSharedMemorySize,
                         2 * CBUF);
    conv_mma<C1><<<dim3(L2O / 128, C2C / 128, NB), 256, 2 * CBUF>>>(
        x1h, x1l, w2h, w2l, b2, x2h, x2l, L1O, L2O, C2C, 1, 8, 4);

    cudaFuncSetAttribute(conv_mma<C2C>, cudaFuncAttributeMaxDynamicSharedMemorySize,
                         2 * CBUF);
    conv_mma<C2C><<<dim3(L3O / 128, C3 / 128, NB), 256, 2 * CBUF>>>(
        x2h, x2l, w3h, w3l, b3, ah, al, L2O, L3O, C3, 0, 0, 0);

    // per-row thresholds (needs conv3 output + codebook norms)
    thr_kernel<<<MTOT / 8, 256>>>(ah, al, miscp, thrp);

    // approx vq (hh only) -> 8-code subgroup keys + candidate masks
    cudaFuncSetAttribute(vq_approx, cudaFuncAttributeMaxDynamicSharedMemorySize,
                         2 * VBUF2);
    vq_approx<<<dim3(MTOT / 128, NCODES / 128), 256, 2 * VBUF2>>>(
        ah, bh, c2p, thrp, gkeyp);

    // flag candidate subgroups, then exact refine of masked codes
    flag_kernel<<<MTOT / 8, 256>>>(gkeyp, thrp, miscp, itemsp);
    refine_kernel<<<1024, 256>>>(ah, al, bh, bl, c2p, miscp, itemsp, resp);

    finalize_kernel<<<MTOT, 128>>>(resp, emb, out);
}

// round 13
// speedup vs baseline: 1.5400x; 1.0974x over previous
#include <cuda_runtime.h>
#include <cuda_bf16.h>
#include <cstdint>

// Problem constants
#define NB 4
#define SLEN 32768
#define C1 128
#define C2C 256
#define C3 512
#define L1O 16384
#define L2O 8192
#define L3O 4096
#define VOCAB 2048
#define KCB 4
#define NCODES (KCB * VOCAB)   // 8192
#define MTOT (NB * L3O)        // 16384
#define NGRP 1024              // 8-code subgroups per row (8192/8)

typedef unsigned long long u64;

// bf16 split activations, transposed: X [b][pos][CI], 4 guard rows each side.
__device__ ulonglong2 g_X1h[NB * (L1O + 8) * C1 / 8];
__device__ ulonglong2 g_X1l[NB * (L1O + 8) * C1 / 8];
__device__ ulonglong2 g_X2h[NB * (L2O + 8) * C2C / 8];
__device__ ulonglong2 g_X2l[NB * (L2O + 8) * C2C / 8];
// split weights [7][CO][CI]
__device__ ulonglong2 g_W2h[7 * C2C * C1 / 8];
__device__ ulonglong2 g_W2l[7 * C2C * C1 / 8];
__device__ ulonglong2 g_W3h[7 * C3 * C2C / 8];
__device__ ulonglong2 g_W3l[7 * C3 * C2C / 8];
// vq operands
__device__ ulonglong2 g_Ah[MTOT * 512 / 8];      // feats hi  [m][k] (conv3 output)
__device__ ulonglong2 g_Al[MTOT * 512 / 8];
__device__ ulonglong2 g_Bh[NCODES * 512 / 8];    // codes hi  [n][k]
__device__ ulonglong2 g_Bl[NCODES * 512 / 8];
__device__ float  g_c2[NCODES];
__device__ float  g_thr[MTOT];                   // per-row threshold 2*eb + 0.25
__device__ uint32_t g_gkey32[(size_t)MTOT * NGRP]; // per group: encdist24|mask8
__device__ uint32_t g_items[(size_t)MTOT * NGRP];  // work list (worst case)
__device__ uint32_t g_misc[4];                   // [0]=count [1]=maxBh2 [2]=maxBl2
__device__ u64    g_res[MTOT * KCB];             // final per (row, cb) key

// ---------------------------------------------------------------------------
// helpers
// ---------------------------------------------------------------------------
__device__ __forceinline__ void cp16(uint32_t dst, const void* src) {
    asm volatile("cp.async.cg.shared.global [%0], [%1], 16;" :: "r"(dst), "l"(src));
}
__device__ __forceinline__ void cp_commit() { asm volatile("cp.async.commit_group;"); }
__device__ __forceinline__ void cp_wait0()  { asm volatile("cp.async.wait_group 0;"); }

__device__ __forceinline__ uint32_t smem_u32(const void* p) {
    return (uint32_t)__cvta_generic_to_shared(p);
}

__device__ __forceinline__ u64 dist_key(float v, int n) {
    unsigned int fb = __float_as_uint(v);
    fb = (fb & 0x80000000u) ? ~fb : (fb | 0x80000000u);
    return ((u64)fb << 32) | (unsigned int)n;
}
__device__ __forceinline__ float dec_bits(unsigned int x) {
    unsigned int vb = (x & 0x80000000u) ? (x & 0x7fffffffu) : ~x;
    return __uint_as_float(vb);
}
__device__ __forceinline__ unsigned int enc_bits(float v) {
    unsigned int tb = __float_as_uint(v);
    return (tb & 0x80000000u) ? ~tb : (tb | 0x80000000u);
}

__device__ __forceinline__ void ldm4(uint32_t* r, uint32_t addr) {
    asm volatile("ldmatrix.sync.aligned.m8n8.x4.shared.b16 {%0,%1,%2,%3}, [%4];"
                 : "=r"(r[0]), "=r"(r[1]), "=r"(r[2]), "=r"(r[3]) : "r"(addr));
}
__device__ __forceinline__ void mma16816(float* c, const uint32_t* a,
                                         uint32_t b0, uint32_t b1) {
    asm volatile(
        "mma.sync.aligned.m16n8k16.row.col.f32.bf16.bf16.f32 "
        "{%0,%1,%2,%3}, {%4,%5,%6,%7}, {%8,%9}, {%0,%1,%2,%3};"
        : "+f"(c[0]), "+f"(c[1]), "+f"(c[2]), "+f"(c[3])
        : "r"(a[0]), "r"(a[1]), "r"(a[2]), "r"(a[3]), "r"(b0), "r"(b1));
}

// smem swizzle (rows of 64 B = 4 x 16B chunks)
__device__ __forceinline__ int swz(int row, int c) {
    return row * 64 + ((c ^ ((row & 3) ^ ((row >> 2) & 1))) << 4);
}
// conv smem swizzle for 32 B rows (2 chunks)
__device__ __forceinline__ int s3(int row) {
    return (row ^ (row >> 1) ^ (row >> 2)) & 1;
}
// unpack 8 bf16 (uint4) -> 8 floats (exact: bf16 = fp32 top bits)
__device__ __forceinline__ void bf8(const uint4 v, float* o) {
    o[0] = __uint_as_float(v.x << 16); o[1] = __uint_as_float(v.x & 0xffff0000u);
    o[2] = __uint_as_float(v.y << 16); o[3] = __uint_as_float(v.y & 0xffff0000u);
    o[4] = __uint_as_float(v.z << 16); o[5] = __uint_as_float(v.z & 0xffff0000u);
    o[6] = __uint_as_float(v.w << 16); o[7] = __uint_as_float(v.w & 0xffff0000u);
}

// ---------------------------------------------------------------------------
// prep: res init + guard zeroing + misc counters
// ---------------------------------------------------------------------------
__global__ void prep_kernel(u64* res, uint32_t* misc,
                            uint32_t* x1h, uint32_t* x1l,
                            uint32_t* x2h, uint32_t* x2l) {
    int i = blockIdx.x * 256 + threadIdx.x;
    if (i < MTOT * KCB) res[i] = ~0ull;
    if (i < 4) misc[i] = 0u;
    if (i < 4096) {
        int half = i >> 11, j = i & 2047;
        int b = j >> 9, r = (j >> 6) & 7, w = j & 63;
        int row = (r < 4) ? r : (L1O + r);
        uint32_t* p = half ? x1l : x1h;
        p[(size_t)(b * (L1O + 8) + row) * 64 + w] = 0u;
    } else if (i < 4096 + 8192) {
        int j = i - 4096;
        int half = j >> 12; j &= 4095;
        int b = j >> 10, r = (j >> 7) & 7, w = j & 127;
        int row = (r < 4) ? r : (L2O + r);
        uint32_t* p = half ? x2l : x2h;
        p[(size_t)(b * (L2O + 8) + row) * 128 + w] = 0u;
    }
}

// ---------------------------------------------------------------------------
// split weights: w [CO][CI][7] fp32 -> Wh/Wl [7][CO][CI] bf16
// ---------------------------------------------------------------------------
__global__ void split_W(const float* __restrict__ w,
                        __nv_bfloat16* __restrict__ wh,
                        __nv_bfloat16* __restrict__ wl, int CO, int CI) {
    int i = blockIdx.x * 256 + threadIdx.x;
    if (i >= CO * CI * 7) return;
    int co = i / (CI * 7);
    int r  = i % (CI * 7);
    int ci = r / 7, t = r % 7;
    float v = w[i];
    __nv_bfloat16 h = __float2bfloat16(v);
    wh[((size_t)t * CO + co) * CI + ci] = h;
    wl[((size_t)t * CO + co) * CI + ci] = __float2bfloat16(v - __bfloat162float(h));
}

// ---------------------------------------------------------------------------
// conv1: [B,1,32768] -> relu -> X1 [b][pos][128] bf16 hi/lo (offset 4 rows)
// ---------------------------------------------------------------------------
__global__ void conv1_kernel(const float* __restrict__ x,
                             const float* __restrict__ w,
                             const float* __restrict__ bias,
                             __nv_bfloat16* __restrict__ yh,
                             __nv_bfloat16* __restrict__ yl) {
    int tid = threadIdx.x;
    int co = tid & 127;
    int l  = blockIdx.x * 2 + (tid >> 7);
    int b  = blockIdx.z;
    const float* xb = x + b * SLEN;
    float acc = bias[co];
#pragma unroll
    for (int t = 0; t < 7; ++t) {
        int g = 2 * l + t - 3;
        float xv = (g >= 0 && g < SLEN) ? xb[g] : 0.0f;
        acc = fmaf(w[co * 7 + t], xv, acc);
    }
    acc = fmaxf(acc, 0.0f);
    __nv_bfloat16 h = __float2bfloat16(acc);
    size_t o = (size_t)(b * (L1O + 8) + l + 4) * C1 + co;
    yh[o] = h;
    yl[o] = __float2bfloat16(acc - __bfloat162float(h));
}

// ---------------------------------------------------------------------------
// conv via mma.sync bf16 split (hh + hl + lh).
// R12: SINGLE buffer, 2 CTAs/SM (cross-CTA overlap replaces double buffering).
// ---------------------------------------------------------------------------
#define SLAB_PAR  4352
#define SLAB_HALF 8704
#define SLAB_SZ   17408
#define W_HALF    28672
#define CBUF      74752

template <int CI>
__global__ __launch_bounds__(256, 2) void conv_mma(
        const __nv_bfloat16* __restrict__ Xh, const __nv_bfloat16* __restrict__ Xl,
        const __nv_bfloat16* __restrict__ Wh, const __nv_bfloat16* __restrict__ Wl,
        const float* __restrict__ bias,
        __nv_bfloat16* __restrict__ Yh, __nv_bfloat16* __restrict__ Yl,
        int L_in, int L_out, int CO, int do_relu, int y_pad, int y_off) {
    extern __shared__ __align__(16) char dsm[];
    const uint32_t bb = smem_u32(dsm);

    const int tid  = threadIdx.x;
    const int lane = tid & 31;
    const int wid  = tid >> 5;
    const int wm   = wid >> 1;
    const int wn   = wid & 1;
    const int l0  = blockIdx.x * 128;
    const int co0 = blockIdx.y * 128;
    const int b   = blockIdx.z;

    float acc[2][8][4];
#pragma unroll
    for (int i = 0; i < 2; ++i)
#pragma unroll
        for (int j = 0; j < 8; ++j)
#pragma unroll
            for (int q = 0; q < 4; ++q) acc[i][j][q] = 0.0f;

    auto load_chunk = [&](int ch) {
        const int ci0 = ch * 16;
        for (int i = tid; i < 262 * 4; i += 256) {
            int rel = i >> 2;
            int half = (i >> 1) & 1, ck = i & 1;
            int e = rel >> 1, par = rel & 1;
            const __nv_bfloat16* src = (half ? Xl : Xh) +
                (size_t)(b * (L_in + 8) + 2 * l0 + rel) * CI + ci0 + ck * 8;
            cp16(bb + half * SLAB_HALF + par * SLAB_PAR + e * 32 +
                 ((ck ^ s3(e)) << 4), src);
        }
#pragma unroll
        for (int r = 0; r < 14; ++r) {
            int i = tid + r * 256;
            int row = i >> 2;
            int half = (i >> 1) & 1, ck = i & 1;
            int t = row >> 7, col = row & 127;
            const __nv_bfloat16* src = (half ? Wl : Wh) +
                (size_t)(t * CO + co0 + col) * CI + ci0 + ck * 8;
            cp16(bb + SLAB_SZ + half * W_HALF + row * 32 +
                 ((ck ^ s3(row)) << 4), src);
        }
    };

    const int a_r = lane & 15;
    const int a_h = lane >> 4;
    const int b_r = (lane & 7) + ((lane >> 4) << 3);
    const int b_h = (lane >> 3) & 1;

    const int NCH = CI / 16;
    for (int ch = 0; ch < NCH; ++ch) {
        load_chunk(ch);
        cp_commit();
        cp_wait0();
        __syncthreads();                       // loads visible to all
#pragma unroll
        for (int t = 0; t < 7; ++t) {
            const int par = (t + 1) & 1;
            const int shift = (t + 1) >> 1;
            uint32_t aH[2][4], aL[2][4];
#pragma unroll
            for (int mt = 0; mt < 2; ++mt) {
                int e = wm * 32 + mt * 16 + a_r + shift;
                uint32_t sa = bb + par * SLAB_PAR + e * 32 + ((a_h ^ s3(e)) << 4);
                ldm4(aH[mt], sa);
                ldm4(aL[mt], sa + SLAB_HALF);
            }
#pragma unroll
            for (int g = 0; g < 4; ++g) {
                uint32_t bH[4], bL[4];
                int row = t * 128 + wn * 64 + g * 16 + b_r;
                uint32_t sb = bb + SLAB_SZ + row * 32 + ((b_h ^ s3(row)) << 4);
                ldm4(bH, sb);
                ldm4(bL, sb + W_HALF);
#pragma unroll
                for (int mt = 0; mt < 2; ++mt) {
                    mma16816(acc[mt][g * 2],     aH[mt], bH[0], bH[1]);
                    mma16816(acc[mt][g * 2 + 1], aH[mt], bH[2], bH[3]);
                    mma16816(acc[mt][g * 2],     aH[mt], bL[0], bL[1]);
                    mma16816(acc[mt][g * 2 + 1], aH[mt], bL[2], bL[3]);
                    mma16816(acc[mt][g * 2],     aL[mt], bH[0], bH[1]);
                    mma16816(acc[mt][g * 2 + 1], aL[mt], bH[2], bH[3]);
                }
            }
        }
        if (ch + 1 < NCH) __syncthreads();     // WAR: compute done before reload
    }

    const size_t ybase = (size_t)b * (L_out + y_pad) + y_off;
#pragma unroll
    for (int mt = 0; mt < 2; ++mt)
#pragma unroll
        for (int j = 0; j < 8; ++j)
#pragma unroll
            for (int h8 = 0; h8 < 2; ++h8) {
                int l = l0 + wm * 32 + mt * 16 + (lane >> 2) + h8 * 8;
                int co = co0 + wn * 64 + j * 8 + (lane & 3) * 2;
                float v0 = acc[mt][j][h8 * 2]     + __ldg(&bias[co]);
                float v1 = acc[mt][j][h8 * 2 + 1] + __ldg(&bias[co + 1]);
                if (do_relu) { v0 = fmaxf(v0, 0.0f); v1 = fmaxf(v1, 0.0f); }
                __nv_bfloat16 h0 = __float2bfloat16(v0);
                __nv_bfloat16 h1 = __float2bfloat16(v1);
                __nv_bfloat162 hp; hp.x = h0; hp.y = h1;
                __nv_bfloat162 lp;
                lp.x = __float2bfloat16(v0 - __bfloat162float(h0));
                lp.y = __float2bfloat16(v1 - __bfloat162float(h1));
                size_t o = (ybase + l) * CO + co;
                *(__nv_bfloat162*)(Yh + o) = hp;
                *(__nv_bfloat162*)(Yl + o) = lp;
            }
}

// ---------------------------------------------------------------------------
// fused split_B + bnorm: one pass over cb -> Bh/Bl + c2 + max split norms
// ---------------------------------------------------------------------------
__global__ void splitb_kernel(const float* __restrict__ cb,
                              __nv_bfloat16* __restrict__ bh,
                              __nv_bfloat16* __restrict__ bl,
                              float* __restrict__ c2,
                              uint32_t* __restrict__ misc) {
    int code = blockIdx.x * 8 + (threadIdx.x >> 5);
    int lane = threadIdx.x & 31;
    if (code >= NCODES) return;
    const float* row = cb + (size_t)code * 512 + lane * 16;
    float s = 0.0f, h2 = 0.0f, l2 = 0.0f;
    unsigned int hw[8], lw[8];
#pragma unroll
    for (int q = 0; q < 4; ++q) {
        float4 v = *(const float4*)(row + q * 4);
        float vv[4] = {v.x, v.y, v.z, v.w};
#pragma unroll
        for (int e = 0; e < 2; ++e) {
            float a0 = vv[e * 2], a1 = vv[e * 2 + 1];
            __nv_bfloat16 hb0 = __float2bfloat16(a0);
            __nv_bfloat16 hb1 = __float2bfloat16(a1);
            float hf0 = __bfloat162float(hb0), hf1 = __bfloat162float(hb1);
            float lf0 = a0 - hf0, lf1 = a1 - hf1;
            __nv_bfloat16 lb0 = __float2bfloat16(lf0);
            __nv_bfloat16 lb1 = __float2bfloat16(lf1);
            float lq0 = __bfloat162float(lb0), lq1 = __bfloat162float(lb1);
            __nv_bfloat162 hp; hp.x = hb0; hp.y = hb1;
            __nv_bfloat162 lp; lp.x = lb0; lp.y = lb1;
            hw[q * 2 + e] = *(unsigned int*)&hp;
            lw[q * 2 + e] = *(unsigned int*)&lp;
            s  = fmaf(a0, a0, fmaf(a1, a1, s));
            h2 = fmaf(hf0, hf0, fmaf(hf1, hf1, h2));
            l2 = fmaf(lq0, lq0, fmaf(lq1, lq1, l2));
        }
    }
    uint4* dh = (uint4*)(bh + (size_t)code * 512 + lane * 16);
    uint4* dl = (uint4*)(bl + (size_t)code * 512 + lane * 16);
    dh[0] = make_uint4(hw[0], hw[1], hw[2], hw[3]);
    dh[1] = make_uint4(hw[4], hw[5], hw[6], hw[7]);
    dl[0] = make_uint4(lw[0], lw[1], lw[2], lw[3]);
    dl[1] = make_uint4(lw[4], lw[5], lw[6], lw[7]);
#pragma unroll
    for (int o = 16; o > 0; o >>= 1) {
        s  += __shfl_down_sync(0xffffffffu, s, o);
        h2 += __shfl_down_sync(0xffffffffu, h2, o);
        l2 += __shfl_down_sync(0xffffffffu, l2, o);
    }
    if (lane == 0) {
        c2[code] = s;
        atomicMax(&misc[1], __float_as_uint(h2));
        atomicMax(&misc[2], __float_as_uint(l2));
    }
}

// ---------------------------------------------------------------------------
// thr: per feats row, threshold 2*eb + 0.25 from split norms
// ---------------------------------------------------------------------------
__global__ void thr_kernel(const __nv_bfloat16* __restrict__ Ah,
                           const __nv_bfloat16* __restrict__ Al,
                           const uint32_t* __restrict__ misc,
                           float* __restrict__ thr) {
    int row = blockIdx.x * 8 + (threadIdx.x >> 5);
    int lane = threadIdx.x & 31;
    if (row >= MTOT) return;
    const uint4* ph = (const uint4*)(Ah + (size_t)row * 512 + lane * 16);
    const uint4* pl = (const uint4*)(Al + (size_t)row * 512 + lane * 16);
    float fh[16], fl[16];
    bf8(ph[0], fh); bf8(ph[1], fh + 8);
    bf8(pl[0], fl); bf8(pl[1], fl + 8);
    float sh = 0.0f, sl = 0.0f;
#pragma unroll
    for (int e = 0; e < 16; ++e) {
        sh = fmaf(fh[e], fh[e], sh);
        sl = fmaf(fl[e], fl[e], sl);
    }
#pragma unroll
    for (int o = 16; o > 0; o >>= 1) {
        sh += __shfl_down_sync(0xffffffffu, sh, o);
        sl += __shfl_down_sync(0xffffffffu, sl, o);
    }
    if (lane == 0) {
        float maxBh2 = __uint_as_float(misc[1]);
        float maxBl2 = __uint_as_float(misc[2]);
        float eb = 2.0f * (sqrtf(sh * maxBl2) + sqrtf(sl * maxBh2)
                           + sqrtf(sl * maxBl2));
        thr[row] = 2.0f * eb + 0.25f;
    }
}

// ---------------------------------------------------------------------------
// Approx VQ GEMM (hh only) + per-(row, 8-code subgroup) u32 key:
//   [enc(dist) top 24 bits][candidate mask 8]
// ---------------------------------------------------------------------------
#define VBUF2 16384

__global__ __launch_bounds__(256, 2) void vq_approx(
        const __nv_bfloat16* __restrict__ Ah, const __nv_bfloat16* __restrict__ Bh,
        const float* __restrict__ c2, const float* __restrict__ thr,
        uint32_t* __restrict__ gkey) {
    extern __shared__ __align__(16) char dsm[];          // 2 * 16 KB
    __shared__ uint32_t sG[128][16];

    const int tid  = threadIdx.x;
    const int lane = tid & 31;
    const int wid  = tid >> 5;
    const int wm   = wid >> 1;           // 0..3: m block of 32
    const int wn   = wid & 1;            // 0..1: n block of 64
    const int m0 = blockIdx.x * 128;
    const int n0 = blockIdx.y * 128;
    const uint32_t sbase = smem_u32(dsm);

    float acc[2][8][4];
#pragma unroll
    for (int i = 0; i < 2; ++i)
#pragma unroll
        for (int j = 0; j < 8; ++j)
#pragma unroll
            for (int q = 0; q < 4; ++q) acc[i][j][q] = 0.0f;

    auto load_chunk = [&](int c, int buf) {
        const int k0 = c * 32;
        const uint32_t bb = sbase + buf * VBUF2;
#pragma unroll
        for (int r = 0; r < 4; ++r) {
            int i = tid + r * 256;
            int row = (i >> 2) & 127;
            int cc  = i & 3;
            if (i < 512) {
                cp16(bb + swz(row, cc),
                     Ah + (size_t)(m0 + row) * 512 + k0 + cc * 8);
            } else {
                cp16(bb + 8192 + swz(row, cc),
                     Bh + (size_t)(n0 + row) * 512 + k0 + cc * 8);
            }
        }
    };

    load_chunk(0, 0);
    cp_commit();

    const int a_r = lane & 15;
    const int a_h = lane >> 4;
    const int b_r = (lane & 7) + ((lane >> 4) << 3);
    const int b_h = (lane >> 3) & 1;

    for (int c = 0; c < 16; ++c) {
        const int buf = c & 1;
        cp_wait0();
        __syncthreads();
        if (c < 15) { load_chunk(c + 1, buf ^ 1); cp_commit(); }

        const uint32_t bb = sbase + buf * VBUF2;
#pragma unroll
        for (int s = 0; s < 2; ++s) {
            uint32_t a[2][4];
#pragma unroll
            for (int mt = 0; mt < 2; ++mt) {
                int r = wm * 32 + mt * 16 + a_r;
                ldm4(a[mt], bb + swz(r, s * 2 + a_h));
            }
#pragma unroll
            for (int g = 0; g < 4; ++g) {
                uint32_t bH[4];
                int r = wn * 64 + g * 16 + b_r;
                ldm4(bH, bb + 8192 + swz(r, s * 2 + b_h));
#pragma unroll
                for (int mt = 0; mt < 2; ++mt) {
                    mma16816(acc[mt][g * 2],     a[mt], bH[0], bH[1]);
                    mma16816(acc[mt][g * 2 + 1], a[mt], bH[2], bH[3]);
                }
            }
        }
    }

    // c2 for this thread's 16 columns
    float c2v[16];
#pragma unroll
    for (int j = 0; j < 8; ++j)
#pragma unroll
        for (int cb = 0; cb < 2; ++cb)
            c2v[j * 2 + cb] =
                __ldg(&c2[n0 + wn * 64 + j * 8 + (lane & 3) * 2 + cb]);

    // per-(row, 8-code subgroup) min + candidate masks -> u32
#pragma unroll
    for (int mt = 0; mt < 2; ++mt)
#pragma unroll
        for (int h = 0; h < 2; ++h) {
            int row = wm * 32 + mt * 16 + (lane >> 2) + h * 8;
            float tv = __ldg(&thr[m0 + row]);
#pragma unroll
            for (int j = 0; j < 8; ++j) {
                float d0 = c2v[j * 2]     - 2.0f * acc[mt][j][h * 2];
                float d1 = c2v[j * 2 + 1] - 2.0f * acc[mt][j][h * 2 + 1];
                float dmin = fminf(d0, d1);
                float o1 = __uint_as_float(
                    __shfl_xor_sync(0xffffffffu, __float_as_uint(dmin), 1));
                dmin = fminf(dmin, o1);
                float o2 = __uint_as_float(
                    __shfl_xor_sync(0xffffffffu, __float_as_uint(dmin), 2));
                dmin = fminf(dmin, o2);
                // within-group candidate mask (superset of global candidates)
                float Tg = dmin + tv;
                unsigned int lm = 0;
                if (d0 <= Tg) lm |= 1u << ((lane & 3) * 2);
                if (d1 <= Tg) lm |= 1u << ((lane & 3) * 2 + 1);
                lm |= __shfl_xor_sync(0xffffffffu, lm, 1);
                lm |= __shfl_xor_sync(0xffffffffu, lm, 2);
                if ((lane & 3) == 0)
                    sG[row][wn * 8 + j] = (enc_bits(dmin) & 0xffffff00u) | lm;
            }
        }
    __syncthreads();

    // coalesced write: per row 16 contiguous u32
    for (int i = tid; i < 2048; i += 256) {
        int row = i >> 4, j = i & 15;
        gkey[(size_t)(m0 + row) * NGRP + blockIdx.y * 16 + j] = sG[row][j];
    }
}

// ---------------------------------------------------------------------------
// flag: per (row, cb) min over 256 subgroup keys, threshold, emit items
// item = m(14b) << 18 | group(10b) << 8 | mask(8b)
// ---------------------------------------------------------------------------
__global__ void flag_kernel(const uint32_t* __restrict__ gkey,
                            const float* __restrict__ thr,
                            uint32_t* __restrict__ misc,
                            uint32_t* __restrict__ items) {
    int m = blockIdx.x * 8 + (threadIdx.x >> 5);
    int lane = threadIdx.x & 31;
    if (m >= MTOT) return;

    float tv = __ldg(&thr[m]);

#pragma unroll
    for (int cb = 0; cb < 4; ++cb) {
        uint32_t kq[8];
        unsigned int mn = ~0u;
#pragma unroll
        for (int q = 0; q < 8; ++q) {
            uint32_t k = gkey[(size_t)m * NGRP + cb * 256 + q * 32 + lane];
            kq[q] = k;
            unsigned int e = k >> 8;
            if (e < mn) mn = e;
        }
#pragma unroll
        for (int o = 16; o > 0; o >>= 1) {
            unsigned int v = __shfl_xor_sync(0xffffffffu, mn, o);
            if (v < mn) mn = v;
        }
        float M = dec_bits(mn << 8);         // <= true approx min
        unsigned int encT = enc_bits(M + tv) >> 8;
        unsigned int cbmask = 0;
#pragma unroll
        for (int q = 0; q < 8; ++q)
            if ((kq[q] >> 8) <= encT) cbmask |= 1u << q;

        int cnt = __popc(cbmask);
        int incl = cnt;
#pragma unroll
        for (int o = 1; o < 32; o <<= 1) {
            int v = __shfl_up_sync(0xffffffffu, incl, o);
            if (lane >= o) incl += v;
        }
        int total = __shfl_sync(0xffffffffu, incl, 31);
        unsigned int base = 0;
        if (lane == 31 && total > 0)
            base = atomicAdd(&misc[0], (unsigned int)total);
        base = __shfl_sync(0xffffffffu, base, 31);
        int off = (int)base + incl - cnt;
#pragma unroll
        for (int q = 0; q < 8; ++q)
            if (cbmask & (1u << q)) {
                int g = cb * 256 + q * 32 + lane;
                items[off++] = ((unsigned int)m << 18) |
                               ((unsigned int)g << 8) | (kq[q] & 0xffu);
            }
    }
}

// ---------------------------------------------------------------------------
// refine: exact fp32 distances for masked codes of each flagged subgroup
// ---------------------------------------------------------------------------
__global__ void refine_kernel(const __nv_bfloat16* __restrict__ Ah,
                              const __nv_bfloat16* __restrict__ Al,
                              const __nv_bfloat16* __restrict__ Bh,
                              const __nv_bfloat16* __restrict__ Bl,
                              const float* __restrict__ c2,
                              const uint32_t* __restrict__ misc,
                              const uint32_t* __restrict__ items,
                              u64* __restrict__ res) {
    const int lane = threadIdx.x & 31;
    const int wgid = blockIdx.x * 8 + (threadIdx.x >> 5);
    const int nw = gridDim.x * 8;
    const int cnt = (int)misc[0];

    for (int it = wgid; it < cnt; it += nw) {
        unsigned int item = items[it];
        int m = item >> 18;
        int g = (item >> 8) & 1023;
        unsigned int cmask = item & 0xffu;
        int cb = g >> 8;
        int n0 = g * 8;

        float f[16], t0[8], t1[8];
        {
            const uint4* ph = (const uint4*)(Ah + (size_t)m * 512 + lane * 16);
            const uint4* pl = (const uint4*)(Al + (size_t)m * 512 + lane * 16);
            uint4 h0 = ph[0], h1 = ph[1], l0v = pl[0], l1v = pl[1];
            bf8(h0, f); bf8(h1, f + 8);
            bf8(l0v, t0); bf8(l1v, t1);
#pragma unroll
            for (int e = 0; e < 8; ++e)  f[e] += t0[e];
#pragma unroll
            for (int e = 0; e < 8; ++e)  f[e + 8] += t1[e];
        }

        u64 best = ~0ull;
        unsigned int mm = cmask;
        while (mm) {
            int c = __ffs(mm) - 1;
            mm &= mm - 1;
            int n = n0 + c;
            const uint4* pb = (const uint4*)(Bh + (size_t)n * 512 + lane * 16);
            const uint4* pq = (const uint4*)(Bl + (size_t)n * 512 + lane * 16);
            uint4 b0 = pb[0], b1 = pb[1], q0 = pq[0], q1 = pq[1];
            float g0[8], g1[8], r0[8], r1[8];
            bf8(b0, g0); bf8(b1, g1); bf8(q0, r0); bf8(q1, r1);
            float dot = 0.0f;
#pragma unroll
            for (int e = 0; e < 8; ++e) dot = fmaf(f[e], g0[e] + r0[e], dot);
#pragma unroll
            for (int e = 0; e < 8; ++e) dot = fmaf(f[e + 8], g1[e] + r1[e], dot);
#pragma unroll
            for (int o = 16; o > 0; o >>= 1)
                dot += __shfl_down_sync(0xffffffffu, dot, o);
            if (lane == 0) {
                float d = __ldg(&c2[n]) - 2.0f * dot;
                u64 k = dist_key(d, n);
                if (k < best) best = k;
            }
        }
        if (lane == 0 && best != ~0ull) atomicMin(&res[m * 4 + cb], best);
    }
}

// ---------------------------------------------------------------------------
// Finalize: tokens from g_res + embedding mean
// ---------------------------------------------------------------------------
__global__ void finalize_kernel(const u64* __restrict__ res,
                                const float* __restrict__ emb_table,
                                float* __restrict__ out) {
    __shared__ int tok[KCB];
    const int m = blockIdx.x;
    const int b = m >> 12, l = m & 4095;
    const int tid = threadIdx.x;

    if (tid < KCB) {
        int t = ((int)(res[m * 4 + tid] & 0xffffffffu)) & (VOCAB - 1);
        tok[tid] = t;
        out[((size_t)b * KCB + tid) * L3O + l] = (float)t;
    }
    __syncthreads();

    float* out_emb = out + (size_t)NB * KCB * L3O;
    int t0 = tok[0], t1 = tok[1], t2 = tok[2], t3 = tok[3];
    for (int h = tid; h < 512; h += 128) {
        float s = emb_table[(size_t)t0 * 512 + h] + emb_table[(size_t)t1 * 512 + h]
                + emb_table[(size_t)t2 * 512 + h] + emb_table[(size_t)t3 * 512 + h];
        out_emb[((size_t)b * L3O + l) * 512 + h] = 0.25f * s;
    }
}

// ---------------------------------------------------------------------------
extern "C" void kernel_launch(void* const* d_in, const int* in_sizes, int n_in,
                              void* d_out, int out_size) {
    const float* audio = (const float*)d_in[0];
    const float* w1    = (const float*)d_in[1];
    const float* b1    = (const float*)d_in[2];
    const float* w2    = (const float*)d_in[3];
    const float* b2    = (const float*)d_in[4];
    const float* w3    = (const float*)d_in[5];
    const float* b3    = (const float*)d_in[6];
    const float* cb    = (const float*)d_in[7];
    const float* emb   = (const float*)d_in[8];
    float* out = (float*)d_out;

    __nv_bfloat16 *x1h, *x1l, *x2h, *x2l, *w2h, *w2l, *w3h, *w3l;
    __nv_bfloat16 *ah, *al, *bh, *bl;
    float *c2p, *thrp;
    u64 *resp;
    uint32_t *gkeyp, *miscp, *itemsp;
    cudaGetSymbolAddress((void**)&x1h, g_X1h);
    cudaGetSymbolAddress((void**)&x1l, g_X1l);
    cudaGetSymbolAddress((void**)&x2h, g_X2h);
    cudaGetSymbolAddress((void**)&x2l, g_X2l);
    cudaGetSymbolAddress((void**)&w2h, g_W2h);
    cudaGetSymbolAddress((void**)&w2l, g_W2l);
    cudaGetSymbolAddress((void**)&w3h, g_W3h);
    cudaGetSymbolAddress((void**)&w3l, g_W3l);
    cudaGetSymbolAddress((void**)&ah,  g_Ah);
    cudaGetSymbolAddress((void**)&al,  g_Al);
    cudaGetSymbolAddress((void**)&bh,  g_Bh);
    cudaGetSymbolAddress((void**)&bl,  g_Bl);
    cudaGetSymbolAddress((void**)&c2p, g_c2);
    cudaGetSymbolAddress((void**)&thrp, g_thr);
    cudaGetSymbolAddress((void**)&gkeyp, g_gkey32);
    cudaGetSymbolAddress((void**)&itemsp, g_items);
    cudaGetSymbolAddress((void**)&miscp, g_misc);
    cudaGetSymbolAddress((void**)&resp, g_res);

    // prep (res init + guards + misc), weights, fused codebook split+norms
    prep_kernel<<<(MTOT * KCB + 255) / 256, 256>>>(
        resp, miscp, (uint32_t*)x1h, (uint32_t*)x1l, (uint32_t*)x2h, (uint32_t*)x2l);
    split_W<<<(C2C * C1 * 7 + 255) / 256, 256>>>(w2, w2h, w2l, C2C, C1);
    split_W<<<(C3 * C2C * 7 + 255) / 256, 256>>>(w3, w3h, w3l, C3, C2C);
    splitb_kernel<<<NCODES / 8, 256>>>(cb, bh, bl, c2p, miscp);

    // conv chain (all tensor-core; single-buffer, 2 CTAs/SM)
    conv1_kernel<<<dim3(L1O / 2, 1, NB), 256>>>(audio, w1, b1, x1h, x1l);

    cudaFuncSetAttribute(conv_mma<C1>, cudaFuncAttributeMaxDynamicSharedMemorySize,
                         CBUF);
    conv_mma<C1><<<dim3(L2O / 128, C2C / 128, NB), 256, CBUF>>>(
        x1h, x1l, w2h, w2l, b2, x2h, x2l, L1O, L2O, C2C, 1, 8, 4);

    cudaFuncSetAttribute(conv_mma<C2C>, cudaFuncAttributeMaxDynamicSharedMemorySize,
                         CBUF);
    conv_mma<C2C><<<dim3(L3O / 128, C3 / 128, NB), 256, CBUF>>>(
        x2h, x2l, w3h, w3l, b3, ah, al, L2O, L3O, C3, 0, 0, 0);

    // per-row thresholds (needs conv3 output + codebook norms)
    thr_kernel<<<MTOT / 8, 256>>>(ah, al, miscp, thrp);

    // approx vq (hh only) -> compressed 8-code subgroup keys + masks
    cudaFuncSetAttribute(vq_approx, cudaFuncAttributeMaxDynamicSharedMemorySize,
                         2 * VBUF2);
    vq_approx<<<dim3(MTOT / 128, NCODES / 128), 256, 2 * VBUF2>>>(
        ah, bh, c2p, thrp, gkeyp);

    // flag candidate subgroups, then exact refine of masked codes
    flag_kernel<<<MTOT / 8, 256>>>(gkeyp, thrp, miscp, itemsp);
    refine_kernel<<<1024, 256>>>(ah, al, bh, bl, c2p, miscp, itemsp, resp);

    finalize_kernel<<<MTOT, 128>>>(resp, emb, out);
}

// round 14
// speedup vs baseline: 1.5438x; 1.0024x over previous
#include <cuda_runtime.h>
#include <cuda_bf16.h>
#include <cstdint>

// Problem constants
#define NB 4
#define SLEN 32768
#define C1 128
#define C2C 256
#define C3 512
#define L1O 16384
#define L2O 8192
#define L3O 4096
#define VOCAB 2048
#define KCB 4
#define NCODES (KCB * VOCAB)   // 8192
#define MTOT (NB * L3O)        // 16384
#define NGRP 1024              // 8-code subgroups per row (8192/8)

typedef unsigned long long u64;

// bf16 split activations, transposed: X [b][pos][CI], 4 guard rows each side.
__device__ ulonglong2 g_X1h[NB * (L1O + 8) * C1 / 8];
__device__ ulonglong2 g_X1l[NB * (L1O + 8) * C1 / 8];
__device__ ulonglong2 g_X2h[NB * (L2O + 8) * C2C / 8];
__device__ ulonglong2 g_X2l[NB * (L2O + 8) * C2C / 8];
// split weights [7][CO][CI]
__device__ ulonglong2 g_W2h[7 * C2C * C1 / 8];
__device__ ulonglong2 g_W2l[7 * C2C * C1 / 8];
__device__ ulonglong2 g_W3h[7 * C3 * C2C / 8];
__device__ ulonglong2 g_W3l[7 * C3 * C2C / 8];
// vq operands
__device__ ulonglong2 g_Ah[MTOT * 512 / 8];      // feats hi  [m][k] (conv3 output)
__device__ ulonglong2 g_Al[MTOT * 512 / 8];
__device__ ulonglong2 g_Bh[NCODES * 512 / 8];    // codes hi  [n][k]
__device__ ulonglong2 g_Bl[NCODES * 512 / 8];
__device__ float  g_c2[NCODES];
__device__ float  g_thr[MTOT];                   // per-row threshold 2*eb + 0.25
__device__ uint32_t g_gkey32[(size_t)MTOT * NGRP]; // per group: encdist24|mask8
__device__ uint32_t g_items[(size_t)MTOT * NGRP];  // work list (worst case)
__device__ uint32_t g_misc[4];                   // [0]=count [1]=maxBh2 [2]=maxBl2
__device__ u64    g_res[MTOT * KCB];             // final per (row, cb) key

// ---------------------------------------------------------------------------
// helpers
// ---------------------------------------------------------------------------
__device__ __forceinline__ void cp16(uint32_t dst, const void* src) {
    asm volatile("cp.async.cg.shared.global [%0], [%1], 16;" :: "r"(dst), "l"(src));
}
__device__ __forceinline__ void cp_commit() { asm volatile("cp.async.commit_group;"); }
__device__ __forceinline__ void cp_wait0()  { asm volatile("cp.async.wait_group 0;"); }

__device__ __forceinline__ uint32_t smem_u32(const void* p) {
    return (uint32_t)__cvta_generic_to_shared(p);
}

__device__ __forceinline__ u64 dist_key(float v, int n) {
    unsigned int fb = __float_as_uint(v);
    fb = (fb & 0x80000000u) ? ~fb : (fb | 0x80000000u);
    return ((u64)fb << 32) | (unsigned int)n;
}
__device__ __forceinline__ float dec_bits(unsigned int x) {
    unsigned int vb = (x & 0x80000000u) ? (x & 0x7fffffffu) : ~x;
    return __uint_as_float(vb);
}
__device__ __forceinline__ unsigned int enc_bits(float v) {
    unsigned int tb = __float_as_uint(v);
    return (tb & 0x80000000u) ? ~tb : (tb | 0x80000000u);
}

__device__ __forceinline__ void ldm4(uint32_t* r, uint32_t addr) {
    asm volatile("ldmatrix.sync.aligned.m8n8.x4.shared.b16 {%0,%1,%2,%3}, [%4];"
                 : "=r"(r[0]), "=r"(r[1]), "=r"(r[2]), "=r"(r[3]) : "r"(addr));
}
__device__ __forceinline__ void mma16816(float* c, const uint32_t* a,
                                         uint32_t b0, uint32_t b1) {
    asm volatile(
        "mma.sync.aligned.m16n8k16.row.col.f32.bf16.bf16.f32 "
        "{%0,%1,%2,%3}, {%4,%5,%6,%7}, {%8,%9}, {%0,%1,%2,%3};"
        : "+f"(c[0]), "+f"(c[1]), "+f"(c[2]), "+f"(c[3])
        : "r"(a[0]), "r"(a[1]), "r"(a[2]), "r"(a[3]), "r"(b0), "r"(b1));
}

// smem swizzle (rows of 64 B = 4 x 16B chunks)
__device__ __forceinline__ int swz(int row, int c) {
    return row * 64 + ((c ^ ((row & 3) ^ ((row >> 2) & 1))) << 4);
}
// conv smem swizzle for 32 B rows (2 chunks)
__device__ __forceinline__ int s3(int row) {
    return (row ^ (row >> 1) ^ (row >> 2)) & 1;
}
// unpack 8 bf16 (uint4) -> 8 floats (exact: bf16 = fp32 top bits)
__device__ __forceinline__ void bf8(const uint4 v, float* o) {
    o[0] = __uint_as_float(v.x << 16); o[1] = __uint_as_float(v.x & 0xffff0000u);
    o[2] = __uint_as_float(v.y << 16); o[3] = __uint_as_float(v.y & 0xffff0000u);
    o[4] = __uint_as_float(v.z << 16); o[5] = __uint_as_float(v.z & 0xffff0000u);
    o[6] = __uint_as_float(v.w << 16); o[7] = __uint_as_float(v.w & 0xffff0000u);
}

// ---------------------------------------------------------------------------
// prep: res init + guard zeroing + misc counters
// ---------------------------------------------------------------------------
__global__ void prep_kernel(u64* res, uint32_t* misc,
                            uint32_t* x1h, uint32_t* x1l,
                            uint32_t* x2h, uint32_t* x2l) {
    int i = blockIdx.x * 256 + threadIdx.x;
    if (i < MTOT * KCB) res[i] = ~0ull;
    if (i < 4) misc[i] = 0u;
    if (i < 4096) {
        int half = i >> 11, j = i & 2047;
        int b = j >> 9, r = (j >> 6) & 7, w = j & 63;
        int row = (r < 4) ? r : (L1O + r);
        uint32_t* p = half ? x1l : x1h;
        p[(size_t)(b * (L1O + 8) + row) * 64 + w] = 0u;
    } else if (i < 4096 + 8192) {
        int j = i - 4096;
        int half = j >> 12; j &= 4095;
        int b = j >> 10, r = (j >> 7) & 7, w = j & 127;
        int row = (r < 4) ? r : (L2O + r);
        uint32_t* p = half ? x2l : x2h;
        p[(size_t)(b * (L2O + 8) + row) * 128 + w] = 0u;
    }
}

// ---------------------------------------------------------------------------
// split weights: w [CO][CI][7] fp32 -> Wh/Wl [7][CO][CI] bf16
// ---------------------------------------------------------------------------
__global__ void split_W(const float* __restrict__ w,
                        __nv_bfloat16* __restrict__ wh,
                        __nv_bfloat16* __restrict__ wl, int CO, int CI) {
    int i = blockIdx.x * 256 + threadIdx.x;
    if (i >= CO * CI * 7) return;
    int co = i / (CI * 7);
    int r  = i % (CI * 7);
    int ci = r / 7, t = r % 7;
    float v = w[i];
    __nv_bfloat16 h = __float2bfloat16(v);
    wh[((size_t)t * CO + co) * CI + ci] = h;
    wl[((size_t)t * CO + co) * CI + ci] = __float2bfloat16(v - __bfloat162float(h));
}

// ---------------------------------------------------------------------------
// conv1: [B,1,32768] -> relu -> X1 [b][pos][128] bf16 hi/lo (offset 4 rows)
// ---------------------------------------------------------------------------
__global__ void conv1_kernel(const float* __restrict__ x,
                             const float* __restrict__ w,
                             const float* __restrict__ bias,
                             __nv_bfloat16* __restrict__ yh,
                             __nv_bfloat16* __restrict__ yl) {
    int tid = threadIdx.x;
    int co = tid & 127;
    int l  = blockIdx.x * 2 + (tid >> 7);
    int b  = blockIdx.z;
    const float* xb = x + b * SLEN;
    float acc = bias[co];
#pragma unroll
    for (int t = 0; t < 7; ++t) {
        int g = 2 * l + t - 3;
        float xv = (g >= 0 && g < SLEN) ? xb[g] : 0.0f;
        acc = fmaf(w[co * 7 + t], xv, acc);
    }
    acc = fmaxf(acc, 0.0f);
    __nv_bfloat16 h = __float2bfloat16(acc);
    size_t o = (size_t)(b * (L1O + 8) + l + 4) * C1 + co;
    yh[o] = h;
    yl[o] = __float2bfloat16(acc - __bfloat162float(h));
}

// ---------------------------------------------------------------------------
// conv via mma.sync bf16 split (hh + hl + lh). Single buffer, 2 CTAs/SM.
// ---------------------------------------------------------------------------
#define SLAB_PAR  4352
#define SLAB_HALF 8704
#define SLAB_SZ   17408
#define W_HALF    28672
#define CBUF      74752

template <int CI>
__global__ __launch_bounds__(256, 2) void conv_mma(
        const __nv_bfloat16* __restrict__ Xh, const __nv_bfloat16* __restrict__ Xl,
        const __nv_bfloat16* __restrict__ Wh, const __nv_bfloat16* __restrict__ Wl,
        const float* __restrict__ bias,
        __nv_bfloat16* __restrict__ Yh, __nv_bfloat16* __restrict__ Yl,
        int L_in, int L_out, int CO, int do_relu, int y_pad, int y_off) {
    extern __shared__ __align__(16) char dsm[];
    const uint32_t bb = smem_u32(dsm);

    const int tid  = threadIdx.x;
    const int lane = tid & 31;
    const int wid  = tid >> 5;
    const int wm   = wid >> 1;
    const int wn   = wid & 1;
    const int l0  = blockIdx.x * 128;
    const int co0 = blockIdx.y * 128;
    const int b   = blockIdx.z;

    float acc[2][8][4];
#pragma unroll
    for (int i = 0; i < 2; ++i)
#pragma unroll
        for (int j = 0; j < 8; ++j)
#pragma unroll
            for (int q = 0; q < 4; ++q) acc[i][j][q] = 0.0f;

    auto load_chunk = [&](int ch) {
        const int ci0 = ch * 16;
        for (int i = tid; i < 262 * 4; i += 256) {
            int rel = i >> 2;
            int half = (i >> 1) & 1, ck = i & 1;
            int e = rel >> 1, par = rel & 1;
            const __nv_bfloat16* src = (half ? Xl : Xh) +
                (size_t)(b * (L_in + 8) + 2 * l0 + rel) * CI + ci0 + ck * 8;
            cp16(bb + half * SLAB_HALF + par * SLAB_PAR + e * 32 +
                 ((ck ^ s3(e)) << 4), src);
        }
#pragma unroll
        for (int r = 0; r < 14; ++r) {
            int i = tid + r * 256;
            int row = i >> 2;
            int half = (i >> 1) & 1, ck = i & 1;
            int t = row >> 7, col = row & 127;
            const __nv_bfloat16* src = (half ? Wl : Wh) +
                (size_t)(t * CO + co0 + col) * CI + ci0 + ck * 8;
            cp16(bb + SLAB_SZ + half * W_HALF + row * 32 +
                 ((ck ^ s3(row)) << 4), src);
        }
    };

    const int a_r = lane & 15;
    const int a_h = lane >> 4;
    const int b_r = (lane & 7) + ((lane >> 4) << 3);
    const int b_h = (lane >> 3) & 1;

    const int NCH = CI / 16;
    for (int ch = 0; ch < NCH; ++ch) {
        load_chunk(ch);
        cp_commit();
        cp_wait0();
        __syncthreads();
#pragma unroll
        for (int t = 0; t < 7; ++t) {
            const int par = (t + 1) & 1;
            const int shift = (t + 1) >> 1;
            uint32_t aH[2][4], aL[2][4];
#pragma unroll
            for (int mt = 0; mt < 2; ++mt) {
                int e = wm * 32 + mt * 16 + a_r + shift;
                uint32_t sa = bb + par * SLAB_PAR + e * 32 + ((a_h ^ s3(e)) << 4);
                ldm4(aH[mt], sa);
                ldm4(aL[mt], sa + SLAB_HALF);
            }
#pragma unroll
            for (int g = 0; g < 4; ++g) {
                uint32_t bH[4], bL[4];
                int row = t * 128 + wn * 64 + g * 16 + b_r;
                uint32_t sb = bb + SLAB_SZ + row * 32 + ((b_h ^ s3(row)) << 4);
                ldm4(bH, sb);
                ldm4(bL, sb + W_HALF);
#pragma unroll
                for (int mt = 0; mt < 2; ++mt) {
                    mma16816(acc[mt][g * 2],     aH[mt], bH[0], bH[1]);
                    mma16816(acc[mt][g * 2 + 1], aH[mt], bH[2], bH[3]);
                    mma16816(acc[mt][g * 2],     aH[mt], bL[0], bL[1]);
                    mma16816(acc[mt][g * 2 + 1], aH[mt], bL[2], bL[3]);
                    mma16816(acc[mt][g * 2],     aL[mt], bH[0], bH[1]);
                    mma16816(acc[mt][g * 2 + 1], aL[mt], bH[2], bH[3]);
                }
            }
        }
        if (ch + 1 < NCH) __syncthreads();
    }

    const size_t ybase = (size_t)b * (L_out + y_pad) + y_off;
#pragma unroll
    for (int mt = 0; mt < 2; ++mt)
#pragma unroll
        for (int j = 0; j < 8; ++j)
#pragma unroll
            for (int h8 = 0; h8 < 2; ++h8) {
                int l = l0 + wm * 32 + mt * 16 + (lane >> 2) + h8 * 8;
                int co = co0 + wn * 64 + j * 8 + (lane & 3) * 2;
                float v0 = acc[mt][j][h8 * 2]     + __ldg(&bias[co]);
                float v1 = acc[mt][j][h8 * 2 + 1] + __ldg(&bias[co + 1]);
                if (do_relu) { v0 = fmaxf(v0, 0.0f); v1 = fmaxf(v1, 0.0f); }
                __nv_bfloat16 h0 = __float2bfloat16(v0);
                __nv_bfloat16 h1 = __float2bfloat16(v1);
                __nv_bfloat162 hp; hp.x = h0; hp.y = h1;
                __nv_bfloat162 lp;
                lp.x = __float2bfloat16(v0 - __bfloat162float(h0));
                lp.y = __float2bfloat16(v1 - __bfloat162float(h1));
                size_t o = (ybase + l) * CO + co;
                *(__nv_bfloat162*)(Yh + o) = hp;
                *(__nv_bfloat162*)(Yl + o) = lp;
            }
}

// ---------------------------------------------------------------------------
// fused split_B + bnorm: one pass over cb -> Bh/Bl + c2 + max split norms
// ---------------------------------------------------------------------------
__global__ void splitb_kernel(const float* __restrict__ cb,
                              __nv_bfloat16* __restrict__ bh,
                              __nv_bfloat16* __restrict__ bl,
                              float* __restrict__ c2,
                              uint32_t* __restrict__ misc) {
    int code = blockIdx.x * 8 + (threadIdx.x >> 5);
    int lane = threadIdx.x & 31;
    if (code >= NCODES) return;
    const float* row = cb + (size_t)code * 512 + lane * 16;
    float s = 0.0f, h2 = 0.0f, l2 = 0.0f;
    unsigned int hw[8], lw[8];
#pragma unroll
    for (int q = 0; q < 4; ++q) {
        float4 v = *(const float4*)(row + q * 4);
        float vv[4] = {v.x, v.y, v.z, v.w};
#pragma unroll
        for (int e = 0; e < 2; ++e) {
            float a0 = vv[e * 2], a1 = vv[e * 2 + 1];
            __nv_bfloat16 hb0 = __float2bfloat16(a0);
            __nv_bfloat16 hb1 = __float2bfloat16(a1);
            float hf0 = __bfloat162float(hb0), hf1 = __bfloat162float(hb1);
            float lf0 = a0 - hf0, lf1 = a1 - hf1;
            __nv_bfloat16 lb0 = __float2bfloat16(lf0);
            __nv_bfloat16 lb1 = __float2bfloat16(lf1);
            float lq0 = __bfloat162float(lb0), lq1 = __bfloat162float(lb1);
            __nv_bfloat162 hp; hp.x = hb0; hp.y = hb1;
            __nv_bfloat162 lp; lp.x = lb0; lp.y = lb1;
            hw[q * 2 + e] = *(unsigned int*)&hp;
            lw[q * 2 + e] = *(unsigned int*)&lp;
            s  = fmaf(a0, a0, fmaf(a1, a1, s));
            h2 = fmaf(hf0, hf0, fmaf(hf1, hf1, h2));
            l2 = fmaf(lq0, lq0, fmaf(lq1, lq1, l2));
        }
    }
    uint4* dh = (uint4*)(bh + (size_t)code * 512 + lane * 16);
    uint4* dl = (uint4*)(bl + (size_t)code * 512 + lane * 16);
    dh[0] = make_uint4(hw[0], hw[1], hw[2], hw[3]);
    dh[1] = make_uint4(hw[4], hw[5], hw[6], hw[7]);
    dl[0] = make_uint4(lw[0], lw[1], lw[2], lw[3]);
    dl[1] = make_uint4(lw[4], lw[5], lw[6], lw[7]);
#pragma unroll
    for (int o = 16; o > 0; o >>= 1) {
        s  += __shfl_down_sync(0xffffffffu, s, o);
        h2 += __shfl_down_sync(0xffffffffu, h2, o);
        l2 += __shfl_down_sync(0xffffffffu, l2, o);
    }
    if (lane == 0) {
        c2[code] = s;
        atomicMax(&misc[1], __float_as_uint(h2));
        atomicMax(&misc[2], __float_as_uint(l2));
    }
}

// ---------------------------------------------------------------------------
// thr: per feats row, threshold 2*eb + 0.25 from split norms
// ---------------------------------------------------------------------------
__global__ void thr_kernel(const __nv_bfloat16* __restrict__ Ah,
                           const __nv_bfloat16* __restrict__ Al,
                           const uint32_t* __restrict__ misc,
                           float* __restrict__ thr) {
    int row = blockIdx.x * 8 + (threadIdx.x >> 5);
    int lane = threadIdx.x & 31;
    if (row >= MTOT) return;
    const uint4* ph = (const uint4*)(Ah + (size_t)row * 512 + lane * 16);
    const uint4* pl = (const uint4*)(Al + (size_t)row * 512 + lane * 16);
    float fh[16], fl[16];
    bf8(ph[0], fh); bf8(ph[1], fh + 8);
    bf8(pl[0], fl); bf8(pl[1], fl + 8);
    float sh = 0.0f, sl = 0.0f;
#pragma unroll
    for (int e = 0; e < 16; ++e) {
        sh = fmaf(fh[e], fh[e], sh);
        sl = fmaf(fl[e], fl[e], sl);
    }
#pragma unroll
    for (int o = 16; o > 0; o >>= 1) {
        sh += __shfl_down_sync(0xffffffffu, sh, o);
        sl += __shfl_down_sync(0xffffffffu, sl, o);
    }
    if (lane == 0) {
        float maxBh2 = __uint_as_float(misc[1]);
        float maxBl2 = __uint_as_float(misc[2]);
        float eb = 2.0f * (sqrtf(sh * maxBl2) + sqrtf(sl * maxBh2)
                           + sqrtf(sl * maxBl2));
        thr[row] = 2.0f * eb + 0.25f;
    }
}

// ---------------------------------------------------------------------------
// Approx VQ GEMM (hh only) + per-(row, 8-code subgroup) u32 key:
//   [enc(dist) top 24 bits][candidate mask 8]
// ---------------------------------------------------------------------------
#define VBUF2 16384

__global__ __launch_bounds__(256, 2) void vq_approx(
        const __nv_bfloat16* __restrict__ Ah, const __nv_bfloat16* __restrict__ Bh,
        const float* __restrict__ c2, const float* __restrict__ thr,
        uint32_t* __restrict__ gkey) {
    extern __shared__ __align__(16) char dsm[];          // 2 * 16 KB
    __shared__ uint32_t sG[128][16];

    const int tid  = threadIdx.x;
    const int lane = tid & 31;
    const int wid  = tid >> 5;
    const int wm   = wid >> 1;
    const int wn   = wid & 1;
    const int m0 = blockIdx.x * 128;
    const int n0 = blockIdx.y * 128;
    const uint32_t sbase = smem_u32(dsm);

    float acc[2][8][4];
#pragma unroll
    for (int i = 0; i < 2; ++i)
#pragma unroll
        for (int j = 0; j < 8; ++j)
#pragma unroll
            for (int q = 0; q < 4; ++q) acc[i][j][q] = 0.0f;

    auto load_chunk = [&](int c, int buf) {
        const int k0 = c * 32;
        const uint32_t bb = sbase + buf * VBUF2;
#pragma unroll
        for (int r = 0; r < 4; ++r) {
            int i = tid + r * 256;
            int row = (i >> 2) & 127;
            int cc  = i & 3;
            if (i < 512) {
                cp16(bb + swz(row, cc),
                     Ah + (size_t)(m0 + row) * 512 + k0 + cc * 8);
            } else {
                cp16(bb + 8192 + swz(row, cc),
                     Bh + (size_t)(n0 + row) * 512 + k0 + cc * 8);
            }
        }
    };

    load_chunk(0, 0);
    cp_commit();

    const int a_r = lane & 15;
    const int a_h = lane >> 4;
    const int b_r = (lane & 7) + ((lane >> 4) << 3);
    const int b_h = (lane >> 3) & 1;

    for (int c = 0; c < 16; ++c) {
        const int buf = c & 1;
        cp_wait0();
        __syncthreads();
        if (c < 15) { load_chunk(c + 1, buf ^ 1); cp_commit(); }

        const uint32_t bb = sbase + buf * VBUF2;
#pragma unroll
        for (int s = 0; s < 2; ++s) {
            uint32_t a[2][4];
#pragma unroll
            for (int mt = 0; mt < 2; ++mt) {
                int r = wm * 32 + mt * 16 + a_r;
                ldm4(a[mt], bb + swz(r, s * 2 + a_h));
            }
#pragma unroll
            for (int g = 0; g < 4; ++g) {
                uint32_t bH[4];
                int r = wn * 64 + g * 16 + b_r;
                ldm4(bH, bb + 8192 + swz(r, s * 2 + b_h));
#pragma unroll
                for (int mt = 0; mt < 2; ++mt) {
                    mma16816(acc[mt][g * 2],     a[mt], bH[0], bH[1]);
                    mma16816(acc[mt][g * 2 + 1], a[mt], bH[2], bH[3]);
                }
            }
        }
    }

    // c2 for this thread's 16 columns
    float c2v[16];
#pragma unroll
    for (int j = 0; j < 8; ++j)
#pragma unroll
        for (int cb = 0; cb < 2; ++cb)
            c2v[j * 2 + cb] =
                __ldg(&c2[n0 + wn * 64 + j * 8 + (lane & 3) * 2 + cb]);

    // per-(row, 8-code subgroup) min + candidate masks -> u32
#pragma unroll
    for (int mt = 0; mt < 2; ++mt)
#pragma unroll
        for (int h = 0; h < 2; ++h) {
            int row = wm * 32 + mt * 16 + (lane >> 2) + h * 8;
            float tv = __ldg(&thr[m0 + row]);
#pragma unroll
            for (int j = 0; j < 8; ++j) {
                float d0 = c2v[j * 2]     - 2.0f * acc[mt][j][h * 2];
                float d1 = c2v[j * 2 + 1] - 2.0f * acc[mt][j][h * 2 + 1];
                float dmin = fminf(d0, d1);
                float o1 = __uint_as_float(
                    __shfl_xor_sync(0xffffffffu, __float_as_uint(dmin), 1));
                dmin = fminf(dmin, o1);
                float o2 = __uint_as_float(
                    __shfl_xor_sync(0xffffffffu, __float_as_uint(dmin), 2));
                dmin = fminf(dmin, o2);
                float Tg = dmin + tv;
                unsigned int lm = 0;
                if (d0 <= Tg) lm |= 1u << ((lane & 3) * 2);
                if (d1 <= Tg) lm |= 1u << ((lane & 3) * 2 + 1);
                lm |= __shfl_xor_sync(0xffffffffu, lm, 1);
                lm |= __shfl_xor_sync(0xffffffffu, lm, 2);
                if ((lane & 3) == 0)
                    sG[row][wn * 8 + j] = (enc_bits(dmin) & 0xffffff00u) | lm;
            }
        }
    __syncthreads();

    for (int i = tid; i < 2048; i += 256) {
        int row = i >> 4, j = i & 15;
        gkey[(size_t)(m0 + row) * NGRP + blockIdx.y * 16 + j] = sG[row][j];
    }
}

// ---------------------------------------------------------------------------
// flag: per (row, cb) min over 256 subgroup keys, threshold, emit items
// item = m(14b) << 18 | group(10b) << 8 | mask(8b)
// ---------------------------------------------------------------------------
__global__ void flag_kernel(const uint32_t* __restrict__ gkey,
                            const float* __restrict__ thr,
                            uint32_t* __restrict__ misc,
                            uint32_t* __restrict__ items) {
    int m = blockIdx.x * 8 + (threadIdx.x >> 5);
    int lane = threadIdx.x & 31;
    if (m >= MTOT) return;

    float tv = __ldg(&thr[m]);

#pragma unroll
    for (int cb = 0; cb < 4; ++cb) {
        uint32_t kq[8];
        unsigned int mn = ~0u;
#pragma unroll
        for (int q = 0; q < 8; ++q) {
            uint32_t k = gkey[(size_t)m * NGRP + cb * 256 + q * 32 + lane];
            kq[q] = k;
            unsigned int e = k >> 8;
            if (e < mn) mn = e;
        }
#pragma unroll
        for (int o = 16; o > 0; o >>= 1) {
            unsigned int v = __shfl_xor_sync(0xffffffffu, mn, o);
            if (v < mn) mn = v;
        }
        float M = dec_bits(mn << 8);
        unsigned int encT = enc_bits(M + tv) >> 8;
        unsigned int cbmask = 0;
#pragma unroll
        for (int q = 0; q < 8; ++q)
            if ((kq[q] >> 8) <= encT) cbmask |= 1u << q;

        int cnt = __popc(cbmask);
        int incl = cnt;
#pragma unroll
        for (int o = 1; o < 32; o <<= 1) {
            int v = __shfl_up_sync(0xffffffffu, incl, o);
            if (lane >= o) incl += v;
        }
        int total = __shfl_sync(0xffffffffu, incl, 31);
        unsigned int base = 0;
        if (lane == 31 && total > 0)
            base = atomicAdd(&misc[0], (unsigned int)total);
        base = __shfl_sync(0xffffffffu, base, 31);
        int off = (int)base + incl - cnt;
#pragma unroll
        for (int q = 0; q < 8; ++q)
            if (cbmask & (1u << q)) {
                int g = cb * 256 + q * 32 + lane;
                items[off++] = ((unsigned int)m << 18) |
                               ((unsigned int)g << 8) | (kq[q] & 0xffu);
            }
    }
}

// ---------------------------------------------------------------------------
// refine: exact fp32 distances for masked codes of each flagged subgroup
// ---------------------------------------------------------------------------
__global__ void refine_kernel(const __nv_bfloat16* __restrict__ Ah,
                              const __nv_bfloat16* __restrict__ Al,
                              const __nv_bfloat16* __restrict__ Bh,
                              const __nv_bfloat16* __restrict__ Bl,
                              const float* __restrict__ c2,
                              const uint32_t* __restrict__ misc,
                              const uint32_t* __restrict__ items,
                              u64* __restrict__ res) {
    const int lane = threadIdx.x & 31;
    const int wgid = blockIdx.x * 8 + (threadIdx.x >> 5);
    const int nw = gridDim.x * 8;
    const int cnt = (int)misc[0];

    for (int it = wgid; it < cnt; it += nw) {
        unsigned int item = items[it];
        int m = item >> 18;
        int g = (item >> 8) & 1023;
        unsigned int cmask = item & 0xffu;
        int cb = g >> 8;
        int n0 = g * 8;

        float f[16], t0[8], t1[8];
        {
            const uint4* ph = (const uint4*)(Ah + (size_t)m * 512 + lane * 16);
            const uint4* pl = (const uint4*)(Al + (size_t)m * 512 + lane * 16);
            uint4 h0 = ph[0], h1 = ph[1], l0v = pl[0], l1v = pl[1];
            bf8(h0, f); bf8(h1, f + 8);
            bf8(l0v, t0); bf8(l1v, t1);
#pragma unroll
            for (int e = 0; e < 8; ++e)  f[e] += t0[e];
#pragma unroll
            for (int e = 0; e < 8; ++e)  f[e + 8] += t1[e];
        }

        u64 best = ~0ull;
        unsigned int mm = cmask;
        while (mm) {
            int c = __ffs(mm) - 1;
            mm &= mm - 1;
            int n = n0 + c;
            const uint4* pb = (const uint4*)(Bh + (size_t)n * 512 + lane * 16);
            const uint4* pq = (const uint4*)(Bl + (size_t)n * 512 + lane * 16);
            uint4 b0 = pb[0], b1 = pb[1], q0 = pq[0], q1 = pq[1];
            float g0[8], g1[8], r0[8], r1[8];
            bf8(b0, g0); bf8(b1, g1); bf8(q0, r0); bf8(q1, r1);
            float dot = 0.0f;
#pragma unroll
            for (int e = 0; e < 8; ++e) dot = fmaf(f[e], g0[e] + r0[e], dot);
#pragma unroll
            for (int e = 0; e < 8; ++e) dot = fmaf(f[e + 8], g1[e] + r1[e], dot);
#pragma unroll
            for (int o = 16; o > 0; o >>= 1)
                dot += __shfl_down_sync(0xffffffffu, dot, o);
            if (lane == 0) {
                float d = __ldg(&c2[n]) - 2.0f * dot;
                u64 k = dist_key(d, n);
                if (k < best) best = k;
            }
        }
        if (lane == 0 && best != ~0ull) atomicMin(&res[m * 4 + cb], best);
    }
}

// ---------------------------------------------------------------------------
// Finalize: tokens from g_res + embedding mean
// ---------------------------------------------------------------------------
__global__ void finalize_kernel(const u64* __restrict__ res,
                                const float* __restrict__ emb_table,
                                float* __restrict__ out) {
    __shared__ int tok[KCB];
    const int m = blockIdx.x;
    const int b = m >> 12, l = m & 4095;
    const int tid = threadIdx.x;

    if (tid < KCB) {
        int t = ((int)(res[m * 4 + tid] & 0xffffffffu)) & (VOCAB - 1);
        tok[tid] = t;
        out[((size_t)b * KCB + tid) * L3O + l] = (float)t;
    }
    __syncthreads();

    float* out_emb = out + (size_t)NB * KCB * L3O;
    int t0 = tok[0], t1 = tok[1], t2 = tok[2], t3 = tok[3];
    for (int h = tid; h < 512; h += 128) {
        float s = emb_table[(size_t)t0 * 512 + h] + emb_table[(size_t)t1 * 512 + h]
                + emb_table[(size_t)t2 * 512 + h] + emb_table[(size_t)t3 * 512 + h];
        out_emb[((size_t)b * L3O + l) * 512 + h] = 0.25f * s;
    }
}

// ---------------------------------------------------------------------------
extern "C" void kernel_launch(void* const* d_in, const int* in_sizes, int n_in,
                              void* d_out, int out_size) {
    const float* audio = (const float*)d_in[0];
    const float* w1    = (const float*)d_in[1];
    const float* b1    = (const float*)d_in[2];
    const float* w2    = (const float*)d_in[3];
    const float* b2    = (const float*)d_in[4];
    const float* w3    = (const float*)d_in[5];
    const float* b3    = (const float*)d_in[6];
    const float* cb    = (const float*)d_in[7];
    const float* emb   = (const float*)d_in[8];
    float* out = (float*)d_out;

    __nv_bfloat16 *x1h, *x1l, *x2h, *x2l, *w2h, *w2l, *w3h, *w3l;
    __nv_bfloat16 *ah, *al, *bh, *bl;
    float *c2p, *thrp;
    u64 *resp;
    uint32_t *gkeyp, *miscp, *itemsp;
    cudaGetSymbolAddress((void**)&x1h, g_X1h);
    cudaGetSymbolAddress((void**)&x1l, g_X1l);
    cudaGetSymbolAddress((void**)&x2h, g_X2h);
    cudaGetSymbolAddress((void**)&x2l, g_X2l);
    cudaGetSymbolAddress((void**)&w2h, g_W2h);
    cudaGetSymbolAddress((void**)&w2l, g_W2l);
    cudaGetSymbolAddress((void**)&w3h, g_W3h);
    cudaGetSymbolAddress((void**)&w3l, g_W3l);
    cudaGetSymbolAddress((void**)&ah,  g_Ah);
    cudaGetSymbolAddress((void**)&al,  g_Al);
    cudaGetSymbolAddress((void**)&bh,  g_Bh);
    cudaGetSymbolAddress((void**)&bl,  g_Bl);
    cudaGetSymbolAddress((void**)&c2p, g_c2);
    cudaGetSymbolAddress((void**)&thrp, g_thr);
    cudaGetSymbolAddress((void**)&gkeyp, g_gkey32);
    cudaGetSymbolAddress((void**)&itemsp, g_items);
    cudaGetSymbolAddress((void**)&miscp, g_misc);
    cudaGetSymbolAddress((void**)&resp, g_res);

    // side stream for the codebook/weight prep chain (graph fork pattern).
    // Created per call: kernel_launch only runs for correctness + capture,
    // never per graph replay, so the handful of leaked handles is harmless.
    cudaStream_t side;
    cudaStreamCreateWithFlags(&side, cudaStreamNonBlocking);
    cudaEvent_t eFork, eW2, eW3, eSB;
    cudaEventCreateWithFlags(&eFork, cudaEventDisableTiming);
    cudaEventCreateWithFlags(&eW2,   cudaEventDisableTiming);
    cudaEventCreateWithFlags(&eW3,   cudaEventDisableTiming);
    cudaEventCreateWithFlags(&eSB,   cudaEventDisableTiming);

    cudaEventRecord(eFork, 0);
    cudaStreamWaitEvent(side, eFork, 0);
    split_W<<<(C2C * C1 * 7 + 255) / 256, 256, 0, side>>>(w2, w2h, w2l, C2C, C1);
    cudaEventRecord(eW2, side);
    split_W<<<(C3 * C2C * 7 + 255) / 256, 256, 0, side>>>(w3, w3h, w3l, C3, C2C);
    cudaEventRecord(eW3, side);
    splitb_kernel<<<NCODES / 8, 256, 0, side>>>(cb, bh, bl, c2p, miscp);
    cudaEventRecord(eSB, side);

    // main stream: audio chain
    prep_kernel<<<(MTOT * KCB + 255) / 256, 256>>>(
        resp, miscp, (uint32_t*)x1h, (uint32_t*)x1l, (uint32_t*)x2h, (uint32_t*)x2l);
    conv1_kernel<<<dim3(L1O / 2, 1, NB), 256>>>(audio, w1, b1, x1h, x1l);

    cudaStreamWaitEvent(0, eW2, 0);
    cudaFuncSetAttribute(conv_mma<C1>, cudaFuncAttributeMaxDynamicSharedMemorySize,
                         CBUF);
    conv_mma<C1><<<dim3(L2O / 128, C2C / 128, NB), 256, CBUF>>>(
        x1h, x1l, w2h, w2l, b2, x2h, x2l, L1O, L2O, C2C, 1, 8, 4);

    cudaStreamWaitEvent(0, eW3, 0);
    cudaFuncSetAttribute(conv_mma<C2C>, cudaFuncAttributeMaxDynamicSharedMemorySize,
                         CBUF);
    conv_mma<C2C><<<dim3(L3O / 128, C3 / 128, NB), 256, CBUF>>>(
        x2h, x2l, w3h, w3l, b3, ah, al, L2O, L3O, C3, 0, 0, 0);

    cudaStreamWaitEvent(0, eSB, 0);
    thr_kernel<<<MTOT / 8, 256>>>(ah, al, miscp, thrp);

    cudaFuncSetAttribute(vq_approx, cudaFuncAttributeMaxDynamicSharedMemorySize,
                         2 * VBUF2);
    vq_approx<<<dim3(MTOT / 128, NCODES / 128), 256, 2 * VBUF2>>>(
        ah, bh, c2p, thrp, gkeyp);

    flag_kernel<<<MTOT / 8, 256>>>(gkeyp, thrp, miscp, itemsp);
    refine_kernel<<<1024, 256>>>(ah, al, bh, bl, c2p, miscp, itemsp, resp);

    finalize_kernel<<<MTOT, 128>>>(resp, emb, out);
}

// round 15
// speedup vs baseline: 1.5511x; 1.0047x over previous
#include <cuda_runtime.h>
#include <cuda_bf16.h>
#include <cstdint>

// Problem constants
#define NB 4
#define SLEN 32768
#define C1 128
#define C2C 256
#define C3 512
#define L1O 16384
#define L2O 8192
#define L3O 4096
#define VOCAB 2048
#define KCB 4
#define NCODES (KCB * VOCAB)   // 8192
#define MTOT (NB * L3O)        // 16384
#define NGRP 1024              // 8-code subgroups per row (8192/8)
#define GRP_CB 256             // subgroups per codebook per row

typedef unsigned long long u64;

// bf16 split activations, transposed: X [b][pos][CI], 4 guard rows each side.
__device__ ulonglong2 g_X1h[NB * (L1O + 8) * C1 / 8];
__device__ ulonglong2 g_X1l[NB * (L1O + 8) * C1 / 8];
__device__ ulonglong2 g_X2h[NB * (L2O + 8) * C2C / 8];
__device__ ulonglong2 g_X2l[NB * (L2O + 8) * C2C / 8];
// split weights [7][CO][CI]
__device__ ulonglong2 g_W2h[7 * C2C * C1 / 8];
__device__ ulonglong2 g_W2l[7 * C2C * C1 / 8];
__device__ ulonglong2 g_W3h[7 * C3 * C2C / 8];
__device__ ulonglong2 g_W3l[7 * C3 * C2C / 8];
// vq operands
__device__ ulonglong2 g_Ah[MTOT * 512 / 8];      // feats hi  [m][k] (conv3 output)
__device__ ulonglong2 g_Al[MTOT * 512 / 8];
__device__ ulonglong2 g_Bh[NCODES * 512 / 8];    // codes hi  [n][k]
__device__ ulonglong2 g_Bl[NCODES * 512 / 8];
__device__ float  g_c2[NCODES];
__device__ float  g_thr[MTOT];                   // per-row threshold 2*eb + 0.25
__device__ uint32_t g_gkey32[(size_t)MTOT * NGRP]; // per group: encdist24|mask8
__device__ uint32_t g_items[(size_t)MTOT * NGRP];  // per-cb partitions
__device__ uint32_t g_misc[8];                   // [1]=maxBh2 [2]=maxBl2 [4+cb]=count
__device__ u64    g_res[MTOT * KCB];             // final per (row, cb) key

// ---------------------------------------------------------------------------
// helpers
// ---------------------------------------------------------------------------
__device__ __forceinline__ void cp16(uint32_t dst, const void* src) {
    asm volatile("cp.async.cg.shared.global [%0], [%1], 16;" :: "r"(dst), "l"(src));
}
__device__ __forceinline__ void cp_commit() { asm volatile("cp.async.commit_group;"); }
__device__ __forceinline__ void cp_wait0()  { asm volatile("cp.async.wait_group 0;"); }

__device__ __forceinline__ uint32_t smem_u32(const void* p) {
    return (uint32_t)__cvta_generic_to_shared(p);
}

__device__ __forceinline__ u64 dist_key(float v, int n) {
    unsigned int fb = __float_as_uint(v);
    fb = (fb & 0x80000000u) ? ~fb : (fb | 0x80000000u);
    return ((u64)fb << 32) | (unsigned int)n;
}
__device__ __forceinline__ float dec_bits(unsigned int x) {
    unsigned int vb = (x & 0x80000000u) ? (x & 0x7fffffffu) : ~x;
    return __uint_as_float(vb);
}
__device__ __forceinline__ unsigned int enc_bits(float v) {
    unsigned int tb = __float_as_uint(v);
    return (tb & 0x80000000u) ? ~tb : (tb | 0x80000000u);
}

__device__ __forceinline__ void ldm4(uint32_t* r, uint32_t addr) {
    asm volatile("ldmatrix.sync.aligned.m8n8.x4.shared.b16 {%0,%1,%2,%3}, [%4];"
                 : "=r"(r[0]), "=r"(r[1]), "=r"(r[2]), "=r"(r[3]) : "r"(addr));
}
__device__ __forceinline__ void mma16816(float* c, const uint32_t* a,
                                         uint32_t b0, uint32_t b1) {
    asm volatile(
        "mma.sync.aligned.m16n8k16.row.col.f32.bf16.bf16.f32 "
        "{%0,%1,%2,%3}, {%4,%5,%6,%7}, {%8,%9}, {%0,%1,%2,%3};"
        : "+f"(c[0]), "+f"(c[1]), "+f"(c[2]), "+f"(c[3])
        : "r"(a[0]), "r"(a[1]), "r"(a[2]), "r"(a[3]), "r"(b0), "r"(b1));
}

// smem swizzle (rows of 64 B = 4 x 16B chunks)
__device__ __forceinline__ int swz(int row, int c) {
    return row * 64 + ((c ^ ((row & 3) ^ ((row >> 2) & 1))) << 4);
}
// conv smem swizzle for 32 B rows (2 chunks)
__device__ __forceinline__ int s3(int row) {
    return (row ^ (row >> 1) ^ (row >> 2)) & 1;
}
// unpack 8 bf16 (uint4) -> 8 floats (exact: bf16 = fp32 top bits)
__device__ __forceinline__ void bf8(const uint4 v, float* o) {
    o[0] = __uint_as_float(v.x << 16); o[1] = __uint_as_float(v.x & 0xffff0000u);
    o[2] = __uint_as_float(v.y << 16); o[3] = __uint_as_float(v.y & 0xffff0000u);
    o[4] = __uint_as_float(v.z << 16); o[5] = __uint_as_float(v.z & 0xffff0000u);
    o[6] = __uint_as_float(v.w << 16); o[7] = __uint_as_float(v.w & 0xffff0000u);
}

// ---------------------------------------------------------------------------
// prep: res init + guard zeroing + misc counters
// ---------------------------------------------------------------------------
__global__ void prep_kernel(u64* res, uint32_t* misc,
                            uint32_t* x1h, uint32_t* x1l,
                            uint32_t* x2h, uint32_t* x2l) {
    int i = blockIdx.x * 256 + threadIdx.x;
    if (i < MTOT * KCB) res[i] = ~0ull;
    if (i < 8) misc[i] = 0u;
    if (i < 4096) {
        int half = i >> 11, j = i & 2047;
        int b = j >> 9, r = (j >> 6) & 7, w = j & 63;
        int row = (r < 4) ? r : (L1O + r);
        uint32_t* p = half ? x1l : x1h;
        p[(size_t)(b * (L1O + 8) + row) * 64 + w] = 0u;
    } else if (i < 4096 + 8192) {
        int j = i - 4096;
        int half = j >> 12; j &= 4095;
        int b = j >> 10, r = (j >> 7) & 7, w = j & 127;
        int row = (r < 4) ? r : (L2O + r);
        uint32_t* p = half ? x2l : x2h;
        p[(size_t)(b * (L2O + 8) + row) * 128 + w] = 0u;
    }
}

// ---------------------------------------------------------------------------
// split weights: w [CO][CI][7] fp32 -> Wh/Wl [7][CO][CI] bf16
// ---------------------------------------------------------------------------
__global__ void split_W(const float* __restrict__ w,
                        __nv_bfloat16* __restrict__ wh,
                        __nv_bfloat16* __restrict__ wl, int CO, int CI) {
    int i = blockIdx.x * 256 + threadIdx.x;
    if (i >= CO * CI * 7) return;
    int co = i / (CI * 7);
    int r  = i % (CI * 7);
    int ci = r / 7, t = r % 7;
    float v = w[i];
    __nv_bfloat16 h = __float2bfloat16(v);
    wh[((size_t)t * CO + co) * CI + ci] = h;
    wl[((size_t)t * CO + co) * CI + ci] = __float2bfloat16(v - __bfloat162float(h));
}

// ---------------------------------------------------------------------------
// conv1: [B,1,32768] -> relu -> X1 [b][pos][128] bf16 hi/lo (offset 4 rows)
// ---------------------------------------------------------------------------
__global__ void conv1_kernel(const float* __restrict__ x,
                             const float* __restrict__ w,
                             const float* __restrict__ bias,
                             __nv_bfloat16* __restrict__ yh,
                             __nv_bfloat16* __restrict__ yl) {
    int tid = threadIdx.x;
    int co = tid & 127;
    int l  = blockIdx.x * 2 + (tid >> 7);
    int b  = blockIdx.z;
    const float* xb = x + b * SLEN;
    float acc = bias[co];
#pragma unroll
    for (int t = 0; t < 7; ++t) {
        int g = 2 * l + t - 3;
        float xv = (g >= 0 && g < SLEN) ? xb[g] : 0.0f;
        acc = fmaf(w[co * 7 + t], xv, acc);
    }
    acc = fmaxf(acc, 0.0f);
    __nv_bfloat16 h = __float2bfloat16(acc);
    size_t o = (size_t)(b * (L1O + 8) + l + 4) * C1 + co;
    yh[o] = h;
    yl[o] = __float2bfloat16(acc - __bfloat162float(h));
}

// ---------------------------------------------------------------------------
// conv via mma.sync bf16 split (hh + hl + lh). Single buffer, 2 CTAs/SM.
// ---------------------------------------------------------------------------
#define SLAB_PAR  4352
#define SLAB_HALF 8704
#define SLAB_SZ   17408
#define W_HALF    28672
#define CBUF      74752

template <int CI>
__global__ __launch_bounds__(256, 2) void conv_mma(
        const __nv_bfloat16* __restrict__ Xh, const __nv_bfloat16* __restrict__ Xl,
        const __nv_bfloat16* __restrict__ Wh, const __nv_bfloat16* __restrict__ Wl,
        const float* __restrict__ bias,
        __nv_bfloat16* __restrict__ Yh, __nv_bfloat16* __restrict__ Yl,
        int L_in, int L_out, int CO, int do_relu, int y_pad, int y_off) {
    extern __shared__ __align__(16) char dsm[];
    const uint32_t bb = smem_u32(dsm);

    const int tid  = threadIdx.x;
    const int lane = tid & 31;
    const int wid  = tid >> 5;
    const int wm   = wid >> 1;
    const int wn   = wid & 1;
    const int l0  = blockIdx.x * 128;
    const int co0 = blockIdx.y * 128;
    const int b   = blockIdx.z;

    float acc[2][8][4];
#pragma unroll
    for (int i = 0; i < 2; ++i)
#pragma unroll
        for (int j = 0; j < 8; ++j)
#pragma unroll
            for (int q = 0; q < 4; ++q) acc[i][j][q] = 0.0f;

    auto load_chunk = [&](int ch) {
        const int ci0 = ch * 16;
        for (int i = tid; i < 262 * 4; i += 256) {
            int rel = i >> 2;
            int half = (i >> 1) & 1, ck = i & 1;
            int e = rel >> 1, par = rel & 1;
            const __nv_bfloat16* src = (half ? Xl : Xh) +
                (size_t)(b * (L_in + 8) + 2 * l0 + rel) * CI + ci0 + ck * 8;
            cp16(bb + half * SLAB_HALF + par * SLAB_PAR + e * 32 +
                 ((ck ^ s3(e)) << 4), src);
        }
#pragma unroll
        for (int r = 0; r < 14; ++r) {
            int i = tid + r * 256;
            int row = i >> 2;
            int half = (i >> 1) & 1, ck = i & 1;
            int t = row >> 7, col = row & 127;
            const __nv_bfloat16* src = (half ? Wl : Wh) +
                (size_t)(t * CO + co0 + col) * CI + ci0 + ck * 8;
            cp16(bb + SLAB_SZ + half * W_HALF + row * 32 +
                 ((ck ^ s3(row)) << 4), src);
        }
    };

    const int a_r = lane & 15;
    const int a_h = lane >> 4;
    const int b_r = (lane & 7) + ((lane >> 4) << 3);
    const int b_h = (lane >> 3) & 1;

    const int NCH = CI / 16;
    for (int ch = 0; ch < NCH; ++ch) {
        load_chunk(ch);
        cp_commit();
        cp_wait0();
        __syncthreads();
#pragma unroll
        for (int t = 0; t < 7; ++t) {
            const int par = (t + 1) & 1;
            const int shift = (t + 1) >> 1;
            uint32_t aH[2][4], aL[2][4];
#pragma unroll
            for (int mt = 0; mt < 2; ++mt) {
                int e = wm * 32 + mt * 16 + a_r + shift;
                uint32_t sa = bb + par * SLAB_PAR + e * 32 + ((a_h ^ s3(e)) << 4);
                ldm4(aH[mt], sa);
                ldm4(aL[mt], sa + SLAB_HALF);
            }
#pragma unroll
            for (int g = 0; g < 4; ++g) {
                uint32_t bH[4], bL[4];
                int row = t * 128 + wn * 64 + g * 16 + b_r;
                uint32_t sb = bb + SLAB_SZ + row * 32 + ((b_h ^ s3(row)) << 4);
                ldm4(bH, sb);
                ldm4(bL, sb + W_HALF);
#pragma unroll
                for (int mt = 0; mt < 2; ++mt) {
                    mma16816(acc[mt][g * 2],     aH[mt], bH[0], bH[1]);
                    mma16816(acc[mt][g * 2 + 1], aH[mt], bH[2], bH[3]);
                    mma16816(acc[mt][g * 2],     aH[mt], bL[0], bL[1]);
                    mma16816(acc[mt][g * 2 + 1], aH[mt], bL[2], bL[3]);
                    mma16816(acc[mt][g * 2],     aL[mt], bH[0], bH[1]);
                    mma16816(acc[mt][g * 2 + 1], aL[mt], bH[2], bH[3]);
                }
            }
        }
        if (ch + 1 < NCH) __syncthreads();
    }

    const size_t ybase = (size_t)b * (L_out + y_pad) + y_off;
#pragma unroll
    for (int mt = 0; mt < 2; ++mt)
#pragma unroll
        for (int j = 0; j < 8; ++j)
#pragma unroll
            for (int h8 = 0; h8 < 2; ++h8) {
                int l = l0 + wm * 32 + mt * 16 + (lane >> 2) + h8 * 8;
                int co = co0 + wn * 64 + j * 8 + (lane & 3) * 2;
                float v0 = acc[mt][j][h8 * 2]     + __ldg(&bias[co]);
                float v1 = acc[mt][j][h8 * 2 + 1] + __ldg(&bias[co + 1]);
                if (do_relu) { v0 = fmaxf(v0, 0.0f); v1 = fmaxf(v1, 0.0f); }
                __nv_bfloat16 h0 = __float2bfloat16(v0);
                __nv_bfloat16 h1 = __float2bfloat16(v1);
                __nv_bfloat162 hp; hp.x = h0; hp.y = h1;
                __nv_bfloat162 lp;
                lp.x = __float2bfloat16(v0 - __bfloat162float(h0));
                lp.y = __float2bfloat16(v1 - __bfloat162float(h1));
                size_t o = (ybase + l) * CO + co;
                *(__nv_bfloat162*)(Yh + o) = hp;
                *(__nv_bfloat162*)(Yl + o) = lp;
            }
}

// ---------------------------------------------------------------------------
// fused split_B + bnorm: one pass over cb -> Bh/Bl + c2 + max split norms
// ---------------------------------------------------------------------------
__global__ void splitb_kernel(const float* __restrict__ cb,
                              __nv_bfloat16* __restrict__ bh,
                              __nv_bfloat16* __restrict__ bl,
                              float* __restrict__ c2,
                              uint32_t* __restrict__ misc) {
    int code = blockIdx.x * 8 + (threadIdx.x >> 5);
    int lane = threadIdx.x & 31;
    if (code >= NCODES) return;
    const float* row = cb + (size_t)code * 512 + lane * 16;
    float s = 0.0f, h2 = 0.0f, l2 = 0.0f;
    unsigned int hw[8], lw[8];
#pragma unroll
    for (int q = 0; q < 4; ++q) {
        float4 v = *(const float4*)(row + q * 4);
        float vv[4] = {v.x, v.y, v.z, v.w};
#pragma unroll
        for (int e = 0; e < 2; ++e) {
            float a0 = vv[e * 2], a1 = vv[e * 2 + 1];
            __nv_bfloat16 hb0 = __float2bfloat16(a0);
            __nv_bfloat16 hb1 = __float2bfloat16(a1);
            float hf0 = __bfloat162float(hb0), hf1 = __bfloat162float(hb1);
            float lf0 = a0 - hf0, lf1 = a1 - hf1;
            __nv_bfloat16 lb0 = __float2bfloat16(lf0);
            __nv_bfloat16 lb1 = __float2bfloat16(lf1);
            float lq0 = __bfloat162float(lb0), lq1 = __bfloat162float(lb1);
            __nv_bfloat162 hp; hp.x = hb0; hp.y = hb1;
            __nv_bfloat162 lp; lp.x = lb0; lp.y = lb1;
            hw[q * 2 + e] = *(unsigned int*)&hp;
            lw[q * 2 + e] = *(unsigned int*)&lp;
            s  = fmaf(a0, a0, fmaf(a1, a1, s));
            h2 = fmaf(hf0, hf0, fmaf(hf1, hf1, h2));
            l2 = fmaf(lq0, lq0, fmaf(lq1, lq1, l2));
        }
    }
    uint4* dh = (uint4*)(bh + (size_t)code * 512 + lane * 16);
    uint4* dl = (uint4*)(bl + (size_t)code * 512 + lane * 16);
    dh[0] = make_uint4(hw[0], hw[1], hw[2], hw[3]);
    dh[1] = make_uint4(hw[4], hw[5], hw[6], hw[7]);
    dl[0] = make_uint4(lw[0], lw[1], lw[2], lw[3]);
    dl[1] = make_uint4(lw[4], lw[5], lw[6], lw[7]);
#pragma unroll
    for (int o = 16; o > 0; o >>= 1) {
        s  += __shfl_down_sync(0xffffffffu, s, o);
        h2 += __shfl_down_sync(0xffffffffu, h2, o);
        l2 += __shfl_down_sync(0xffffffffu, l2, o);
    }
    if (lane == 0) {
        c2[code] = s;
        atomicMax(&misc[1], __float_as_uint(h2));
        atomicMax(&misc[2], __float_as_uint(l2));
    }
}

// ---------------------------------------------------------------------------
// thr: per feats row, threshold 2*eb + 0.25 from split norms
// ---------------------------------------------------------------------------
__global__ void thr_kernel(const __nv_bfloat16* __restrict__ Ah,
                           const __nv_bfloat16* __restrict__ Al,
                           const uint32_t* __restrict__ misc,
                           float* __restrict__ thr) {
    int row = blockIdx.x * 8 + (threadIdx.x >> 5);
    int lane = threadIdx.x & 31;
    if (row >= MTOT) return;
    const uint4* ph = (const uint4*)(Ah + (size_t)row * 512 + lane * 16);
    const uint4* pl = (const uint4*)(Al + (size_t)row * 512 + lane * 16);
    float fh[16], fl[16];
    bf8(ph[0], fh); bf8(ph[1], fh + 8);
    bf8(pl[0], fl); bf8(pl[1], fl + 8);
    float sh = 0.0f, sl = 0.0f;
#pragma unroll
    for (int e = 0; e < 16; ++e) {
        sh = fmaf(fh[e], fh[e], sh);
        sl = fmaf(fl[e], fl[e], sl);
    }
#pragma unroll
    for (int o = 16; o > 0; o >>= 1) {
        sh += __shfl_down_sync(0xffffffffu, sh, o);
        sl += __shfl_down_sync(0xffffffffu, sl, o);
    }
    if (lane == 0) {
        float maxBh2 = __uint_as_float(misc[1]);
        float maxBl2 = __uint_as_float(misc[2]);
        float eb = 2.0f * (sqrtf(sh * maxBl2) + sqrtf(sl * maxBh2)
                           + sqrtf(sl * maxBl2));
        thr[row] = 2.0f * eb + 0.25f;
    }
}

// ---------------------------------------------------------------------------
// Approx VQ GEMM (hh only) for ONE codebook slice (2048 codes).
// Per-(row, 8-code subgroup) u32 key: [enc(dist) top 24][mask 8]
// ---------------------------------------------------------------------------
#define VBUF2 16384

__global__ __launch_bounds__(256, 2) void vq_approx(
        const __nv_bfloat16* __restrict__ Ah, const __nv_bfloat16* __restrict__ Bh,
        const float* __restrict__ c2, const float* __restrict__ thr,
        uint32_t* __restrict__ gkey, int cbk) {
    extern __shared__ __align__(16) char dsm[];          // 2 * 16 KB
    __shared__ uint32_t sG[128][16];

    const int tid  = threadIdx.x;
    const int lane = tid & 31;
    const int wid  = tid >> 5;
    const int wm   = wid >> 1;
    const int wn   = wid & 1;
    const int m0 = blockIdx.x * 128;
    const int n0 = cbk * VOCAB + blockIdx.y * 128;
    const uint32_t sbase = smem_u32(dsm);

    float acc[2][8][4];
#pragma unroll
    for (int i = 0; i < 2; ++i)
#pragma unroll
        for (int j = 0; j < 8; ++j)
#pragma unroll
            for (int q = 0; q < 4; ++q) acc[i][j][q] = 0.0f;

    auto load_chunk = [&](int c, int buf) {
        const int k0 = c * 32;
        const uint32_t bb = sbase + buf * VBUF2;
#pragma unroll
        for (int r = 0; r < 4; ++r) {
            int i = tid + r * 256;
            int row = (i >> 2) & 127;
            int cc  = i & 3;
            if (i < 512) {
                cp16(bb + swz(row, cc),
                     Ah + (size_t)(m0 + row) * 512 + k0 + cc * 8);
            } else {
                cp16(bb + 8192 + swz(row, cc),
                     Bh + (size_t)(n0 + row) * 512 + k0 + cc * 8);
            }
        }
    };

    load_chunk(0, 0);
    cp_commit();

    const int a_r = lane & 15;
    const int a_h = lane >> 4;
    const int b_r = (lane & 7) + ((lane >> 4) << 3);
    const int b_h = (lane >> 3) & 1;

    for (int c = 0; c < 16; ++c) {
        const int buf = c & 1;
        cp_wait0();
        __syncthreads();
        if (c < 15) { load_chunk(c + 1, buf ^ 1); cp_commit(); }

        const uint32_t bb = sbase + buf * VBUF2;
#pragma unroll
        for (int s = 0; s < 2; ++s) {
            uint32_t a[2][4];
#pragma unroll
            for (int mt = 0; mt < 2; ++mt) {
                int r = wm * 32 + mt * 16 + a_r;
                ldm4(a[mt], bb + swz(r, s * 2 + a_h));
            }
#pragma unroll
            for (int g = 0; g < 4; ++g) {
                uint32_t bH[4];
                int r = wn * 64 + g * 16 + b_r;
                ldm4(bH, bb + 8192 + swz(r, s * 2 + b_h));
#pragma unroll
                for (int mt = 0; mt < 2; ++mt) {
                    mma16816(acc[mt][g * 2],     a[mt], bH[0], bH[1]);
                    mma16816(acc[mt][g * 2 + 1], a[mt], bH[2], bH[3]);
                }
            }
        }
    }

    float c2v[16];
#pragma unroll
    for (int j = 0; j < 8; ++j)
#pragma unroll
        for (int cb = 0; cb < 2; ++cb)
            c2v[j * 2 + cb] =
                __ldg(&c2[n0 + wn * 64 + j * 8 + (lane & 3) * 2 + cb]);

#pragma unroll
    for (int mt = 0; mt < 2; ++mt)
#pragma unroll
        for (int h = 0; h < 2; ++h) {
            int row = wm * 32 + mt * 16 + (lane >> 2) + h * 8;
            float tv = __ldg(&thr[m0 + row]);
#pragma unroll
            for (int j = 0; j < 8; ++j) {
                float d0 = c2v[j * 2]     - 2.0f * acc[mt][j][h * 2];
                float d1 = c2v[j * 2 + 1] - 2.0f * acc[mt][j][h * 2 + 1];
                float dmin = fminf(d0, d1);
                float o1 = __uint_as_float(
                    __shfl_xor_sync(0xffffffffu, __float_as_uint(dmin), 1));
                dmin = fminf(dmin, o1);
                float o2 = __uint_as_float(
                    __shfl_xor_sync(0xffffffffu, __float_as_uint(dmin), 2));
                dmin = fminf(dmin, o2);
                float Tg = dmin + tv;
                unsigned int lm = 0;
                if (d0 <= Tg) lm |= 1u << ((lane & 3) * 2);
                if (d1 <= Tg) lm |= 1u << ((lane & 3) * 2 + 1);
                lm |= __shfl_xor_sync(0xffffffffu, lm, 1);
                lm |= __shfl_xor_sync(0xffffffffu, lm, 2);
                if ((lane & 3) == 0)
                    sG[row][wn * 8 + j] = (enc_bits(dmin) & 0xffffff00u) | lm;
            }
        }
    __syncthreads();

    const int gbase = cbk * GRP_CB + blockIdx.y * 16;
    for (int i = tid; i < 2048; i += 256) {
        int row = i >> 4, j = i & 15;
        gkey[(size_t)(m0 + row) * NGRP + gbase + j] = sG[row][j];
    }
}

// ---------------------------------------------------------------------------
// flag (one codebook): per row min over 256 subgroup keys, threshold, emit
// item = m(14b) << 18 | group(10b) << 8 | mask(8b); counter misc[4+cbk]
// ---------------------------------------------------------------------------
__global__ void flag_kernel(const uint32_t* __restrict__ gkey,
                            const float* __restrict__ thr,
                            uint32_t* __restrict__ misc,
                            uint32_t* __restrict__ items, int cbk) {
    int m = blockIdx.x * 8 + (threadIdx.x >> 5);
    int lane = threadIdx.x & 31;
    if (m >= MTOT) return;

    float tv = __ldg(&thr[m]);

    uint32_t kq[8];
    unsigned int mn = ~0u;
#pragma unroll
    for (int q = 0; q < 8; ++q) {
        uint32_t k = gkey[(size_t)m * NGRP + cbk * GRP_CB + q * 32 + lane];
        kq[q] = k;
        unsigned int e = k >> 8;
        if (e < mn) mn = e;
    }
#pragma unroll
    for (int o = 16; o > 0; o >>= 1) {
        unsigned int v = __shfl_xor_sync(0xffffffffu, mn, o);
        if (v < mn) mn = v;
    }
    float M = dec_bits(mn << 8);
    unsigned int encT = enc_bits(M + tv) >> 8;
    unsigned int cbmask = 0;
#pragma unroll
    for (int q = 0; q < 8; ++q)
        if ((kq[q] >> 8) <= encT) cbmask |= 1u << q;

    int cnt = __popc(cbmask);
    int incl = cnt;
#pragma unroll
    for (int o = 1; o < 32; o <<= 1) {
        int v = __shfl_up_sync(0xffffffffu, incl, o);
        if (lane >= o) incl += v;
    }
    int total = __shfl_sync(0xffffffffu, incl, 31);
    unsigned int base = 0;
    if (lane == 31 && total > 0)
        base = atomicAdd(&misc[4 + cbk], (unsigned int)total);
    base = __shfl_sync(0xffffffffu, base, 31);
    int off = (int)base + incl - cnt;
#pragma unroll
    for (int q = 0; q < 8; ++q)
        if (cbmask & (1u << q)) {
            int g = cbk * GRP_CB + q * 32 + lane;
            items[off++] = ((unsigned int)m << 18) |
                           ((unsigned int)g << 8) | (kq[q] & 0xffu);
        }
}

// ---------------------------------------------------------------------------
// refine (one codebook): exact fp32 distances for masked codes of each item
// ---------------------------------------------------------------------------
__global__ void refine_kernel(const __nv_bfloat16* __restrict__ Ah,
                              const __nv_bfloat16* __restrict__ Al,
                              const __nv_bfloat16* __restrict__ Bh,
                              const __nv_bfloat16* __restrict__ Bl,
                              const float* __restrict__ c2,
                              const uint32_t* __restrict__ misc,
                              const uint32_t* __restrict__ items,
                              u64* __restrict__ res, int cbk) {
    const int lane = threadIdx.x & 31;
    const int wgid = blockIdx.x * 8 + (threadIdx.x >> 5);
    const int nw = gridDim.x * 8;
    const int cnt = (int)misc[4 + cbk];

    for (int it = wgid; it < cnt; it += nw) {
        unsigned int item = items[it];
        int m = item >> 18;
        int g = (item >> 8) & 1023;
        unsigned int cmask = item & 0xffu;
        int cb = g >> 8;
        int n0 = g * 8;

        float f[16], t0[8], t1[8];
        {
            const uint4* ph = (const uint4*)(Ah + (size_t)m * 512 + lane * 16);
            const uint4* pl = (const uint4*)(Al + (size_t)m * 512 + lane * 16);
            uint4 h0 = ph[0], h1 = ph[1], l0v = pl[0], l1v = pl[1];
            bf8(h0, f); bf8(h1, f + 8);
            bf8(l0v, t0); bf8(l1v, t1);
#pragma unroll
            for (int e = 0; e < 8; ++e)  f[e] += t0[e];
#pragma unroll
            for (int e = 0; e < 8; ++e)  f[e + 8] += t1[e];
        }

        u64 best = ~0ull;
        unsigned int mm = cmask;
        while (mm) {
            int c = __ffs(mm) - 1;
            mm &= mm - 1;
            int n = n0 + c;
            const uint4* pb = (const uint4*)(Bh + (size_t)n * 512 + lane * 16);
            const uint4* pq = (const uint4*)(Bl + (size_t)n * 512 + lane * 16);
            uint4 b0 = pb[0], b1 = pb[1], q0 = pq[0], q1 = pq[1];
            float g0[8], g1[8], r0[8], r1[8];
            bf8(b0, g0); bf8(b1, g1); bf8(q0, r0); bf8(q1, r1);
            float dot = 0.0f;
#pragma unroll
            for (int e = 0; e < 8; ++e) dot = fmaf(f[e], g0[e] + r0[e], dot);
#pragma unroll
            for (int e = 0; e < 8; ++e) dot = fmaf(f[e + 8], g1[e] + r1[e], dot);
#pragma unroll
            for (int o = 16; o > 0; o >>= 1)
                dot += __shfl_down_sync(0xffffffffu, dot, o);
            if (lane == 0) {
                float d = __ldg(&c2[n]) - 2.0f * dot;
                u64 k = dist_key(d, n);
                if (k < best) best = k;
            }
        }
        if (lane == 0 && best != ~0ull) atomicMin(&res[m * 4 + cb], best);
    }
}

// ---------------------------------------------------------------------------
// Finalize: tokens from g_res + embedding mean
// ---------------------------------------------------------------------------
__global__ void finalize_kernel(const u64* __restrict__ res,
                                const float* __restrict__ emb_table,
                                float* __restrict__ out) {
    __shared__ int tok[KCB];
    const int m = blockIdx.x;
    const int b = m >> 12, l = m & 4095;
    const int tid = threadIdx.x;

    if (tid < KCB) {
        int t = ((int)(res[m * 4 + tid] & 0xffffffffu)) & (VOCAB - 1);
        tok[tid] = t;
        out[((size_t)b * KCB + tid) * L3O + l] = (float)t;
    }
    __syncthreads();

    float* out_emb = out + (size_t)NB * KCB * L3O;
    int t0 = tok[0], t1 = tok[1], t2 = tok[2], t3 = tok[3];
    for (int h = tid; h < 512; h += 128) {
        float s = emb_table[(size_t)t0 * 512 + h] + emb_table[(size_t)t1 * 512 + h]
                + emb_table[(size_t)t2 * 512 + h] + emb_table[(size_t)t3 * 512 + h];
        out_emb[((size_t)b * L3O + l) * 512 + h] = 0.25f * s;
    }
}

// ---------------------------------------------------------------------------
extern "C" void kernel_launch(void* const* d_in, const int* in_sizes, int n_in,
                              void* d_out, int out_size) {
    const float* audio = (const float*)d_in[0];
    const float* w1    = (const float*)d_in[1];
    const float* b1    = (const float*)d_in[2];
    const float* w2    = (const float*)d_in[3];
    const float* b2    = (const float*)d_in[4];
    const float* w3    = (const float*)d_in[5];
    const float* b3    = (const float*)d_in[6];
    const float* cb    = (const float*)d_in[7];
    const float* emb   = (const float*)d_in[8];
    float* out = (float*)d_out;

    __nv_bfloat16 *x1h, *x1l, *x2h, *x2l, *w2h, *w2l, *w3h, *w3l;
    __nv_bfloat16 *ah, *al, *bh, *bl;
    float *c2p, *thrp;
    u64 *resp;
    uint32_t *gkeyp, *miscp, *itemsp;
    cudaGetSymbolAddress((void**)&x1h, g_X1h);
    cudaGetSymbolAddress((void**)&x1l, g_X1l);
    cudaGetSymbolAddress((void**)&x2h, g_X2h);
    cudaGetSymbolAddress((void**)&x2l, g_X2l);
    cudaGetSymbolAddress((void**)&w2h, g_W2h);
    cudaGetSymbolAddress((void**)&w2l, g_W2l);
    cudaGetSymbolAddress((void**)&w3h, g_W3h);
    cudaGetSymbolAddress((void**)&w3l, g_W3l);
    cudaGetSymbolAddress((void**)&ah,  g_Ah);
    cudaGetSymbolAddress((void**)&al,  g_Al);
    cudaGetSymbolAddress((void**)&bh,  g_Bh);
    cudaGetSymbolAddress((void**)&bl,  g_Bl);
    cudaGetSymbolAddress((void**)&c2p, g_c2);
    cudaGetSymbolAddress((void**)&thrp, g_thr);
    cudaGetSymbolAddress((void**)&gkeyp, g_gkey32);
    cudaGetSymbolAddress((void**)&itemsp, g_items);
    cudaGetSymbolAddress((void**)&miscp, g_misc);
    cudaGetSymbolAddress((void**)&resp, g_res);

    const size_t ITEMS_CB = (size_t)MTOT * GRP_CB;   // per-cb item partition

    // streams/events created per call (correctness + capture only, not replay)
    cudaStream_t side;
    cudaStreamCreateWithFlags(&side, cudaStreamNonBlocking);
    cudaEvent_t eFork, eW2, eW3, eSB, eA[4], eSideDone;
    cudaEventCreateWithFlags(&eFork, cudaEventDisableTiming);
    cudaEventCreateWithFlags(&eW2,   cudaEventDisableTiming);
    cudaEventCreateWithFlags(&eW3,   cudaEventDisableTiming);
    cudaEventCreateWithFlags(&eSB,   cudaEventDisableTiming);
    for (int i = 0; i < 4; ++i)
        cudaEventCreateWithFlags(&eA[i], cudaEventDisableTiming);
    cudaEventCreateWithFlags(&eSideDone, cudaEventDisableTiming);

    cudaEventRecord(eFork, 0);
    cudaStreamWaitEvent(side, eFork, 0);
    split_W<<<(C2C * C1 * 7 + 255) / 256, 256, 0, side>>>(w2, w2h, w2l, C2C, C1);
    cudaEventRecord(eW2, side);
    split_W<<<(C3 * C2C * 7 + 255) / 256, 256, 0, side>>>(w3, w3h, w3l, C3, C2C);
    cudaEventRecord(eW3, side);
    splitb_kernel<<<NCODES / 8, 256, 0, side>>>(cb, bh, bl, c2p, miscp);
    cudaEventRecord(eSB, side);

    // main stream: audio chain
    prep_kernel<<<(MTOT * KCB + 255) / 256, 256>>>(
        resp, miscp, (uint32_t*)x1h, (uint32_t*)x1l, (uint32_t*)x2h, (uint32_t*)x2l);
    conv1_kernel<<<dim3(L1O / 2, 1, NB), 256>>>(audio, w1, b1, x1h, x1l);

    cudaStreamWaitEvent(0, eW2, 0);
    cudaFuncSetAttribute(conv_mma<C1>, cudaFuncAttributeMaxDynamicSharedMemorySize,
                         CBUF);
    conv_mma<C1><<<dim3(L2O / 128, C2C / 128, NB), 256, CBUF>>>(
        x1h, x1l, w2h, w2l, b2, x2h, x2l, L1O, L2O, C2C, 1, 8, 4);

    cudaStreamWaitEvent(0, eW3, 0);
    cudaFuncSetAttribute(conv_mma<C2C>, cudaFuncAttributeMaxDynamicSharedMemorySize,
                         CBUF);
    conv_mma<C2C><<<dim3(L3O / 128, C3 / 128, NB), 256, CBUF>>>(
        x2h, x2l, w3h, w3l, b3, ah, al, L2O, L3O, C3, 0, 0, 0);

    cudaStreamWaitEvent(0, eSB, 0);
    thr_kernel<<<MTOT / 8, 256>>>(ah, al, miscp, thrp);

    // per-codebook pipelined vq: vqa(cb) on main; flag+refine(cb) on side,
    // overlapping vqa(cb+1)'s tensor work.
    cudaFuncSetAttribute(vq_approx, cudaFuncAttributeMaxDynamicSharedMemorySize,
                         2 * VBUF2);
    for (int cbk = 0; cbk < 4; ++cbk) {
        vq_approx<<<dim3(MTOT / 128, VOCAB / 128), 256, 2 * VBUF2>>>(
            ah, bh, c2p, thrp, gkeyp, cbk);
        cudaEventRecord(eA[cbk], 0);
        cudaStreamWaitEvent(side, eA[cbk], 0);
        flag_kernel<<<MTOT / 8, 256, 0, side>>>(
            gkeyp, thrp, miscp, itemsp + cbk * ITEMS_CB, cbk);
        refine_kernel<<<512, 256, 0, side>>>(
            ah, al, bh, bl, c2p, miscp, itemsp + cbk * ITEMS_CB, resp, cbk);
    }
    cudaEventRecord(eSideDone, side);
    cudaStreamWaitEvent(0, eSideDone, 0);

    finalize_kernel<<<MTOT, 128>>>(resp, emb, out);
}